// round 7
// baseline (speedup 1.0000x reference)
#include <cuda_runtime.h>
#include <cuda_bf16.h>
#include <math.h>
#include <stdint.h>

#define BB 4
#define SS 2048
#define HH 2048
#define NHH 8
#define DD 256
#define QKVW 2560            // (8 + 2*1) * 256
#define MROWS (BB * SS)      // 8192

// ---------------------------------------------------------------------------
// Scratch (allocation-free rule: device globals)
// ---------------------------------------------------------------------------
__device__ float g_qkv[MROWS * QKVW];                         // ~84 MB fp32
__device__ __align__(16) __nv_bfloat16 g_hid_hi[MROWS * HH];
__device__ __align__(16) __nv_bfloat16 g_hid_lo[MROWS * HH];
__device__ __align__(16) __nv_bfloat16 g_wqkv_hi[QKVW * HH];  // transposed [N][K]
__device__ __align__(16) __nv_bfloat16 g_wqkv_lo[QKVW * HH];
__device__ __align__(16) __nv_bfloat16 g_wo_hi[HH * HH];      // transposed [N][K]
__device__ __align__(16) __nv_bfloat16 g_wo_lo[HH * HH];
__device__ __align__(16) __nv_bfloat16 g_atn_hi[MROWS * HH];
__device__ __align__(16) __nv_bfloat16 g_atn_lo[MROWS * HH];
__device__ __align__(16) __nv_bfloat16 g_q_hi[(size_t)BB * NHH * SS * DD];
__device__ __align__(16) __nv_bfloat16 g_q_lo[(size_t)BB * NHH * SS * DD];
__device__ __align__(16) __nv_bfloat16 g_k_hi[(size_t)BB * SS * DD];
__device__ __align__(16) __nv_bfloat16 g_k_lo[(size_t)BB * SS * DD];
__device__ __align__(16) __nv_bfloat16 g_v_hi[(size_t)BB * SS * DD];
__device__ __align__(16) __nv_bfloat16 g_v_lo[(size_t)BB * SS * DD];

// ---------------------------------------------------------------------------
// helpers
// ---------------------------------------------------------------------------
__device__ __forceinline__ uint32_t smem_u32(const void* p) {
    uint32_t a;
    asm("{ .reg .u64 t; cvta.to.shared.u64 t, %1; cvt.u32.u64 %0, t; }"
        : "=r"(a) : "l"(p));
    return a;
}

__device__ __forceinline__ void ldsm_x4(uint32_t (&r)[4], uint32_t addr) {
    asm volatile("ldmatrix.sync.aligned.m8n8.x4.shared.b16 {%0,%1,%2,%3}, [%4];"
                 : "=r"(r[0]), "=r"(r[1]), "=r"(r[2]), "=r"(r[3]) : "r"(addr));
}

__device__ __forceinline__ void ldsm_x4_t(uint32_t (&r)[4], uint32_t addr) {
    asm volatile("ldmatrix.sync.aligned.m8n8.x4.trans.shared.b16 {%0,%1,%2,%3}, [%4];"
                 : "=r"(r[0]), "=r"(r[1]), "=r"(r[2]), "=r"(r[3]) : "r"(addr));
}

__device__ __forceinline__ void mma_bf16(float (&d)[4], const uint32_t (&a)[4],
                                         const uint32_t* b) {
    asm volatile(
        "mma.sync.aligned.m16n8k16.row.col.f32.bf16.bf16.f32 "
        "{%0,%1,%2,%3}, {%4,%5,%6,%7}, {%8,%9}, {%0,%1,%2,%3};"
        : "+f"(d[0]), "+f"(d[1]), "+f"(d[2]), "+f"(d[3])
        : "r"(a[0]), "r"(a[1]), "r"(a[2]), "r"(a[3]), "r"(b[0]), "r"(b[1]));
}

__device__ __forceinline__ void cp16(uint32_t dst, const void* src) {
    asm volatile("cp.async.cg.shared.global [%0], [%1], 16;"
                 :: "r"(dst), "l"(src) : "memory");
}

__device__ __forceinline__ uint32_t pk_bf2(float a, float b) {
    __nv_bfloat162 t = __floats2bfloat162_rn(a, b);
    return *reinterpret_cast<uint32_t*>(&t);
}

// ---------------------------------------------------------------------------
// HMMA split-bf16 GEMM v2: block tile 256x128x32, 256 threads (8 warps, 4Mx2N),
// warp tile 64x64. 3-stage cp.async, distance-2 prefetch, 1 barrier/chunk.
// Memory-bound: big M-tile cuts global traffic (1/BM + 1/BN).
// ---------------------------------------------------------------------------
#define ROWB 80                    // 32 bf16 + 8B pad per smem row
#define GA_T (256 * ROWB)          // 20480: one A half (hi or lo)
#define GB_T (128 * ROWB)          // 10240: one B half
#define GSTAGE (2 * GA_T + 2 * GB_T)   // 61440
#define GEMM_SMEM (3 * GSTAGE)         // 184320

__global__ __launch_bounds__(256) void hmma_gemm_kernel(
    const __nv_bfloat16* __restrict__ Ahi, const __nv_bfloat16* __restrict__ Alo,
    const __nv_bfloat16* __restrict__ Bhi, const __nv_bfloat16* __restrict__ Blo,
    float* __restrict__ C, int M, int N, int K)
{
    extern __shared__ char gsm[];
    const uint32_t base = smem_u32(gsm);

    const int tid = threadIdx.x;
    const int lane = tid & 31;
    const int wid = tid >> 5;
    const int warp_m = wid & 3;          // 4 warps in M: 64 rows each
    const int warp_n = wid >> 2;         // 2 warps in N: 64 cols each
    const int row0 = blockIdx.y * 256, col0 = blockIdx.x * 128;

    float acc[4][8][4];
#pragma unroll
    for (int i = 0; i < 4; i++)
#pragma unroll
        for (int j = 0; j < 8; j++)
#pragma unroll
            for (int e = 0; e < 4; e++) acc[i][j][e] = 0.f;

    const int nch = K >> 5;              // 64 for K=2048

    // stage loader: 3072 x 16B = Ahi(1024) Alo(1024) Bhi(512) Blo(512)
    auto load_stage = [&](int st, int k0) {
        const uint32_t sb = base + st * GSTAGE;
#pragma unroll
        for (int i2 = 0; i2 < 12; i2++) {
            int g = tid + (i2 << 8);               // 0..3071
            const __nv_bfloat16* src;
            uint32_t dst;
            if (g < 2048) {                        // A tiles
                int half = g >> 10;                // 0:hi 1:lo
                int r = (g >> 2) & 255;
                int kq = g & 3;
                const __nv_bfloat16* bp = half ? Alo : Ahi;
                src = bp + (size_t)(row0 + r) * K + k0 + (kq << 3);
                dst = sb + half * GA_T + r * ROWB + (kq << 4);
            } else {                               // B tiles
                int g2 = g - 2048;
                int half = g2 >> 9;
                int r = (g2 >> 2) & 127;
                int kq = g2 & 3;
                const __nv_bfloat16* bp = half ? Blo : Bhi;
                src = bp + (size_t)(col0 + r) * K + k0 + (kq << 3);
                dst = sb + 2 * GA_T + half * GB_T + r * ROWB + (kq << 4);
            }
            cp16(dst, src);
        }
        asm volatile("cp.async.commit_group;" ::: "memory");
    };

    load_stage(0, 0);
    load_stage(1, 32);

    int st = 0;                          // stage index of chunk c (c % 3)
    for (int c = 0; c < nch; c++) {
        if (c == nch - 1) { asm volatile("cp.async.wait_group 0;" ::: "memory"); }
        else              { asm volatile("cp.async.wait_group 1;" ::: "memory"); }
        __syncthreads();   // stage c visible; all warps done reading stage c-1's buffer

        if (c + 2 < nch) {
            int pst = st + 2; if (pst >= 3) pst -= 3;
            load_stage(pst, (c + 2) << 5);
        }

        const uint32_t sb = base + st * GSTAGE;
        const uint32_t aH = sb, bH = sb + 2 * GA_T;

#pragma unroll
        for (int ks = 0; ks < 2; ks++) {
            uint32_t ah[4][4], al[4][4], bh[8][2], bl[8][2];
            const int arow = warp_m * 64 + (lane & 15);
            const uint32_t akoff = (ks << 5) + ((lane >> 4) << 4);
#pragma unroll
            for (int i = 0; i < 4; i++) {
                uint32_t ad = aH + (uint32_t)(arow + i * 16) * ROWB + akoff;
                ldsm_x4(ah[i], ad);
                ldsm_x4(al[i], ad + GA_T);
            }
            const int quad = lane >> 3, wi = lane & 7;
#pragma unroll
            for (int t = 0; t < 4; t++) {
                int ntile = 2 * t + (quad >> 1);
                int brow = warp_n * 64 + ntile * 8 + wi;
                uint32_t bd = bH + (uint32_t)brow * ROWB + (ks << 5) + ((quad & 1) << 4);
                uint32_t r4[4];
                ldsm_x4(r4, bd);
                bh[2 * t][0] = r4[0]; bh[2 * t][1] = r4[1];
                bh[2 * t + 1][0] = r4[2]; bh[2 * t + 1][1] = r4[3];
                ldsm_x4(r4, bd + GB_T);
                bl[2 * t][0] = r4[0]; bl[2 * t][1] = r4[1];
                bl[2 * t + 1][0] = r4[2]; bl[2 * t + 1][1] = r4[3];
            }
#pragma unroll
            for (int i = 0; i < 4; i++)
#pragma unroll
                for (int j = 0; j < 8; j++) {
                    mma_bf16(acc[i][j], ah[i], bh[j]);
                    mma_bf16(acc[i][j], ah[i], bl[j]);
                    mma_bf16(acc[i][j], al[i], bh[j]);
                }
        }
        if (++st >= 3) st -= 3;
    }

    const int rb = row0 + warp_m * 64 + (lane >> 2);
    const int cb = col0 + warp_n * 64 + (lane & 3) * 2;
#pragma unroll
    for (int i = 0; i < 4; i++)
#pragma unroll
        for (int j = 0; j < 8; j++) {
            float* p0 = C + (size_t)(rb + i * 16) * N + cb + j * 8;
            float* p1 = C + (size_t)(rb + i * 16 + 8) * N + cb + j * 8;
            *(float2*)p0 = make_float2(acc[i][j][0], acc[i][j][1]);
            *(float2*)p1 = make_float2(acc[i][j][2], acc[i][j][3]);
        }
}

// ---------------------------------------------------------------------------
// fp32 -> split bf16 (hi/lo)
// ---------------------------------------------------------------------------
__global__ void split_kernel(const float* __restrict__ x,
                             __nv_bfloat16* __restrict__ hi,
                             __nv_bfloat16* __restrict__ lo, int n4)
{
    int i = blockIdx.x * blockDim.x + threadIdx.x;
    if (i >= n4) return;
    float4 v = ((const float4*)x)[i];
    float vv[4] = {v.x, v.y, v.z, v.w};
    __nv_bfloat16 hv[4], lv[4];
#pragma unroll
    for (int j = 0; j < 4; j++) {
        hv[j] = __float2bfloat16_rn(vv[j]);
        lv[j] = __float2bfloat16_rn(vv[j] - __bfloat162float(hv[j]));
    }
    *(uint2*)&hi[(size_t)i * 4] = *(uint2*)hv;
    *(uint2*)&lo[(size_t)i * 4] = *(uint2*)lv;
}

// ---------------------------------------------------------------------------
// fp32 [R][Cn] -> transposed split bf16 [Cn][R] (hi/lo). 32x32 tiles.
// ---------------------------------------------------------------------------
__global__ void tsplit_kernel(const float* __restrict__ x,
                              __nv_bfloat16* __restrict__ hi,
                              __nv_bfloat16* __restrict__ lo, int R, int Cn)
{
    __shared__ float t[32][33];
    int bc = blockIdx.x * 32, br = blockIdx.y * 32;
    int tx = threadIdx.x, ty = threadIdx.y;
#pragma unroll
    for (int j = 0; j < 32; j += 8)
        t[ty + j][tx] = x[(size_t)(br + ty + j) * Cn + bc + tx];
    __syncthreads();
#pragma unroll
    for (int j = 0; j < 32; j += 8) {
        int orow = bc + ty + j;
        int ocol = br + tx;
        float v = t[tx][ty + j];
        __nv_bfloat16 h = __float2bfloat16_rn(v);
        hi[(size_t)orow * R + ocol] = h;
        lo[(size_t)orow * R + ocol] = __float2bfloat16_rn(v - __bfloat162float(h));
    }
}

// ---------------------------------------------------------------------------
// Fused RoPE + split. Q is PRE-SCALED by 1/16 (softmax scale folded in).
// ---------------------------------------------------------------------------
__global__ void rope_split_kernel(
    const float* __restrict__ qkv, const int* __restrict__ positions,
    __nv_bfloat16* __restrict__ qhi, __nv_bfloat16* __restrict__ qlo,
    __nv_bfloat16* __restrict__ khi, __nv_bfloat16* __restrict__ klo,
    __nv_bfloat16* __restrict__ vhi, __nv_bfloat16* __restrict__ vlo)
{
    const int total = MROWS * 11 * 128;
    int idx = blockIdx.x * blockDim.x + threadIdx.x;
    if (idx >= total) return;
    int j = idx & 127;
    int t = idx >> 7;
    int unit = t % 11;
    int row = t / 11;
    int s = row & (SS - 1);
    int b = row >> 11;

    if (unit < 9) {
        float pos = (float)positions[s];
        const float LOG_THETA = 9.210340371976184f;
        float e = (float)j * (1.0f / 128.0f);
        float invf = expf(-LOG_THETA * e);
        float ang = pos * invf;
        float sn, cs;
        sincosf(ang, &sn, &cs);

        int inoff = row * QKVW + (unit < 8 ? unit * 256 : 2048);
        float x1 = qkv[inoff + j];
        float x2 = qkv[inoff + 128 + j];
        float y1 = x1 * cs - x2 * sn;
        float y2 = x2 * cs + x1 * sn;

        size_t ooff;
        __nv_bfloat16 *ph, *pl;
        if (unit < 8) {
            y1 *= 0.0625f;
            y2 *= 0.0625f;
            ooff = ((size_t)(b * NHH + unit) * SS + s) * DD;
            ph = qhi; pl = qlo;
        } else {
            ooff = (size_t)row * DD;
            ph = khi; pl = klo;
        }
        __nv_bfloat16 h1 = __float2bfloat16_rn(y1);
        __nv_bfloat16 h2 = __float2bfloat16_rn(y2);
        ph[ooff + j] = h1;
        ph[ooff + 128 + j] = h2;
        pl[ooff + j] = __float2bfloat16_rn(y1 - __bfloat162float(h1));
        pl[ooff + 128 + j] = __float2bfloat16_rn(y2 - __bfloat162float(h2));
    } else {
        int jj = (unit - 9) * 128 + j;
        float v = qkv[row * QKVW + 2304 + jj];
        __nv_bfloat16 h = __float2bfloat16_rn(v);
        vhi[(size_t)row * DD + jj] = h;
        vlo[(size_t)row * DD + jj] = __float2bfloat16_rn(v - __bfloat162float(h));
    }
}

// ---------------------------------------------------------------------------
// HMMA flash attention v2: Br=128, Bc=32, 256 threads (8 warps). (unchanged)
// ---------------------------------------------------------------------------
#define KSTR 528
#define PSTR 80
#define FQHI 0
#define FQLO (FQHI + 128 * KSTR)
#define FKHI (FQLO + 128 * KSTR)
#define FKLO (FKHI + 32 * KSTR)
#define FVHI (FKLO + 32 * KSTR)
#define FVLO (FVHI + 32 * KSTR)
#define FPHI (FVLO + 32 * KSTR)
#define FPLO (FPHI + 128 * PSTR)
#define FLASH_SMEM (FPLO + 128 * PSTR)

__global__ __launch_bounds__(256) void flash_hmma_kernel(
    const __nv_bfloat16* __restrict__ Qhi, const __nv_bfloat16* __restrict__ Qlo,
    const __nv_bfloat16* __restrict__ Khi, const __nv_bfloat16* __restrict__ Klo,
    const __nv_bfloat16* __restrict__ Vhi, const __nv_bfloat16* __restrict__ Vlo,
    __nv_bfloat16* __restrict__ Ohi, __nv_bfloat16* __restrict__ Olo)
{
    extern __shared__ char fsm[];
    const uint32_t base = smem_u32(fsm);
    const int qt = (gridDim.x - 1) - blockIdx.x;
    const int h = blockIdx.y, b = blockIdx.z;
    const int tid = threadIdx.x, lane = tid & 31, w = tid >> 5;
    const int q0 = qt * 128;
    const int nj = (q0 + 128) >> 5;

    const __nv_bfloat16* qhp = Qhi + ((size_t)(b * NHH + h) * SS + q0) * DD;
    const __nv_bfloat16* qlp = Qlo + ((size_t)(b * NHH + h) * SS + q0) * DD;
    const __nv_bfloat16* khp = Khi + (size_t)b * SS * DD;
    const __nv_bfloat16* klp = Klo + (size_t)b * SS * DD;
    const __nv_bfloat16* vhp = Vhi + (size_t)b * SS * DD;
    const __nv_bfloat16* vlp = Vlo + (size_t)b * SS * DD;

    {
#pragma unroll
        for (int i = 0; i < 16; i++) {
            int g = tid + (i << 8);
            int r = g >> 5, cq = g & 31;
            cp16(base + FQHI + r * KSTR + (cq << 4),
                 qhp + (size_t)r * DD + (cq << 3));
        }
#pragma unroll
        for (int i = 0; i < 16; i++) {
            int g = tid + (i << 8);
            int r = g >> 5, cq = g & 31;
            cp16(base + FQLO + r * KSTR + (cq << 4),
                 qlp + (size_t)r * DD + (cq << 3));
        }
        asm volatile("cp.async.commit_group;" ::: "memory");
    }

    auto ldkv = [&](uint32_t offhi, uint32_t offlo, const __nv_bfloat16* ph,
                    const __nv_bfloat16* pl, int c0) {
#pragma unroll
        for (int i = 0; i < 4; i++) {
            int g = tid + (i << 8);
            int r = g >> 5, cq = g & 31;
            cp16(base + offhi + r * KSTR + (cq << 4),
                 ph + (size_t)(c0 + r) * DD + (cq << 3));
        }
#pragma unroll
        for (int i = 0; i < 4; i++) {
            int g = tid + (i << 8);
            int r = g >> 5, cq = g & 31;
            cp16(base + offlo + r * KSTR + (cq << 4),
                 pl + (size_t)(c0 + r) * DD + (cq << 3));
        }
        asm volatile("cp.async.commit_group;" ::: "memory");
    };

    ldkv(FKHI, FKLO, khp, klp, 0);
    ldkv(FVHI, FVLO, vhp, vlp, 0);

    float acc[32][4];
#pragma unroll
    for (int t = 0; t < 32; t++)
#pragma unroll
        for (int e = 0; e < 4; e++) acc[t][e] = 0.f;
    float m0 = -1e30f, m1 = -1e30f, l0 = 0.f, l1 = 0.f;

    const uint32_t aQbase = base + FQHI + (w * 16 + (lane & 15)) * KSTR + ((lane >> 4) << 4);
    const int quad = lane >> 3, wi = lane & 7;
    const uint32_t bKbase = base + FKHI + ((quad >> 1) * 8 + wi) * KSTR + ((quad & 1) << 4);
    const uint32_t aPbase = base + FPHI + (w * 16 + (lane & 15)) * PSTR + ((lane >> 4) << 4);
    const uint32_t bVbase = base + FVHI + ((lane & 7) + ((lane >> 3) & 1) * 8) * KSTR
                          + (lane >> 4) * 16;
    const uint32_t pstore = base + FPHI + (w * 16 + (lane >> 2)) * PSTR + (lane & 3) * 4;

    for (int jt = 0; jt < nj; jt++) {
        const int c0 = jt * 32;
        asm volatile("cp.async.wait_group 1;" ::: "memory");
        __syncthreads();

        float sacc[4][4];
#pragma unroll
        for (int t = 0; t < 4; t++)
#pragma unroll
            for (int e = 0; e < 4; e++) sacc[t][e] = 0.f;

#pragma unroll
        for (int ks = 0; ks < 16; ks++) {
            uint32_t ah[4], al[4];
            ldsm_x4(ah, aQbase + ks * 32);
            ldsm_x4(al, aQbase + (FQLO - FQHI) + ks * 32);
#pragma unroll
            for (int np = 0; np < 2; np++) {
                uint32_t bh4[4], bl4[4];
                uint32_t ka = bKbase + np * 16 * KSTR + ks * 32;
                ldsm_x4(bh4, ka);
                ldsm_x4(bl4, ka + (FKLO - FKHI));
                mma_bf16(sacc[2 * np],     ah, bh4);
                mma_bf16(sacc[2 * np],     ah, bl4);
                mma_bf16(sacc[2 * np],     al, bh4);
                mma_bf16(sacc[2 * np + 1], ah, bh4 + 2);
                mma_bf16(sacc[2 * np + 1], ah, bl4 + 2);
                mma_bf16(sacc[2 * np + 1], al, bh4 + 2);
            }
        }
        __syncthreads();
        if (jt + 1 < nj) ldkv(FKHI, FKLO, khp, klp, c0 + 32);

        const int colb = c0 + (lane & 3) * 2;
        const int row0g = q0 + w * 16 + (lane >> 2);
        const int row1g = row0g + 8;
        if (c0 + 31 > q0) {
#pragma unroll
            for (int t = 0; t < 4; t++) {
                int cg = colb + t * 8;
#pragma unroll
                for (int e = 0; e < 4; e++) {
                    int c = cg + (e & 1);
                    int rg = (e < 2) ? row0g : row1g;
                    if (c > rg) sacc[t][e] = -1e30f;
                }
            }
        }
        float mx0 = -1e30f, mx1 = -1e30f;
#pragma unroll
        for (int t = 0; t < 4; t++) {
            mx0 = fmaxf(mx0, fmaxf(sacc[t][0], sacc[t][1]));
            mx1 = fmaxf(mx1, fmaxf(sacc[t][2], sacc[t][3]));
        }
        mx0 = fmaxf(mx0, __shfl_xor_sync(0xffffffffu, mx0, 1));
        mx0 = fmaxf(mx0, __shfl_xor_sync(0xffffffffu, mx0, 2));
        mx1 = fmaxf(mx1, __shfl_xor_sync(0xffffffffu, mx1, 1));
        mx1 = fmaxf(mx1, __shfl_xor_sync(0xffffffffu, mx1, 2));

        float mn0 = fmaxf(m0, mx0), mn1 = fmaxf(m1, mx1);
        float a0 = __expf(m0 - mn0), a1 = __expf(m1 - mn1);
        m0 = mn0; m1 = mn1;
        float s0 = 0.f, s1 = 0.f;
#pragma unroll
        for (int t = 0; t < 4; t++) {
            float p0 = __expf(sacc[t][0] - mn0);
            float p1 = __expf(sacc[t][1] - mn0);
            float p2 = __expf(sacc[t][2] - mn1);
            float p3 = __expf(sacc[t][3] - mn1);
            s0 += p0 + p1; s1 += p2 + p3;
            uint32_t h01 = pk_bf2(p0, p1);
            uint32_t h23 = pk_bf2(p2, p3);
            __nv_bfloat162* hp = (__nv_bfloat162*)&h01;
            __nv_bfloat162* hq = (__nv_bfloat162*)&h23;
            uint32_t lo01 = pk_bf2(p0 - __bfloat162float(hp->x), p1 - __bfloat162float(hp->y));
            uint32_t lo23 = pk_bf2(p2 - __bfloat162float(hq->x), p3 - __bfloat162float(hq->y));
            asm volatile("st.shared.b32 [%0], %1;" :: "r"(pstore + t * 16), "r"(h01) : "memory");
            asm volatile("st.shared.b32 [%0], %1;" :: "r"(pstore + 8 * PSTR + t * 16), "r"(h23) : "memory");
            asm volatile("st.shared.b32 [%0], %1;" :: "r"(pstore + (FPLO - FPHI) + t * 16), "r"(lo01) : "memory");
            asm volatile("st.shared.b32 [%0], %1;" :: "r"(pstore + (FPLO - FPHI) + 8 * PSTR + t * 16), "r"(lo23) : "memory");
        }
        s0 += __shfl_xor_sync(0xffffffffu, s0, 1);
        s0 += __shfl_xor_sync(0xffffffffu, s0, 2);
        s1 += __shfl_xor_sync(0xffffffffu, s1, 1);
        s1 += __shfl_xor_sync(0xffffffffu, s1, 2);
        l0 = l0 * a0 + s0;
        l1 = l1 * a1 + s1;
        bool noresc = __all_sync(0xffffffffu, (a0 == 1.0f) && (a1 == 1.0f));
        if (!noresc) {
#pragma unroll
            for (int t = 0; t < 32; t++) {
                acc[t][0] *= a0; acc[t][1] *= a0;
                acc[t][2] *= a1; acc[t][3] *= a1;
            }
        }

        if (jt + 1 < nj) { asm volatile("cp.async.wait_group 1;" ::: "memory"); }
        else             { asm volatile("cp.async.wait_group 0;" ::: "memory"); }
        __syncthreads();

#pragma unroll
        for (int ks = 0; ks < 2; ks++) {
            uint32_t ph4[4], pl4[4];
            ldsm_x4(ph4, aPbase + ks * 32);
            ldsm_x4(pl4, aPbase + (FPLO - FPHI) + ks * 32);
#pragma unroll
            for (int np = 0; np < 16; np++) {
                uint32_t vh4[4], vl4[4];
                uint32_t va = bVbase + ks * 16 * KSTR + np * 32;
                ldsm_x4_t(vh4, va);
                ldsm_x4_t(vl4, va + (FVLO - FVHI));
                mma_bf16(acc[2 * np],     ph4, vh4);
                mma_bf16(acc[2 * np],     pl4, vh4);
                mma_bf16(acc[2 * np],     ph4, vl4);
                mma_bf16(acc[2 * np + 1], ph4, vh4 + 2);
                mma_bf16(acc[2 * np + 1], pl4, vh4 + 2);
                mma_bf16(acc[2 * np + 1], ph4, vl4 + 2);
            }
        }
        __syncthreads();
        if (jt + 1 < nj) ldkv(FVHI, FVLO, vhp, vlp, c0 + 32);
    }

    float inv0 = 1.0f / l0, inv1 = 1.0f / l1;
    size_t ob0 = ((size_t)(b * SS) + q0 + w * 16 + (lane >> 2)) * HH + h * DD + (lane & 3) * 2;
    size_t ob1 = ob0 + 8 * (size_t)HH;
#pragma unroll
    for (int t = 0; t < 32; t++) {
        float o0 = acc[t][0] * inv0, o1 = acc[t][1] * inv0;
        float o2 = acc[t][2] * inv1, o3 = acc[t][3] * inv1;
        uint32_t h01 = pk_bf2(o0, o1);
        uint32_t h23 = pk_bf2(o2, o3);
        __nv_bfloat162* hp = (__nv_bfloat162*)&h01;
        __nv_bfloat162* hq = (__nv_bfloat162*)&h23;
        uint32_t lo01 = pk_bf2(o0 - __bfloat162float(hp->x), o1 - __bfloat162float(hp->y));
        uint32_t lo23 = pk_bf2(o2 - __bfloat162float(hq->x), o3 - __bfloat162float(hq->y));
        *(uint32_t*)&Ohi[ob0 + t * 8] = h01;
        *(uint32_t*)&Ohi[ob1 + t * 8] = h23;
        *(uint32_t*)&Olo[ob0 + t * 8] = lo01;
        *(uint32_t*)&Olo[ob1 + t * 8] = lo23;
    }
}

// ---------------------------------------------------------------------------
extern "C" void kernel_launch(void* const* d_in, const int* in_sizes, int n_in,
                              void* d_out, int out_size)
{
    const float* hidden    = (const float*)d_in[0];
    const int*   positions = (const int*)d_in[1];
    const float* w_qkv     = (const float*)d_in[2];
    const float* w_o       = (const float*)d_in[3];
    float* out = (float*)d_out;

    float* qkv_ptr;
    __nv_bfloat16 *hid_hi, *hid_lo, *wqkv_hi, *wqkv_lo, *wo_hi, *wo_lo, *atn_hi, *atn_lo;
    __nv_bfloat16 *q_hi, *q_lo, *k_hi, *k_lo, *v_hi, *v_lo;
    cudaGetSymbolAddress((void**)&qkv_ptr, g_qkv);
    cudaGetSymbolAddress((void**)&hid_hi, g_hid_hi);
    cudaGetSymbolAddress((void**)&hid_lo, g_hid_lo);
    cudaGetSymbolAddress((void**)&wqkv_hi, g_wqkv_hi);
    cudaGetSymbolAddress((void**)&wqkv_lo, g_wqkv_lo);
    cudaGetSymbolAddress((void**)&wo_hi, g_wo_hi);
    cudaGetSymbolAddress((void**)&wo_lo, g_wo_lo);
    cudaGetSymbolAddress((void**)&atn_hi, g_atn_hi);
    cudaGetSymbolAddress((void**)&atn_lo, g_atn_lo);
    cudaGetSymbolAddress((void**)&q_hi, g_q_hi);
    cudaGetSymbolAddress((void**)&q_lo, g_q_lo);
    cudaGetSymbolAddress((void**)&k_hi, g_k_hi);
    cudaGetSymbolAddress((void**)&k_lo, g_k_lo);
    cudaGetSymbolAddress((void**)&v_hi, g_v_hi);
    cudaGetSymbolAddress((void**)&v_lo, g_v_lo);

    cudaFuncSetAttribute(hmma_gemm_kernel,
                         cudaFuncAttributeMaxDynamicSharedMemorySize, GEMM_SMEM);
    cudaFuncSetAttribute(flash_hmma_kernel,
                         cudaFuncAttributeMaxDynamicSharedMemorySize, FLASH_SMEM);

    // 1) split hidden -> bf16 hi/lo
    {
        int n4 = MROWS * HH / 4;
        split_kernel<<<(n4 + 255) / 256, 256>>>(hidden, hid_hi, hid_lo, n4);
    }
    // 2) transpose+split w_qkv
    tsplit_kernel<<<dim3(QKVW / 32, HH / 32), dim3(32, 8)>>>(w_qkv, wqkv_hi, wqkv_lo, HH, QKVW);

    // 3) QKV projection (HMMA split-bf16, 256x128 tiles)
    hmma_gemm_kernel<<<dim3(QKVW / 128, MROWS / 256), 256, GEMM_SMEM>>>(
        hid_hi, hid_lo, wqkv_hi, wqkv_lo, qkv_ptr, MROWS, QKVW, HH);

    // 4) fused RoPE + split (Q pre-scaled)
    {
        int total = MROWS * 11 * 128;
        rope_split_kernel<<<(total + 255) / 256, 256>>>(
            qkv_ptr, positions, q_hi, q_lo, k_hi, k_lo, v_hi, v_lo);
    }

    // 5) HMMA flash attention v2
    {
        dim3 grid2(SS / 128, NHH, BB);
        flash_hmma_kernel<<<grid2, 256, FLASH_SMEM>>>(
            q_hi, q_lo, k_hi, k_lo, v_hi, v_lo, atn_hi, atn_lo);
    }

    // 6) transpose+split w_o
    tsplit_kernel<<<dim3(HH / 32, HH / 32), dim3(32, 8)>>>(w_o, wo_hi, wo_lo, HH, HH);

    // 7) Output projection (HMMA split-bf16, 256x128 tiles)
    hmma_gemm_kernel<<<dim3(HH / 128, MROWS / 256), 256, GEMM_SMEM>>>(
        atn_hi, atn_lo, wo_hi, wo_lo, out, MROWS, HH, HH);
}

// round 8
// speedup vs baseline: 1.2914x; 1.2914x over previous
#include <cuda_runtime.h>
#include <cuda_bf16.h>
#include <cuda_fp16.h>
#include <math.h>
#include <stdint.h>

#define BB 4
#define SS 2048
#define HH 2048
#define NHH 8
#define DD 256
#define QKVW 2560            // (8 + 2*1) * 256
#define MROWS (BB * SS)      // 8192

// ---------------------------------------------------------------------------
// Scratch (allocation-free rule: device globals)
// ---------------------------------------------------------------------------
__device__ float g_qkv[MROWS * QKVW];                         // ~84 MB fp32
__device__ __align__(16) __half g_hid_hi[MROWS * HH];         // fp16 activation splits
__device__ __align__(16) __half g_hid_lo[MROWS * HH];
__device__ __align__(16) __half g_wqkv[QKVW * HH];            // transposed [N][K] fp16
__device__ __align__(16) __half g_wo[HH * HH];                // transposed [N][K] fp16
__device__ __align__(16) __half g_atn_hi[MROWS * HH];
__device__ __align__(16) __half g_atn_lo[MROWS * HH];
__device__ __align__(16) __nv_bfloat16 g_q_hi[(size_t)BB * NHH * SS * DD];
__device__ __align__(16) __nv_bfloat16 g_q_lo[(size_t)BB * NHH * SS * DD];
__device__ __align__(16) __nv_bfloat16 g_k_hi[(size_t)BB * SS * DD];
__device__ __align__(16) __nv_bfloat16 g_k_lo[(size_t)BB * SS * DD];
__device__ __align__(16) __nv_bfloat16 g_v_hi[(size_t)BB * SS * DD];
__device__ __align__(16) __nv_bfloat16 g_v_lo[(size_t)BB * SS * DD];

// ---------------------------------------------------------------------------
// helpers
// ---------------------------------------------------------------------------
__device__ __forceinline__ uint32_t smem_u32(const void* p) {
    uint32_t a;
    asm("{ .reg .u64 t; cvta.to.shared.u64 t, %1; cvt.u32.u64 %0, t; }"
        : "=r"(a) : "l"(p));
    return a;
}

__device__ __forceinline__ void ldsm_x4(uint32_t (&r)[4], uint32_t addr) {
    asm volatile("ldmatrix.sync.aligned.m8n8.x4.shared.b16 {%0,%1,%2,%3}, [%4];"
                 : "=r"(r[0]), "=r"(r[1]), "=r"(r[2]), "=r"(r[3]) : "r"(addr));
}

__device__ __forceinline__ void ldsm_x4_t(uint32_t (&r)[4], uint32_t addr) {
    asm volatile("ldmatrix.sync.aligned.m8n8.x4.trans.shared.b16 {%0,%1,%2,%3}, [%4];"
                 : "=r"(r[0]), "=r"(r[1]), "=r"(r[2]), "=r"(r[3]) : "r"(addr));
}

__device__ __forceinline__ void mma_bf16(float (&d)[4], const uint32_t (&a)[4],
                                         const uint32_t* b) {
    asm volatile(
        "mma.sync.aligned.m16n8k16.row.col.f32.bf16.bf16.f32 "
        "{%0,%1,%2,%3}, {%4,%5,%6,%7}, {%8,%9}, {%0,%1,%2,%3};"
        : "+f"(d[0]), "+f"(d[1]), "+f"(d[2]), "+f"(d[3])
        : "r"(a[0]), "r"(a[1]), "r"(a[2]), "r"(a[3]), "r"(b[0]), "r"(b[1]));
}

__device__ __forceinline__ void mma_f16(float (&d)[4], const uint32_t (&a)[4],
                                        const uint32_t* b) {
    asm volatile(
        "mma.sync.aligned.m16n8k16.row.col.f32.f16.f16.f32 "
        "{%0,%1,%2,%3}, {%4,%5,%6,%7}, {%8,%9}, {%0,%1,%2,%3};"
        : "+f"(d[0]), "+f"(d[1]), "+f"(d[2]), "+f"(d[3])
        : "r"(a[0]), "r"(a[1]), "r"(a[2]), "r"(a[3]), "r"(b[0]), "r"(b[1]));
}

__device__ __forceinline__ void cp16(uint32_t dst, const void* src) {
    asm volatile("cp.async.cg.shared.global [%0], [%1], 16;"
                 :: "r"(dst), "l"(src) : "memory");
}

__device__ __forceinline__ uint32_t pk_bf2(float a, float b) {
    __nv_bfloat162 t = __floats2bfloat162_rn(a, b);
    return *reinterpret_cast<uint32_t*>(&t);
}

__device__ __forceinline__ uint32_t pk_h2(float a, float b) {
    __half2 t = __floats2half2_rn(a, b);
    return *reinterpret_cast<uint32_t*>(&t);
}

// ---------------------------------------------------------------------------
// HMMA fp16 2-pass GEMM: C[M,N] fp32 = (Ahi+Alo)[M,K] @ B[N,K]^T
// Block 128x256x32, 256 threads (8 warps, 2Mx4N), warp tile 64x64.
// 3-stage cp.async, distance-2 prefetch, 1 barrier/chunk.
// Error = weight fp16 rounding only (~2^-12 relative).
// ---------------------------------------------------------------------------
#define ROWB 80                    // 32 fp16 + 16B pad per smem row
#define GA_T (128 * ROWB)          // 10240: one A half (hi or lo)
#define GB_T (256 * ROWB)          // 20480: B tile
#define GSTAGE (2 * GA_T + GB_T)   // 40960
#define GEMM_SMEM (3 * GSTAGE)     // 122880

__global__ __launch_bounds__(256) void hmma_gemm_kernel(
    const __half* __restrict__ Ahi, const __half* __restrict__ Alo,
    const __half* __restrict__ Bw,
    float* __restrict__ C, int M, int N, int K)
{
    extern __shared__ char gsm[];
    const uint32_t base = smem_u32(gsm);

    const int tid = threadIdx.x;
    const int lane = tid & 31;
    const int wid = tid >> 5;
    const int warp_m = wid & 1;          // 2 warps in M: 64 rows each
    const int warp_n = wid >> 1;         // 4 warps in N: 64 cols each
    const int row0 = blockIdx.y * 128, col0 = blockIdx.x * 256;

    float acc[4][8][4];
#pragma unroll
    for (int i = 0; i < 4; i++)
#pragma unroll
        for (int j = 0; j < 8; j++)
#pragma unroll
            for (int e = 0; e < 4; e++) acc[i][j][e] = 0.f;

    const int nch = K >> 5;              // 64 for K=2048

    // stage loader: 2048 x 16B = Ahi(512) Alo(512) B(1024)
    auto load_stage = [&](int st, int k0) {
        const uint32_t sb = base + st * GSTAGE;
#pragma unroll
        for (int i2 = 0; i2 < 8; i2++) {
            int g = tid + (i2 << 8);               // 0..2047
            const __half* src;
            uint32_t dst;
            if (g < 1024) {                        // A halves
                int half = g >> 9;                 // 0:hi 1:lo
                int r = (g >> 2) & 127;
                int kq = g & 3;
                const __half* bp = half ? Alo : Ahi;
                src = bp + (size_t)(row0 + r) * K + k0 + (kq << 3);
                dst = sb + half * GA_T + r * ROWB + (kq << 4);
            } else {                               // B tile (256 rows)
                int g2 = g - 1024;
                int r = g2 >> 2;
                int kq = g2 & 3;
                src = Bw + (size_t)(col0 + r) * K + k0 + (kq << 3);
                dst = sb + 2 * GA_T + r * ROWB + (kq << 4);
            }
            cp16(dst, src);
        }
        asm volatile("cp.async.commit_group;" ::: "memory");
    };

    load_stage(0, 0);
    load_stage(1, 32);

    int st = 0;
    for (int c = 0; c < nch; c++) {
        if (c == nch - 1) { asm volatile("cp.async.wait_group 0;" ::: "memory"); }
        else              { asm volatile("cp.async.wait_group 1;" ::: "memory"); }
        __syncthreads();

        if (c + 2 < nch) {
            int pst = st + 2; if (pst >= 3) pst -= 3;
            load_stage(pst, (c + 2) << 5);
        }

        const uint32_t sb = base + st * GSTAGE;
        const uint32_t aH = sb, bT = sb + 2 * GA_T;

#pragma unroll
        for (int ks = 0; ks < 2; ks++) {
            uint32_t ah[4][4], al[4][4], bw[8][2];
            const int arow = warp_m * 64 + (lane & 15);
            const uint32_t akoff = (ks << 5) + ((lane >> 4) << 4);
#pragma unroll
            for (int i = 0; i < 4; i++) {
                uint32_t ad = aH + (uint32_t)(arow + i * 16) * ROWB + akoff;
                ldsm_x4(ah[i], ad);
                ldsm_x4(al[i], ad + GA_T);
            }
            const int quad = lane >> 3, wi = lane & 7;
#pragma unroll
            for (int t = 0; t < 4; t++) {
                int ntile = 2 * t + (quad >> 1);
                int brow = warp_n * 64 + ntile * 8 + wi;
                uint32_t bd = bT + (uint32_t)brow * ROWB + (ks << 5) + ((quad & 1) << 4);
                uint32_t r4[4];
                ldsm_x4(r4, bd);
                bw[2 * t][0] = r4[0]; bw[2 * t][1] = r4[1];
                bw[2 * t + 1][0] = r4[2]; bw[2 * t + 1][1] = r4[3];
            }
#pragma unroll
            for (int i = 0; i < 4; i++)
#pragma unroll
                for (int j = 0; j < 8; j++) {
                    mma_f16(acc[i][j], ah[i], bw[j]);
                    mma_f16(acc[i][j], al[i], bw[j]);
                }
        }
        if (++st >= 3) st -= 3;
    }

    const int rb = row0 + warp_m * 64 + (lane >> 2);
    const int cb = col0 + warp_n * 64 + (lane & 3) * 2;
#pragma unroll
    for (int i = 0; i < 4; i++)
#pragma unroll
        for (int j = 0; j < 8; j++) {
            float* p0 = C + (size_t)(rb + i * 16) * N + cb + j * 8;
            float* p1 = C + (size_t)(rb + i * 16 + 8) * N + cb + j * 8;
            *(float2*)p0 = make_float2(acc[i][j][0], acc[i][j][1]);
            *(float2*)p1 = make_float2(acc[i][j][2], acc[i][j][3]);
        }
}

// ---------------------------------------------------------------------------
// fp32 -> split fp16 (hi/lo)
// ---------------------------------------------------------------------------
__global__ void split2h_kernel(const float* __restrict__ x,
                               __half* __restrict__ hi,
                               __half* __restrict__ lo, int n4)
{
    int i = blockIdx.x * blockDim.x + threadIdx.x;
    if (i >= n4) return;
    float4 v = ((const float4*)x)[i];
    float vv[4] = {v.x, v.y, v.z, v.w};
    __half hv[4], lv[4];
#pragma unroll
    for (int j = 0; j < 4; j++) {
        hv[j] = __float2half_rn(vv[j]);
        lv[j] = __float2half_rn(vv[j] - __half2float(hv[j]));
    }
    *(uint2*)&hi[(size_t)i * 4] = *(uint2*)hv;
    *(uint2*)&lo[(size_t)i * 4] = *(uint2*)lv;
}

// ---------------------------------------------------------------------------
// fp32 [R][Cn] -> transposed fp16 [Cn][R] (single). 32x32 tiles.
// ---------------------------------------------------------------------------
__global__ void tconvh_kernel(const float* __restrict__ x,
                              __half* __restrict__ w, int R, int Cn)
{
    __shared__ float t[32][33];
    int bc = blockIdx.x * 32, br = blockIdx.y * 32;
    int tx = threadIdx.x, ty = threadIdx.y;
#pragma unroll
    for (int j = 0; j < 32; j += 8)
        t[ty + j][tx] = x[(size_t)(br + ty + j) * Cn + bc + tx];
    __syncthreads();
#pragma unroll
    for (int j = 0; j < 32; j += 8) {
        int orow = bc + ty + j;
        int ocol = br + tx;
        w[(size_t)orow * R + ocol] = __float2half_rn(t[tx][ty + j]);
    }
}

// ---------------------------------------------------------------------------
// Fused RoPE + split (bf16 hi/lo for flash). Q pre-scaled by 1/16.
// ---------------------------------------------------------------------------
__global__ void rope_split_kernel(
    const float* __restrict__ qkv, const int* __restrict__ positions,
    __nv_bfloat16* __restrict__ qhi, __nv_bfloat16* __restrict__ qlo,
    __nv_bfloat16* __restrict__ khi, __nv_bfloat16* __restrict__ klo,
    __nv_bfloat16* __restrict__ vhi, __nv_bfloat16* __restrict__ vlo)
{
    const int total = MROWS * 11 * 128;
    int idx = blockIdx.x * blockDim.x + threadIdx.x;
    if (idx >= total) return;
    int j = idx & 127;
    int t = idx >> 7;
    int unit = t % 11;
    int row = t / 11;
    int s = row & (SS - 1);
    int b = row >> 11;

    if (unit < 9) {
        float pos = (float)positions[s];
        const float LOG_THETA = 9.210340371976184f;
        float e = (float)j * (1.0f / 128.0f);
        float invf = expf(-LOG_THETA * e);
        float ang = pos * invf;
        float sn, cs;
        sincosf(ang, &sn, &cs);

        int inoff = row * QKVW + (unit < 8 ? unit * 256 : 2048);
        float x1 = qkv[inoff + j];
        float x2 = qkv[inoff + 128 + j];
        float y1 = x1 * cs - x2 * sn;
        float y2 = x2 * cs + x1 * sn;

        size_t ooff;
        __nv_bfloat16 *ph, *pl;
        if (unit < 8) {
            y1 *= 0.0625f;
            y2 *= 0.0625f;
            ooff = ((size_t)(b * NHH + unit) * SS + s) * DD;
            ph = qhi; pl = qlo;
        } else {
            ooff = (size_t)row * DD;
            ph = khi; pl = klo;
        }
        __nv_bfloat16 h1 = __float2bfloat16_rn(y1);
        __nv_bfloat16 h2 = __float2bfloat16_rn(y2);
        ph[ooff + j] = h1;
        ph[ooff + 128 + j] = h2;
        pl[ooff + j] = __float2bfloat16_rn(y1 - __bfloat162float(h1));
        pl[ooff + 128 + j] = __float2bfloat16_rn(y2 - __bfloat162float(h2));
    } else {
        int jj = (unit - 9) * 128 + j;
        float v = qkv[row * QKVW + 2304 + jj];
        __nv_bfloat16 h = __float2bfloat16_rn(v);
        vhi[(size_t)row * DD + jj] = h;
        vlo[(size_t)row * DD + jj] = __float2bfloat16_rn(v - __bfloat162float(h));
    }
}

// ---------------------------------------------------------------------------
// HMMA flash attention: Br=128, Bc=32, 256 threads (8 warps), bf16 3-pass.
// Output O written as fp16 hi/lo (input for the 2-pass O-projection).
// ---------------------------------------------------------------------------
#define KSTR 528
#define PSTR 80
#define FQHI 0
#define FQLO (FQHI + 128 * KSTR)
#define FKHI (FQLO + 128 * KSTR)
#define FKLO (FKHI + 32 * KSTR)
#define FVHI (FKLO + 32 * KSTR)
#define FVLO (FVHI + 32 * KSTR)
#define FPHI (FVLO + 32 * KSTR)
#define FPLO (FPHI + 128 * PSTR)
#define FLASH_SMEM (FPLO + 128 * PSTR)

__global__ __launch_bounds__(256) void flash_hmma_kernel(
    const __nv_bfloat16* __restrict__ Qhi, const __nv_bfloat16* __restrict__ Qlo,
    const __nv_bfloat16* __restrict__ Khi, const __nv_bfloat16* __restrict__ Klo,
    const __nv_bfloat16* __restrict__ Vhi, const __nv_bfloat16* __restrict__ Vlo,
    __half* __restrict__ Ohi, __half* __restrict__ Olo)
{
    extern __shared__ char fsm[];
    const uint32_t base = smem_u32(fsm);
    const int qt = (gridDim.x - 1) - blockIdx.x;
    const int h = blockIdx.y, b = blockIdx.z;
    const int tid = threadIdx.x, lane = tid & 31, w = tid >> 5;
    const int q0 = qt * 128;
    const int nj = (q0 + 128) >> 5;

    const __nv_bfloat16* qhp = Qhi + ((size_t)(b * NHH + h) * SS + q0) * DD;
    const __nv_bfloat16* qlp = Qlo + ((size_t)(b * NHH + h) * SS + q0) * DD;
    const __nv_bfloat16* khp = Khi + (size_t)b * SS * DD;
    const __nv_bfloat16* klp = Klo + (size_t)b * SS * DD;
    const __nv_bfloat16* vhp = Vhi + (size_t)b * SS * DD;
    const __nv_bfloat16* vlp = Vlo + (size_t)b * SS * DD;

    {
#pragma unroll
        for (int i = 0; i < 16; i++) {
            int g = tid + (i << 8);
            int r = g >> 5, cq = g & 31;
            cp16(base + FQHI + r * KSTR + (cq << 4),
                 qhp + (size_t)r * DD + (cq << 3));
        }
#pragma unroll
        for (int i = 0; i < 16; i++) {
            int g = tid + (i << 8);
            int r = g >> 5, cq = g & 31;
            cp16(base + FQLO + r * KSTR + (cq << 4),
                 qlp + (size_t)r * DD + (cq << 3));
        }
        asm volatile("cp.async.commit_group;" ::: "memory");
    }

    auto ldkv = [&](uint32_t offhi, uint32_t offlo, const __nv_bfloat16* ph,
                    const __nv_bfloat16* pl, int c0) {
#pragma unroll
        for (int i = 0; i < 4; i++) {
            int g = tid + (i << 8);
            int r = g >> 5, cq = g & 31;
            cp16(base + offhi + r * KSTR + (cq << 4),
                 ph + (size_t)(c0 + r) * DD + (cq << 3));
        }
#pragma unroll
        for (int i = 0; i < 4; i++) {
            int g = tid + (i << 8);
            int r = g >> 5, cq = g & 31;
            cp16(base + offlo + r * KSTR + (cq << 4),
                 pl + (size_t)(c0 + r) * DD + (cq << 3));
        }
        asm volatile("cp.async.commit_group;" ::: "memory");
    };

    ldkv(FKHI, FKLO, khp, klp, 0);
    ldkv(FVHI, FVLO, vhp, vlp, 0);

    float acc[32][4];
#pragma unroll
    for (int t = 0; t < 32; t++)
#pragma unroll
        for (int e = 0; e < 4; e++) acc[t][e] = 0.f;
    float m0 = -1e30f, m1 = -1e30f, l0 = 0.f, l1 = 0.f;

    const uint32_t aQbase = base + FQHI + (w * 16 + (lane & 15)) * KSTR + ((lane >> 4) << 4);
    const int quad = lane >> 3, wi = lane & 7;
    const uint32_t bKbase = base + FKHI + ((quad >> 1) * 8 + wi) * KSTR + ((quad & 1) << 4);
    const uint32_t aPbase = base + FPHI + (w * 16 + (lane & 15)) * PSTR + ((lane >> 4) << 4);
    const uint32_t bVbase = base + FVHI + ((lane & 7) + ((lane >> 3) & 1) * 8) * KSTR
                          + (lane >> 4) * 16;
    const uint32_t pstore = base + FPHI + (w * 16 + (lane >> 2)) * PSTR + (lane & 3) * 4;

    for (int jt = 0; jt < nj; jt++) {
        const int c0 = jt * 32;
        asm volatile("cp.async.wait_group 1;" ::: "memory");
        __syncthreads();

        float sacc[4][4];
#pragma unroll
        for (int t = 0; t < 4; t++)
#pragma unroll
            for (int e = 0; e < 4; e++) sacc[t][e] = 0.f;

#pragma unroll
        for (int ks = 0; ks < 16; ks++) {
            uint32_t ah[4], al[4];
            ldsm_x4(ah, aQbase + ks * 32);
            ldsm_x4(al, aQbase + (FQLO - FQHI) + ks * 32);
#pragma unroll
            for (int np = 0; np < 2; np++) {
                uint32_t bh4[4], bl4[4];
                uint32_t ka = bKbase + np * 16 * KSTR + ks * 32;
                ldsm_x4(bh4, ka);
                ldsm_x4(bl4, ka + (FKLO - FKHI));
                mma_bf16(sacc[2 * np],     ah, bh4);
                mma_bf16(sacc[2 * np],     ah, bl4);
                mma_bf16(sacc[2 * np],     al, bh4);
                mma_bf16(sacc[2 * np + 1], ah, bh4 + 2);
                mma_bf16(sacc[2 * np + 1], ah, bl4 + 2);
                mma_bf16(sacc[2 * np + 1], al, bh4 + 2);
            }
        }
        __syncthreads();
        if (jt + 1 < nj) ldkv(FKHI, FKLO, khp, klp, c0 + 32);

        const int colb = c0 + (lane & 3) * 2;
        const int row0g = q0 + w * 16 + (lane >> 2);
        const int row1g = row0g + 8;
        if (c0 + 31 > q0) {
#pragma unroll
            for (int t = 0; t < 4; t++) {
                int cg = colb + t * 8;
#pragma unroll
                for (int e = 0; e < 4; e++) {
                    int c = cg + (e & 1);
                    int rg = (e < 2) ? row0g : row1g;
                    if (c > rg) sacc[t][e] = -1e30f;
                }
            }
        }
        float mx0 = -1e30f, mx1 = -1e30f;
#pragma unroll
        for (int t = 0; t < 4; t++) {
            mx0 = fmaxf(mx0, fmaxf(sacc[t][0], sacc[t][1]));
            mx1 = fmaxf(mx1, fmaxf(sacc[t][2], sacc[t][3]));
        }
        mx0 = fmaxf(mx0, __shfl_xor_sync(0xffffffffu, mx0, 1));
        mx0 = fmaxf(mx0, __shfl_xor_sync(0xffffffffu, mx0, 2));
        mx1 = fmaxf(mx1, __shfl_xor_sync(0xffffffffu, mx1, 1));
        mx1 = fmaxf(mx1, __shfl_xor_sync(0xffffffffu, mx1, 2));

        float mn0 = fmaxf(m0, mx0), mn1 = fmaxf(m1, mx1);
        float a0 = __expf(m0 - mn0), a1 = __expf(m1 - mn1);
        m0 = mn0; m1 = mn1;
        float s0 = 0.f, s1 = 0.f;
#pragma unroll
        for (int t = 0; t < 4; t++) {
            float p0 = __expf(sacc[t][0] - mn0);
            float p1 = __expf(sacc[t][1] - mn0);
            float p2 = __expf(sacc[t][2] - mn1);
            float p3 = __expf(sacc[t][3] - mn1);
            s0 += p0 + p1; s1 += p2 + p3;
            uint32_t h01 = pk_bf2(p0, p1);
            uint32_t h23 = pk_bf2(p2, p3);
            __nv_bfloat162* hp = (__nv_bfloat162*)&h01;
            __nv_bfloat162* hq = (__nv_bfloat162*)&h23;
            uint32_t lo01 = pk_bf2(p0 - __bfloat162float(hp->x), p1 - __bfloat162float(hp->y));
            uint32_t lo23 = pk_bf2(p2 - __bfloat162float(hq->x), p3 - __bfloat162float(hq->y));
            asm volatile("st.shared.b32 [%0], %1;" :: "r"(pstore + t * 16), "r"(h01) : "memory");
            asm volatile("st.shared.b32 [%0], %1;" :: "r"(pstore + 8 * PSTR + t * 16), "r"(h23) : "memory");
            asm volatile("st.shared.b32 [%0], %1;" :: "r"(pstore + (FPLO - FPHI) + t * 16), "r"(lo01) : "memory");
            asm volatile("st.shared.b32 [%0], %1;" :: "r"(pstore + (FPLO - FPHI) + 8 * PSTR + t * 16), "r"(lo23) : "memory");
        }
        s0 += __shfl_xor_sync(0xffffffffu, s0, 1);
        s0 += __shfl_xor_sync(0xffffffffu, s0, 2);
        s1 += __shfl_xor_sync(0xffffffffu, s1, 1);
        s1 += __shfl_xor_sync(0xffffffffu, s1, 2);
        l0 = l0 * a0 + s0;
        l1 = l1 * a1 + s1;
        bool noresc = __all_sync(0xffffffffu, (a0 == 1.0f) && (a1 == 1.0f));
        if (!noresc) {
#pragma unroll
            for (int t = 0; t < 32; t++) {
                acc[t][0] *= a0; acc[t][1] *= a0;
                acc[t][2] *= a1; acc[t][3] *= a1;
            }
        }

        if (jt + 1 < nj) { asm volatile("cp.async.wait_group 1;" ::: "memory"); }
        else             { asm volatile("cp.async.wait_group 0;" ::: "memory"); }
        __syncthreads();

#pragma unroll
        for (int ks = 0; ks < 2; ks++) {
            uint32_t ph4[4], pl4[4];
            ldsm_x4(ph4, aPbase + ks * 32);
            ldsm_x4(pl4, aPbase + (FPLO - FPHI) + ks * 32);
#pragma unroll
            for (int np = 0; np < 16; np++) {
                uint32_t vh4[4], vl4[4];
                uint32_t va = bVbase + ks * 16 * KSTR + np * 32;
                ldsm_x4_t(vh4, va);
                ldsm_x4_t(vl4, va + (FVLO - FVHI));
                mma_bf16(acc[2 * np],     ph4, vh4);
                mma_bf16(acc[2 * np],     pl4, vh4);
                mma_bf16(acc[2 * np],     ph4, vl4);
                mma_bf16(acc[2 * np + 1], ph4, vh4 + 2);
                mma_bf16(acc[2 * np + 1], pl4, vh4 + 2);
                mma_bf16(acc[2 * np + 1], ph4, vl4 + 2);
            }
        }
        __syncthreads();
        if (jt + 1 < nj) ldkv(FVHI, FVLO, vhp, vlp, c0 + 32);
    }

    // epilogue: write O as fp16 hi/lo (exact split for the 2-pass O-proj)
    float inv0 = 1.0f / l0, inv1 = 1.0f / l1;
    size_t ob0 = ((size_t)(b * SS) + q0 + w * 16 + (lane >> 2)) * HH + h * DD + (lane & 3) * 2;
    size_t ob1 = ob0 + 8 * (size_t)HH;
#pragma unroll
    for (int t = 0; t < 32; t++) {
        float o0 = acc[t][0] * inv0, o1 = acc[t][1] * inv0;
        float o2 = acc[t][2] * inv1, o3 = acc[t][3] * inv1;
        uint32_t h01 = pk_h2(o0, o1);
        uint32_t h23 = pk_h2(o2, o3);
        __half2* hp = (__half2*)&h01;
        __half2* hq = (__half2*)&h23;
        uint32_t lo01 = pk_h2(o0 - __half2float(hp->x), o1 - __half2float(hp->y));
        uint32_t lo23 = pk_h2(o2 - __half2float(hq->x), o3 - __half2float(hq->y));
        *(uint32_t*)&Ohi[ob0 + t * 8] = h01;
        *(uint32_t*)&Ohi[ob1 + t * 8] = h23;
        *(uint32_t*)&Olo[ob0 + t * 8] = lo01;
        *(uint32_t*)&Olo[ob1 + t * 8] = lo23;
    }
}

// ---------------------------------------------------------------------------
extern "C" void kernel_launch(void* const* d_in, const int* in_sizes, int n_in,
                              void* d_out, int out_size)
{
    const float* hidden    = (const float*)d_in[0];
    const int*   positions = (const int*)d_in[1];
    const float* w_qkv     = (const float*)d_in[2];
    const float* w_o       = (const float*)d_in[3];
    float* out = (float*)d_out;

    float* qkv_ptr;
    __half *hid_hi, *hid_lo, *wqkv_p, *wo_p, *atn_hi, *atn_lo;
    __nv_bfloat16 *q_hi, *q_lo, *k_hi, *k_lo, *v_hi, *v_lo;
    cudaGetSymbolAddress((void**)&qkv_ptr, g_qkv);
    cudaGetSymbolAddress((void**)&hid_hi, g_hid_hi);
    cudaGetSymbolAddress((void**)&hid_lo, g_hid_lo);
    cudaGetSymbolAddress((void**)&wqkv_p, g_wqkv);
    cudaGetSymbolAddress((void**)&wo_p, g_wo);
    cudaGetSymbolAddress((void**)&atn_hi, g_atn_hi);
    cudaGetSymbolAddress((void**)&atn_lo, g_atn_lo);
    cudaGetSymbolAddress((void**)&q_hi, g_q_hi);
    cudaGetSymbolAddress((void**)&q_lo, g_q_lo);
    cudaGetSymbolAddress((void**)&k_hi, g_k_hi);
    cudaGetSymbolAddress((void**)&k_lo, g_k_lo);
    cudaGetSymbolAddress((void**)&v_hi, g_v_hi);
    cudaGetSymbolAddress((void**)&v_lo, g_v_lo);

    cudaFuncSetAttribute(hmma_gemm_kernel,
                         cudaFuncAttributeMaxDynamicSharedMemorySize, GEMM_SMEM);
    cudaFuncSetAttribute(flash_hmma_kernel,
                         cudaFuncAttributeMaxDynamicSharedMemorySize, FLASH_SMEM);

    // 1) split hidden -> fp16 hi/lo
    {
        int n4 = MROWS * HH / 4;
        split2h_kernel<<<(n4 + 255) / 256, 256>>>(hidden, hid_hi, hid_lo, n4);
    }
    // 2) transpose+convert w_qkv -> fp16 [N][K]
    tconvh_kernel<<<dim3(QKVW / 32, HH / 32), dim3(32, 8)>>>(w_qkv, wqkv_p, HH, QKVW);

    // 3) QKV projection (fp16 2-pass, 128x256 tiles)
    hmma_gemm_kernel<<<dim3(QKVW / 256, MROWS / 128), 256, GEMM_SMEM>>>(
        hid_hi, hid_lo, wqkv_p, qkv_ptr, MROWS, QKVW, HH);

    // 4) fused RoPE + split (bf16, Q pre-scaled)
    {
        int total = MROWS * 11 * 128;
        rope_split_kernel<<<(total + 255) / 256, 256>>>(
            qkv_ptr, positions, q_hi, q_lo, k_hi, k_lo, v_hi, v_lo);
    }

    // 5) HMMA flash attention (bf16 3-pass) -> O fp16 hi/lo
    {
        dim3 grid2(SS / 128, NHH, BB);
        flash_hmma_kernel<<<grid2, 256, FLASH_SMEM>>>(
            q_hi, q_lo, k_hi, k_lo, v_hi, v_lo, atn_hi, atn_lo);
    }

    // 6) transpose+convert w_o -> fp16 [N][K]
    tconvh_kernel<<<dim3(HH / 32, HH / 32), dim3(32, 8)>>>(w_o, wo_p, HH, HH);

    // 7) Output projection (fp16 2-pass, 128x256 tiles)
    hmma_gemm_kernel<<<dim3(HH / 256, MROWS / 128), 256, GEMM_SMEM>>>(
        atn_hi, atn_lo, wo_p, out, MROWS, HH, HH);
}

// round 9
// speedup vs baseline: 1.4750x; 1.1422x over previous
#include <cuda_runtime.h>
#include <cuda_bf16.h>
#include <cuda_fp16.h>
#include <math.h>
#include <stdint.h>

#define BB 4
#define SS 2048
#define HH 2048
#define NHH 8
#define DD 256
#define QKVW 2560            // (8 + 2*1) * 256
#define MROWS (BB * SS)      // 8192

// ---------------------------------------------------------------------------
// Scratch (allocation-free rule: device globals)
// ---------------------------------------------------------------------------
__device__ float g_qkv[MROWS * QKVW];                         // ~84 MB fp32
__device__ __align__(16) __half g_hid_hi[MROWS * HH];         // fp16 activation splits
__device__ __align__(16) __half g_hid_lo[MROWS * HH];
__device__ __align__(16) __half g_wqkv[QKVW * HH];            // transposed [N][K] fp16
__device__ __align__(16) __half g_wo[HH * HH];                // transposed [N][K] fp16
__device__ __align__(16) __half g_atn_hi[MROWS * HH];
__device__ __align__(16) __half g_atn_lo[MROWS * HH];
__device__ __align__(16) __half g_q_hi[(size_t)BB * NHH * SS * DD];
__device__ __align__(16) __half g_q_lo[(size_t)BB * NHH * SS * DD];
__device__ __align__(16) __half g_k[(size_t)BB * SS * DD];    // single fp16
__device__ __align__(16) __half g_v[(size_t)BB * SS * DD];    // single fp16

// ---------------------------------------------------------------------------
// helpers
// ---------------------------------------------------------------------------
__device__ __forceinline__ uint32_t smem_u32(const void* p) {
    uint32_t a;
    asm("{ .reg .u64 t; cvta.to.shared.u64 t, %1; cvt.u32.u64 %0, t; }"
        : "=r"(a) : "l"(p));
    return a;
}

__device__ __forceinline__ void ldsm_x4(uint32_t (&r)[4], uint32_t addr) {
    asm volatile("ldmatrix.sync.aligned.m8n8.x4.shared.b16 {%0,%1,%2,%3}, [%4];"
                 : "=r"(r[0]), "=r"(r[1]), "=r"(r[2]), "=r"(r[3]) : "r"(addr));
}

__device__ __forceinline__ void ldsm_x4_t(uint32_t (&r)[4], uint32_t addr) {
    asm volatile("ldmatrix.sync.aligned.m8n8.x4.trans.shared.b16 {%0,%1,%2,%3}, [%4];"
                 : "=r"(r[0]), "=r"(r[1]), "=r"(r[2]), "=r"(r[3]) : "r"(addr));
}

__device__ __forceinline__ void mma_f16(float (&d)[4], const uint32_t (&a)[4],
                                        const uint32_t* b) {
    asm volatile(
        "mma.sync.aligned.m16n8k16.row.col.f32.f16.f16.f32 "
        "{%0,%1,%2,%3}, {%4,%5,%6,%7}, {%8,%9}, {%0,%1,%2,%3};"
        : "+f"(d[0]), "+f"(d[1]), "+f"(d[2]), "+f"(d[3])
        : "r"(a[0]), "r"(a[1]), "r"(a[2]), "r"(a[3]), "r"(b[0]), "r"(b[1]));
}

__device__ __forceinline__ void cp16(uint32_t dst, const void* src) {
    asm volatile("cp.async.cg.shared.global [%0], [%1], 16;"
                 :: "r"(dst), "l"(src) : "memory");
}

__device__ __forceinline__ uint32_t pk_h2(float a, float b) {
    __half2 t = __floats2half2_rn(a, b);
    return *reinterpret_cast<uint32_t*>(&t);
}

// ---------------------------------------------------------------------------
// HMMA fp16 2-pass GEMM: C[M,N] fp32 = (Ahi+Alo)[M,K] @ B[N,K]^T
// Block 128x256x32, 256 threads (8 warps, 2Mx4N), warp tile 64x64. (verified R8)
// ---------------------------------------------------------------------------
#define ROWB 80
#define GA_T (128 * ROWB)
#define GB_T (256 * ROWB)
#define GSTAGE (2 * GA_T + GB_T)
#define GEMM_SMEM (3 * GSTAGE)

__global__ __launch_bounds__(256) void hmma_gemm_kernel(
    const __half* __restrict__ Ahi, const __half* __restrict__ Alo,
    const __half* __restrict__ Bw,
    float* __restrict__ C, int M, int N, int K)
{
    extern __shared__ char gsm[];
    const uint32_t base = smem_u32(gsm);

    const int tid = threadIdx.x;
    const int lane = tid & 31;
    const int wid = tid >> 5;
    const int warp_m = wid & 1;
    const int warp_n = wid >> 1;
    const int row0 = blockIdx.y * 128, col0 = blockIdx.x * 256;

    float acc[4][8][4];
#pragma unroll
    for (int i = 0; i < 4; i++)
#pragma unroll
        for (int j = 0; j < 8; j++)
#pragma unroll
            for (int e = 0; e < 4; e++) acc[i][j][e] = 0.f;

    const int nch = K >> 5;

    auto load_stage = [&](int st, int k0) {
        const uint32_t sb = base + st * GSTAGE;
#pragma unroll
        for (int i2 = 0; i2 < 8; i2++) {
            int g = tid + (i2 << 8);
            const __half* src;
            uint32_t dst;
            if (g < 1024) {
                int half = g >> 9;
                int r = (g >> 2) & 127;
                int kq = g & 3;
                const __half* bp = half ? Alo : Ahi;
                src = bp + (size_t)(row0 + r) * K + k0 + (kq << 3);
                dst = sb + half * GA_T + r * ROWB + (kq << 4);
            } else {
                int g2 = g - 1024;
                int r = g2 >> 2;
                int kq = g2 & 3;
                src = Bw + (size_t)(col0 + r) * K + k0 + (kq << 3);
                dst = sb + 2 * GA_T + r * ROWB + (kq << 4);
            }
            cp16(dst, src);
        }
        asm volatile("cp.async.commit_group;" ::: "memory");
    };

    load_stage(0, 0);
    load_stage(1, 32);

    int st = 0;
    for (int c = 0; c < nch; c++) {
        if (c == nch - 1) { asm volatile("cp.async.wait_group 0;" ::: "memory"); }
        else              { asm volatile("cp.async.wait_group 1;" ::: "memory"); }
        __syncthreads();

        if (c + 2 < nch) {
            int pst = st + 2; if (pst >= 3) pst -= 3;
            load_stage(pst, (c + 2) << 5);
        }

        const uint32_t sb = base + st * GSTAGE;
        const uint32_t aH = sb, bT = sb + 2 * GA_T;

#pragma unroll
        for (int ks = 0; ks < 2; ks++) {
            uint32_t ah[4][4], al[4][4], bw[8][2];
            const int arow = warp_m * 64 + (lane & 15);
            const uint32_t akoff = (ks << 5) + ((lane >> 4) << 4);
#pragma unroll
            for (int i = 0; i < 4; i++) {
                uint32_t ad = aH + (uint32_t)(arow + i * 16) * ROWB + akoff;
                ldsm_x4(ah[i], ad);
                ldsm_x4(al[i], ad + GA_T);
            }
            const int quad = lane >> 3, wi = lane & 7;
#pragma unroll
            for (int t = 0; t < 4; t++) {
                int ntile = 2 * t + (quad >> 1);
                int brow = warp_n * 64 + ntile * 8 + wi;
                uint32_t bd = bT + (uint32_t)brow * ROWB + (ks << 5) + ((quad & 1) << 4);
                uint32_t r4[4];
                ldsm_x4(r4, bd);
                bw[2 * t][0] = r4[0]; bw[2 * t][1] = r4[1];
                bw[2 * t + 1][0] = r4[2]; bw[2 * t + 1][1] = r4[3];
            }
#pragma unroll
            for (int i = 0; i < 4; i++)
#pragma unroll
                for (int j = 0; j < 8; j++) {
                    mma_f16(acc[i][j], ah[i], bw[j]);
                    mma_f16(acc[i][j], al[i], bw[j]);
                }
        }
        if (++st >= 3) st -= 3;
    }

    const int rb = row0 + warp_m * 64 + (lane >> 2);
    const int cb = col0 + warp_n * 64 + (lane & 3) * 2;
#pragma unroll
    for (int i = 0; i < 4; i++)
#pragma unroll
        for (int j = 0; j < 8; j++) {
            float* p0 = C + (size_t)(rb + i * 16) * N + cb + j * 8;
            float* p1 = C + (size_t)(rb + i * 16 + 8) * N + cb + j * 8;
            *(float2*)p0 = make_float2(acc[i][j][0], acc[i][j][1]);
            *(float2*)p1 = make_float2(acc[i][j][2], acc[i][j][3]);
        }
}

// ---------------------------------------------------------------------------
// fp32 -> split fp16 (hi/lo)
// ---------------------------------------------------------------------------
__global__ void split2h_kernel(const float* __restrict__ x,
                               __half* __restrict__ hi,
                               __half* __restrict__ lo, int n4)
{
    int i = blockIdx.x * blockDim.x + threadIdx.x;
    if (i >= n4) return;
    float4 v = ((const float4*)x)[i];
    float vv[4] = {v.x, v.y, v.z, v.w};
    __half hv[4], lv[4];
#pragma unroll
    for (int j = 0; j < 4; j++) {
        hv[j] = __float2half_rn(vv[j]);
        lv[j] = __float2half_rn(vv[j] - __half2float(hv[j]));
    }
    *(uint2*)&hi[(size_t)i * 4] = *(uint2*)hv;
    *(uint2*)&lo[(size_t)i * 4] = *(uint2*)lv;
}

// ---------------------------------------------------------------------------
// fp32 [R][Cn] -> transposed fp16 [Cn][R]. 32x32 tiles.
// ---------------------------------------------------------------------------
__global__ void tconvh_kernel(const float* __restrict__ x,
                              __half* __restrict__ w, int R, int Cn)
{
    __shared__ float t[32][33];
    int bc = blockIdx.x * 32, br = blockIdx.y * 32;
    int tx = threadIdx.x, ty = threadIdx.y;
#pragma unroll
    for (int j = 0; j < 32; j += 8)
        t[ty + j][tx] = x[(size_t)(br + ty + j) * Cn + bc + tx];
    __syncthreads();
#pragma unroll
    for (int j = 0; j < 32; j += 8) {
        int orow = bc + ty + j;
        int ocol = br + tx;
        w[(size_t)orow * R + ocol] = __float2half_rn(t[tx][ty + j]);
    }
}

// ---------------------------------------------------------------------------
// Fused RoPE + split: Q -> fp16 hi/lo (pre-scaled 1/16), K,V -> single fp16
// ---------------------------------------------------------------------------
__global__ void rope_split_kernel(
    const float* __restrict__ qkv, const int* __restrict__ positions,
    __half* __restrict__ qhi, __half* __restrict__ qlo,
    __half* __restrict__ kk, __half* __restrict__ vv)
{
    const int total = MROWS * 11 * 128;
    int idx = blockIdx.x * blockDim.x + threadIdx.x;
    if (idx >= total) return;
    int j = idx & 127;
    int t = idx >> 7;
    int unit = t % 11;
    int row = t / 11;
    int s = row & (SS - 1);
    int b = row >> 11;

    if (unit < 9) {
        float pos = (float)positions[s];
        const float LOG_THETA = 9.210340371976184f;
        float e = (float)j * (1.0f / 128.0f);
        float invf = expf(-LOG_THETA * e);
        float ang = pos * invf;
        float sn, cs;
        sincosf(ang, &sn, &cs);

        int inoff = row * QKVW + (unit < 8 ? unit * 256 : 2048);
        float x1 = qkv[inoff + j];
        float x2 = qkv[inoff + 128 + j];
        float y1 = x1 * cs - x2 * sn;
        float y2 = x2 * cs + x1 * sn;

        if (unit < 8) {
            y1 *= 0.0625f;
            y2 *= 0.0625f;
            size_t ooff = ((size_t)(b * NHH + unit) * SS + s) * DD;
            __half h1 = __float2half_rn(y1);
            __half h2 = __float2half_rn(y2);
            qhi[ooff + j] = h1;
            qhi[ooff + 128 + j] = h2;
            qlo[ooff + j] = __float2half_rn(y1 - __half2float(h1));
            qlo[ooff + 128 + j] = __float2half_rn(y2 - __half2float(h2));
        } else {
            size_t ooff = (size_t)row * DD;
            kk[ooff + j] = __float2half_rn(y1);
            kk[ooff + 128 + j] = __float2half_rn(y2);
        }
    } else {
        int jj = (unit - 9) * 128 + j;
        float v = qkv[row * QKVW + 2304 + jj];
        vv[(size_t)row * DD + jj] = __float2half_rn(v);
    }
}

// ---------------------------------------------------------------------------
// HMMA flash attention fp16 2-pass: Br=128, Bc=32, 256 threads (8 warps).
// S = (Qhi+Qlo)·K,  O = (Phi+Plo)·V,  K/V single fp16.
// ---------------------------------------------------------------------------
#define KSTR 528
#define PSTR 80
#define FQHI 0
#define FQLO (FQHI + 128 * KSTR)       // 67584
#define FK   (FQLO + 128 * KSTR)       // 135168
#define FV   (FK + 32 * KSTR)          // 152064
#define FPHI (FV + 32 * KSTR)          // 168960
#define FPLO (FPHI + 128 * PSTR)       // 179200
#define FLASH_SMEM (FPLO + 128 * PSTR) // 189440

__global__ __launch_bounds__(256) void flash_hmma_kernel(
    const __half* __restrict__ Qhi, const __half* __restrict__ Qlo,
    const __half* __restrict__ Kp, const __half* __restrict__ Vp,
    __half* __restrict__ Ohi, __half* __restrict__ Olo)
{
    extern __shared__ char fsm[];
    const uint32_t base = smem_u32(fsm);
    const int qt = (gridDim.x - 1) - blockIdx.x;
    const int h = blockIdx.y, b = blockIdx.z;
    const int tid = threadIdx.x, lane = tid & 31, w = tid >> 5;
    const int q0 = qt * 128;
    const int nj = (q0 + 128) >> 5;

    const __half* qhp = Qhi + ((size_t)(b * NHH + h) * SS + q0) * DD;
    const __half* qlp = Qlo + ((size_t)(b * NHH + h) * SS + q0) * DD;
    const __half* kp = Kp + (size_t)b * SS * DD;
    const __half* vp = Vp + (size_t)b * SS * DD;

    // Q hi+lo load: one group
    {
#pragma unroll
        for (int i = 0; i < 16; i++) {
            int g = tid + (i << 8);
            int r = g >> 5, cq = g & 31;
            cp16(base + FQHI + r * KSTR + (cq << 4),
                 qhp + (size_t)r * DD + (cq << 3));
        }
#pragma unroll
        for (int i = 0; i < 16; i++) {
            int g = tid + (i << 8);
            int r = g >> 5, cq = g & 31;
            cp16(base + FQLO + r * KSTR + (cq << 4),
                 qlp + (size_t)r * DD + (cq << 3));
        }
        asm volatile("cp.async.commit_group;" ::: "memory");
    }

    // single-buffer K/V tile loader: 32 rows, one group
    auto ldkv = [&](uint32_t off, const __half* p, int c0) {
#pragma unroll
        for (int i = 0; i < 4; i++) {
            int g = tid + (i << 8);
            int r = g >> 5, cq = g & 31;
            cp16(base + off + r * KSTR + (cq << 4),
                 p + (size_t)(c0 + r) * DD + (cq << 3));
        }
        asm volatile("cp.async.commit_group;" ::: "memory");
    };

    ldkv(FK, kp, 0);
    ldkv(FV, vp, 0);

    float acc[32][4];
#pragma unroll
    for (int t = 0; t < 32; t++)
#pragma unroll
        for (int e = 0; e < 4; e++) acc[t][e] = 0.f;
    float m0 = -1e30f, m1 = -1e30f, l0 = 0.f, l1 = 0.f;

    const uint32_t aQbase = base + FQHI + (w * 16 + (lane & 15)) * KSTR + ((lane >> 4) << 4);
    const int quad = lane >> 3, wi = lane & 7;
    const uint32_t bKbase = base + FK + ((quad >> 1) * 8 + wi) * KSTR + ((quad & 1) << 4);
    const uint32_t aPbase = base + FPHI + (w * 16 + (lane & 15)) * PSTR + ((lane >> 4) << 4);
    const uint32_t bVbase = base + FV + ((lane & 7) + ((lane >> 3) & 1) * 8) * KSTR
                          + (lane >> 4) * 16;
    const uint32_t pstore = base + FPHI + (w * 16 + (lane >> 2)) * PSTR + (lane & 3) * 4;

    for (int jt = 0; jt < nj; jt++) {
        const int c0 = jt * 32;
        asm volatile("cp.async.wait_group 1;" ::: "memory");
        __syncthreads();

        // ---------------- S = (Qhi+Qlo) K^T ----------------
        float sacc[4][4];
#pragma unroll
        for (int t = 0; t < 4; t++)
#pragma unroll
            for (int e = 0; e < 4; e++) sacc[t][e] = 0.f;

#pragma unroll
        for (int ks = 0; ks < 16; ks++) {
            uint32_t ah[4], al[4];
            ldsm_x4(ah, aQbase + ks * 32);
            ldsm_x4(al, aQbase + (FQLO - FQHI) + ks * 32);
#pragma unroll
            for (int np = 0; np < 2; np++) {
                uint32_t bh4[4];
                ldsm_x4(bh4, bKbase + np * 16 * KSTR + ks * 32);
                mma_f16(sacc[2 * np],     ah, bh4);
                mma_f16(sacc[2 * np],     al, bh4);
                mma_f16(sacc[2 * np + 1], ah, bh4 + 2);
                mma_f16(sacc[2 * np + 1], al, bh4 + 2);
            }
        }
        __syncthreads();
        if (jt + 1 < nj) ldkv(FK, kp, c0 + 32);

        // ---------------- softmax ----------------
        const int colb = c0 + (lane & 3) * 2;
        const int row0g = q0 + w * 16 + (lane >> 2);
        const int row1g = row0g + 8;
        if (c0 + 31 > q0) {
#pragma unroll
            for (int t = 0; t < 4; t++) {
                int cg = colb + t * 8;
#pragma unroll
                for (int e = 0; e < 4; e++) {
                    int c = cg + (e & 1);
                    int rg = (e < 2) ? row0g : row1g;
                    if (c > rg) sacc[t][e] = -1e30f;
                }
            }
        }
        float mx0 = -1e30f, mx1 = -1e30f;
#pragma unroll
        for (int t = 0; t < 4; t++) {
            mx0 = fmaxf(mx0, fmaxf(sacc[t][0], sacc[t][1]));
            mx1 = fmaxf(mx1, fmaxf(sacc[t][2], sacc[t][3]));
        }
        mx0 = fmaxf(mx0, __shfl_xor_sync(0xffffffffu, mx0, 1));
        mx0 = fmaxf(mx0, __shfl_xor_sync(0xffffffffu, mx0, 2));
        mx1 = fmaxf(mx1, __shfl_xor_sync(0xffffffffu, mx1, 1));
        mx1 = fmaxf(mx1, __shfl_xor_sync(0xffffffffu, mx1, 2));

        float mn0 = fmaxf(m0, mx0), mn1 = fmaxf(m1, mx1);
        float a0 = __expf(m0 - mn0), a1 = __expf(m1 - mn1);
        m0 = mn0; m1 = mn1;
        float s0 = 0.f, s1 = 0.f;
#pragma unroll
        for (int t = 0; t < 4; t++) {
            float p0 = __expf(sacc[t][0] - mn0);
            float p1 = __expf(sacc[t][1] - mn0);
            float p2 = __expf(sacc[t][2] - mn1);
            float p3 = __expf(sacc[t][3] - mn1);
            s0 += p0 + p1; s1 += p2 + p3;
            uint32_t h01 = pk_h2(p0, p1);
            uint32_t h23 = pk_h2(p2, p3);
            __half2* hp = (__half2*)&h01;
            __half2* hq = (__half2*)&h23;
            uint32_t lo01 = pk_h2(p0 - __half2float(hp->x), p1 - __half2float(hp->y));
            uint32_t lo23 = pk_h2(p2 - __half2float(hq->x), p3 - __half2float(hq->y));
            asm volatile("st.shared.b32 [%0], %1;" :: "r"(pstore + t * 16), "r"(h01) : "memory");
            asm volatile("st.shared.b32 [%0], %1;" :: "r"(pstore + 8 * PSTR + t * 16), "r"(h23) : "memory");
            asm volatile("st.shared.b32 [%0], %1;" :: "r"(pstore + (FPLO - FPHI) + t * 16), "r"(lo01) : "memory");
            asm volatile("st.shared.b32 [%0], %1;" :: "r"(pstore + (FPLO - FPHI) + 8 * PSTR + t * 16), "r"(lo23) : "memory");
        }
        s0 += __shfl_xor_sync(0xffffffffu, s0, 1);
        s0 += __shfl_xor_sync(0xffffffffu, s0, 2);
        s1 += __shfl_xor_sync(0xffffffffu, s1, 1);
        s1 += __shfl_xor_sync(0xffffffffu, s1, 2);
        l0 = l0 * a0 + s0;
        l1 = l1 * a1 + s1;
        bool noresc = __all_sync(0xffffffffu, (a0 == 1.0f) && (a1 == 1.0f));
        if (!noresc) {
#pragma unroll
            for (int t = 0; t < 32; t++) {
                acc[t][0] *= a0; acc[t][1] *= a0;
                acc[t][2] *= a1; acc[t][3] *= a1;
            }
        }

        if (jt + 1 < nj) { asm volatile("cp.async.wait_group 1;" ::: "memory"); }
        else             { asm volatile("cp.async.wait_group 0;" ::: "memory"); }
        __syncthreads();

        // ---------------- O += (Phi+Plo) V ----------------
#pragma unroll
        for (int ks = 0; ks < 2; ks++) {
            uint32_t ph4[4], pl4[4];
            ldsm_x4(ph4, aPbase + ks * 32);
            ldsm_x4(pl4, aPbase + (FPLO - FPHI) + ks * 32);
#pragma unroll
            for (int np = 0; np < 16; np++) {
                uint32_t vh4[4];
                ldsm_x4_t(vh4, bVbase + ks * 16 * KSTR + np * 32);
                mma_f16(acc[2 * np],     ph4, vh4);
                mma_f16(acc[2 * np],     pl4, vh4);
                mma_f16(acc[2 * np + 1], ph4, vh4 + 2);
                mma_f16(acc[2 * np + 1], pl4, vh4 + 2);
            }
        }
        __syncthreads();
        if (jt + 1 < nj) ldkv(FV, vp, c0 + 32);
    }

    // epilogue: write O as fp16 hi/lo (input for the 2-pass O-proj)
    float inv0 = 1.0f / l0, inv1 = 1.0f / l1;
    size_t ob0 = ((size_t)(b * SS) + q0 + w * 16 + (lane >> 2)) * HH + h * DD + (lane & 3) * 2;
    size_t ob1 = ob0 + 8 * (size_t)HH;
#pragma unroll
    for (int t = 0; t < 32; t++) {
        float o0 = acc[t][0] * inv0, o1 = acc[t][1] * inv0;
        float o2 = acc[t][2] * inv1, o3 = acc[t][3] * inv1;
        uint32_t h01 = pk_h2(o0, o1);
        uint32_t h23 = pk_h2(o2, o3);
        __half2* hp = (__half2*)&h01;
        __half2* hq = (__half2*)&h23;
        uint32_t lo01 = pk_h2(o0 - __half2float(hp->x), o1 - __half2float(hp->y));
        uint32_t lo23 = pk_h2(o2 - __half2float(hq->x), o3 - __half2float(hq->y));
        *(uint32_t*)&Ohi[ob0 + t * 8] = h01;
        *(uint32_t*)&Ohi[ob1 + t * 8] = h23;
        *(uint32_t*)&Olo[ob0 + t * 8] = lo01;
        *(uint32_t*)&Olo[ob1 + t * 8] = lo23;
    }
}

// ---------------------------------------------------------------------------
extern "C" void kernel_launch(void* const* d_in, const int* in_sizes, int n_in,
                              void* d_out, int out_size)
{
    const float* hidden    = (const float*)d_in[0];
    const int*   positions = (const int*)d_in[1];
    const float* w_qkv     = (const float*)d_in[2];
    const float* w_o       = (const float*)d_in[3];
    float* out = (float*)d_out;

    float* qkv_ptr;
    __half *hid_hi, *hid_lo, *wqkv_p, *wo_p, *atn_hi, *atn_lo;
    __half *q_hi, *q_lo, *k_p, *v_p;
    cudaGetSymbolAddress((void**)&qkv_ptr, g_qkv);
    cudaGetSymbolAddress((void**)&hid_hi, g_hid_hi);
    cudaGetSymbolAddress((void**)&hid_lo, g_hid_lo);
    cudaGetSymbolAddress((void**)&wqkv_p, g_wqkv);
    cudaGetSymbolAddress((void**)&wo_p, g_wo);
    cudaGetSymbolAddress((void**)&atn_hi, g_atn_hi);
    cudaGetSymbolAddress((void**)&atn_lo, g_atn_lo);
    cudaGetSymbolAddress((void**)&q_hi, g_q_hi);
    cudaGetSymbolAddress((void**)&q_lo, g_q_lo);
    cudaGetSymbolAddress((void**)&k_p, g_k);
    cudaGetSymbolAddress((void**)&v_p, g_v);

    cudaFuncSetAttribute(hmma_gemm_kernel,
                         cudaFuncAttributeMaxDynamicSharedMemorySize, GEMM_SMEM);
    cudaFuncSetAttribute(flash_hmma_kernel,
                         cudaFuncAttributeMaxDynamicSharedMemorySize, FLASH_SMEM);

    // 1) split hidden -> fp16 hi/lo
    {
        int n4 = MROWS * HH / 4;
        split2h_kernel<<<(n4 + 255) / 256, 256>>>(hidden, hid_hi, hid_lo, n4);
    }
    // 2) transpose+convert w_qkv -> fp16 [N][K]
    tconvh_kernel<<<dim3(QKVW / 32, HH / 32), dim3(32, 8)>>>(w_qkv, wqkv_p, HH, QKVW);

    // 3) QKV projection (fp16 2-pass)
    hmma_gemm_kernel<<<dim3(QKVW / 256, MROWS / 128), 256, GEMM_SMEM>>>(
        hid_hi, hid_lo, wqkv_p, qkv_ptr, MROWS, QKVW, HH);

    // 4) fused RoPE + split: Q fp16 hi/lo (pre-scaled), K/V single fp16
    {
        int total = MROWS * 11 * 128;
        rope_split_kernel<<<(total + 255) / 256, 256>>>(
            qkv_ptr, positions, q_hi, q_lo, k_p, v_p);
    }

    // 5) HMMA flash attention (fp16 2-pass) -> O fp16 hi/lo
    {
        dim3 grid2(SS / 128, NHH, BB);
        flash_hmma_kernel<<<grid2, 256, FLASH_SMEM>>>(
            q_hi, q_lo, k_p, v_p, atn_hi, atn_lo);
    }

    // 6) transpose+convert w_o -> fp16 [N][K]
    tconvh_kernel<<<dim3(HH / 32, HH / 32), dim3(32, 8)>>>(w_o, wo_p, HH, HH);

    // 7) Output projection (fp16 2-pass)
    hmma_gemm_kernel<<<dim3(HH / 256, MROWS / 128), 256, GEMM_SMEM>>>(
        atn_hi, atn_lo, wo_p, out, MROWS, HH, HH);
}

// round 10
// speedup vs baseline: 1.7924x; 1.2151x over previous
#include <cuda_runtime.h>
#include <cuda_bf16.h>
#include <cuda_fp16.h>
#include <math.h>
#include <stdint.h>

#define BB 4
#define SS 2048
#define HH 2048
#define NHH 8
#define DD 256
#define QKVW 2560            // (8 + 2*1) * 256
#define MROWS (BB * SS)      // 8192

// ---------------------------------------------------------------------------
// Scratch (allocation-free rule: device globals)
// ---------------------------------------------------------------------------
__device__ float g_qkv[MROWS * QKVW];                         // ~84 MB fp32
__device__ __align__(16) __half g_hid_hi[MROWS * HH];         // fp16 activation splits
__device__ __align__(16) __half g_hid_lo[MROWS * HH];
__device__ __align__(16) __half g_wqkv[QKVW * HH];            // transposed [N][K] fp16
__device__ __align__(16) __half g_wo[HH * HH];                // transposed [N][K] fp16
__device__ __align__(16) __half g_atn[MROWS * HH];            // attention out, single fp16
__device__ __align__(16) __half g_q[(size_t)BB * NHH * SS * DD];  // single fp16
__device__ __align__(16) __half g_k[(size_t)BB * SS * DD];
__device__ __align__(16) __half g_v[(size_t)BB * SS * DD];

// ---------------------------------------------------------------------------
// helpers
// ---------------------------------------------------------------------------
__device__ __forceinline__ uint32_t smem_u32(const void* p) {
    uint32_t a;
    asm("{ .reg .u64 t; cvta.to.shared.u64 t, %1; cvt.u32.u64 %0, t; }"
        : "=r"(a) : "l"(p));
    return a;
}

__device__ __forceinline__ void ldsm_x4(uint32_t (&r)[4], uint32_t addr) {
    asm volatile("ldmatrix.sync.aligned.m8n8.x4.shared.b16 {%0,%1,%2,%3}, [%4];"
                 : "=r"(r[0]), "=r"(r[1]), "=r"(r[2]), "=r"(r[3]) : "r"(addr));
}

__device__ __forceinline__ void ldsm_x4_t(uint32_t (&r)[4], uint32_t addr) {
    asm volatile("ldmatrix.sync.aligned.m8n8.x4.trans.shared.b16 {%0,%1,%2,%3}, [%4];"
                 : "=r"(r[0]), "=r"(r[1]), "=r"(r[2]), "=r"(r[3]) : "r"(addr));
}

__device__ __forceinline__ void mma_f16(float (&d)[4], const uint32_t (&a)[4],
                                        const uint32_t* b) {
    asm volatile(
        "mma.sync.aligned.m16n8k16.row.col.f32.f16.f16.f32 "
        "{%0,%1,%2,%3}, {%4,%5,%6,%7}, {%8,%9}, {%0,%1,%2,%3};"
        : "+f"(d[0]), "+f"(d[1]), "+f"(d[2]), "+f"(d[3])
        : "r"(a[0]), "r"(a[1]), "r"(a[2]), "r"(a[3]), "r"(b[0]), "r"(b[1]));
}

__device__ __forceinline__ void cp16(uint32_t dst, const void* src) {
    asm volatile("cp.async.cg.shared.global [%0], [%1], 16;"
                 :: "r"(dst), "l"(src) : "memory");
}

__device__ __forceinline__ uint32_t pk_h2(float a, float b) {
    __half2 t = __floats2half2_rn(a, b);
    return *reinterpret_cast<uint32_t*>(&t);
}

// ---------------------------------------------------------------------------
// HMMA fp16 2-pass GEMM (QKV): C = (Ahi+Alo) @ B^T. Verified R8/R9.
// Block 128x256x32, 256 threads (2Mx4N warps), warp tile 64x64.
// ---------------------------------------------------------------------------
#define ROWB 80
#define GA_T (128 * ROWB)
#define GB_T (256 * ROWB)
#define GSTAGE (2 * GA_T + GB_T)
#define GEMM_SMEM (3 * GSTAGE)

__global__ __launch_bounds__(256) void hmma_gemm2_kernel(
    const __half* __restrict__ Ahi, const __half* __restrict__ Alo,
    const __half* __restrict__ Bw,
    float* __restrict__ C, int M, int N, int K)
{
    extern __shared__ char gsm[];
    const uint32_t base = smem_u32(gsm);

    const int tid = threadIdx.x;
    const int lane = tid & 31;
    const int wid = tid >> 5;
    const int warp_m = wid & 1;
    const int warp_n = wid >> 1;
    const int row0 = blockIdx.y * 128, col0 = blockIdx.x * 256;

    float acc[4][8][4];
#pragma unroll
    for (int i = 0; i < 4; i++)
#pragma unroll
        for (int j = 0; j < 8; j++)
#pragma unroll
            for (int e = 0; e < 4; e++) acc[i][j][e] = 0.f;

    const int nch = K >> 5;

    auto load_stage = [&](int st, int k0) {
        const uint32_t sb = base + st * GSTAGE;
#pragma unroll
        for (int i2 = 0; i2 < 8; i2++) {
            int g = tid + (i2 << 8);
            const __half* src;
            uint32_t dst;
            if (g < 1024) {
                int half = g >> 9;
                int r = (g >> 2) & 127;
                int kq = g & 3;
                const __half* bp = half ? Alo : Ahi;
                src = bp + (size_t)(row0 + r) * K + k0 + (kq << 3);
                dst = sb + half * GA_T + r * ROWB + (kq << 4);
            } else {
                int g2 = g - 1024;
                int r = g2 >> 2;
                int kq = g2 & 3;
                src = Bw + (size_t)(col0 + r) * K + k0 + (kq << 3);
                dst = sb + 2 * GA_T + r * ROWB + (kq << 4);
            }
            cp16(dst, src);
        }
        asm volatile("cp.async.commit_group;" ::: "memory");
    };

    load_stage(0, 0);
    load_stage(1, 32);

    int st = 0;
    for (int c = 0; c < nch; c++) {
        if (c == nch - 1) { asm volatile("cp.async.wait_group 0;" ::: "memory"); }
        else              { asm volatile("cp.async.wait_group 1;" ::: "memory"); }
        __syncthreads();

        if (c + 2 < nch) {
            int pst = st + 2; if (pst >= 3) pst -= 3;
            load_stage(pst, (c + 2) << 5);
        }

        const uint32_t sb = base + st * GSTAGE;
        const uint32_t aH = sb, bT = sb + 2 * GA_T;

#pragma unroll
        for (int ks = 0; ks < 2; ks++) {
            uint32_t ah[4][4], al[4][4], bw[8][2];
            const int arow = warp_m * 64 + (lane & 15);
            const uint32_t akoff = (ks << 5) + ((lane >> 4) << 4);
#pragma unroll
            for (int i = 0; i < 4; i++) {
                uint32_t ad = aH + (uint32_t)(arow + i * 16) * ROWB + akoff;
                ldsm_x4(ah[i], ad);
                ldsm_x4(al[i], ad + GA_T);
            }
            const int quad = lane >> 3, wi = lane & 7;
#pragma unroll
            for (int t = 0; t < 4; t++) {
                int ntile = 2 * t + (quad >> 1);
                int brow = warp_n * 64 + ntile * 8 + wi;
                uint32_t bd = bT + (uint32_t)brow * ROWB + (ks << 5) + ((quad & 1) << 4);
                uint32_t r4[4];
                ldsm_x4(r4, bd);
                bw[2 * t][0] = r4[0]; bw[2 * t][1] = r4[1];
                bw[2 * t + 1][0] = r4[2]; bw[2 * t + 1][1] = r4[3];
            }
#pragma unroll
            for (int i = 0; i < 4; i++)
#pragma unroll
                for (int j = 0; j < 8; j++) {
                    mma_f16(acc[i][j], ah[i], bw[j]);
                    mma_f16(acc[i][j], al[i], bw[j]);
                }
        }
        if (++st >= 3) st -= 3;
    }

    const int rb = row0 + warp_m * 64 + (lane >> 2);
    const int cb = col0 + warp_n * 64 + (lane & 3) * 2;
#pragma unroll
    for (int i = 0; i < 4; i++)
#pragma unroll
        for (int j = 0; j < 8; j++) {
            float* p0 = C + (size_t)(rb + i * 16) * N + cb + j * 8;
            float* p1 = C + (size_t)(rb + i * 16 + 8) * N + cb + j * 8;
            *(float2*)p0 = make_float2(acc[i][j][0], acc[i][j][1]);
            *(float2*)p1 = make_float2(acc[i][j][2], acc[i][j][3]);
        }
}

// ---------------------------------------------------------------------------
// HMMA fp16 single-pass GEMM (O-proj): C = A @ B^T, A single fp16.
// Same structure, half the A-smem and half the MMAs.
// ---------------------------------------------------------------------------
#define G1STAGE (GA_T + GB_T)          // 30720
#define GEMM1_SMEM (3 * G1STAGE)       // 92160

__global__ __launch_bounds__(256) void hmma_gemm1_kernel(
    const __half* __restrict__ A, const __half* __restrict__ Bw,
    float* __restrict__ C, int M, int N, int K)
{
    extern __shared__ char gsm[];
    const uint32_t base = smem_u32(gsm);

    const int tid = threadIdx.x;
    const int lane = tid & 31;
    const int wid = tid >> 5;
    const int warp_m = wid & 1;
    const int warp_n = wid >> 1;
    const int row0 = blockIdx.y * 128, col0 = blockIdx.x * 256;

    float acc[4][8][4];
#pragma unroll
    for (int i = 0; i < 4; i++)
#pragma unroll
        for (int j = 0; j < 8; j++)
#pragma unroll
            for (int e = 0; e < 4; e++) acc[i][j][e] = 0.f;

    const int nch = K >> 5;

    // stage: A(512 x 16B) + B(1024 x 16B) = 1536 groups
    auto load_stage = [&](int st, int k0) {
        const uint32_t sb = base + st * G1STAGE;
#pragma unroll
        for (int i2 = 0; i2 < 6; i2++) {
            int g = tid + (i2 << 8);               // 0..1535
            const __half* src;
            uint32_t dst;
            if (g < 512) {
                int r = g >> 2;
                int kq = g & 3;
                src = A + (size_t)(row0 + r) * K + k0 + (kq << 3);
                dst = sb + r * ROWB + (kq << 4);
            } else {
                int g2 = g - 512;
                int r = g2 >> 2;
                int kq = g2 & 3;
                src = Bw + (size_t)(col0 + r) * K + k0 + (kq << 3);
                dst = sb + GA_T + r * ROWB + (kq << 4);
            }
            cp16(dst, src);
        }
        asm volatile("cp.async.commit_group;" ::: "memory");
    };

    load_stage(0, 0);
    load_stage(1, 32);

    int st = 0;
    for (int c = 0; c < nch; c++) {
        if (c == nch - 1) { asm volatile("cp.async.wait_group 0;" ::: "memory"); }
        else              { asm volatile("cp.async.wait_group 1;" ::: "memory"); }
        __syncthreads();

        if (c + 2 < nch) {
            int pst = st + 2; if (pst >= 3) pst -= 3;
            load_stage(pst, (c + 2) << 5);
        }

        const uint32_t sb = base + st * G1STAGE;
        const uint32_t aH = sb, bT = sb + GA_T;

#pragma unroll
        for (int ks = 0; ks < 2; ks++) {
            uint32_t ah[4][4], bw[8][2];
            const int arow = warp_m * 64 + (lane & 15);
            const uint32_t akoff = (ks << 5) + ((lane >> 4) << 4);
#pragma unroll
            for (int i = 0; i < 4; i++)
                ldsm_x4(ah[i], aH + (uint32_t)(arow + i * 16) * ROWB + akoff);
            const int quad = lane >> 3, wi = lane & 7;
#pragma unroll
            for (int t = 0; t < 4; t++) {
                int ntile = 2 * t + (quad >> 1);
                int brow = warp_n * 64 + ntile * 8 + wi;
                uint32_t bd = bT + (uint32_t)brow * ROWB + (ks << 5) + ((quad & 1) << 4);
                uint32_t r4[4];
                ldsm_x4(r4, bd);
                bw[2 * t][0] = r4[0]; bw[2 * t][1] = r4[1];
                bw[2 * t + 1][0] = r4[2]; bw[2 * t + 1][1] = r4[3];
            }
#pragma unroll
            for (int i = 0; i < 4; i++)
#pragma unroll
                for (int j = 0; j < 8; j++)
                    mma_f16(acc[i][j], ah[i], bw[j]);
        }
        if (++st >= 3) st -= 3;
    }

    const int rb = row0 + warp_m * 64 + (lane >> 2);
    const int cb = col0 + warp_n * 64 + (lane & 3) * 2;
#pragma unroll
    for (int i = 0; i < 4; i++)
#pragma unroll
        for (int j = 0; j < 8; j++) {
            float* p0 = C + (size_t)(rb + i * 16) * N + cb + j * 8;
            float* p1 = C + (size_t)(rb + i * 16 + 8) * N + cb + j * 8;
            *(float2*)p0 = make_float2(acc[i][j][0], acc[i][j][1]);
            *(float2*)p1 = make_float2(acc[i][j][2], acc[i][j][3]);
        }
}

// ---------------------------------------------------------------------------
// fp32 -> split fp16 (hi/lo)
// ---------------------------------------------------------------------------
__global__ void split2h_kernel(const float* __restrict__ x,
                               __half* __restrict__ hi,
                               __half* __restrict__ lo, int n4)
{
    int i = blockIdx.x * blockDim.x + threadIdx.x;
    if (i >= n4) return;
    float4 v = ((const float4*)x)[i];
    float vv[4] = {v.x, v.y, v.z, v.w};
    __half hv[4], lv[4];
#pragma unroll
    for (int j = 0; j < 4; j++) {
        hv[j] = __float2half_rn(vv[j]);
        lv[j] = __float2half_rn(vv[j] - __half2float(hv[j]));
    }
    *(uint2*)&hi[(size_t)i * 4] = *(uint2*)hv;
    *(uint2*)&lo[(size_t)i * 4] = *(uint2*)lv;
}

// ---------------------------------------------------------------------------
// fp32 [R][Cn] -> transposed fp16 [Cn][R]. 32x32 tiles.
// ---------------------------------------------------------------------------
__global__ void tconvh_kernel(const float* __restrict__ x,
                              __half* __restrict__ w, int R, int Cn)
{
    __shared__ float t[32][33];
    int bc = blockIdx.x * 32, br = blockIdx.y * 32;
    int tx = threadIdx.x, ty = threadIdx.y;
#pragma unroll
    for (int j = 0; j < 32; j += 8)
        t[ty + j][tx] = x[(size_t)(br + ty + j) * Cn + bc + tx];
    __syncthreads();
#pragma unroll
    for (int j = 0; j < 32; j += 8) {
        int orow = bc + ty + j;
        int ocol = br + tx;
        w[(size_t)orow * R + ocol] = __float2half_rn(t[tx][ty + j]);
    }
}

// ---------------------------------------------------------------------------
// Fused RoPE + convert: Q (pre-scaled 1/16), K, V -> single fp16
// ---------------------------------------------------------------------------
__global__ void rope_split_kernel(
    const float* __restrict__ qkv, const int* __restrict__ positions,
    __half* __restrict__ qq, __half* __restrict__ kk, __half* __restrict__ vv)
{
    const int total = MROWS * 11 * 128;
    int idx = blockIdx.x * blockDim.x + threadIdx.x;
    if (idx >= total) return;
    int j = idx & 127;
    int t = idx >> 7;
    int unit = t % 11;
    int row = t / 11;
    int s = row & (SS - 1);
    int b = row >> 11;

    if (unit < 9) {
        float pos = (float)positions[s];
        const float LOG_THETA = 9.210340371976184f;
        float e = (float)j * (1.0f / 128.0f);
        float invf = expf(-LOG_THETA * e);
        float ang = pos * invf;
        float sn, cs;
        sincosf(ang, &sn, &cs);

        int inoff = row * QKVW + (unit < 8 ? unit * 256 : 2048);
        float x1 = qkv[inoff + j];
        float x2 = qkv[inoff + 128 + j];
        float y1 = x1 * cs - x2 * sn;
        float y2 = x2 * cs + x1 * sn;

        if (unit < 8) {
            y1 *= 0.0625f;
            y2 *= 0.0625f;
            size_t ooff = ((size_t)(b * NHH + unit) * SS + s) * DD;
            qq[ooff + j] = __float2half_rn(y1);
            qq[ooff + 128 + j] = __float2half_rn(y2);
        } else {
            size_t ooff = (size_t)row * DD;
            kk[ooff + j] = __float2half_rn(y1);
            kk[ooff + 128 + j] = __float2half_rn(y2);
        }
    } else {
        int jj = (unit - 9) * 128 + j;
        float v = qkv[row * QKVW + 2304 + jj];
        vv[(size_t)row * DD + jj] = __float2half_rn(v);
    }
}

// ---------------------------------------------------------------------------
// HMMA flash attention fp16 single-pass: Br=128, Bc=32, 256 threads (8 warps).
// S = Q·K^T, O = P·V, everything single fp16 (fp32 accumulate).
// ---------------------------------------------------------------------------
#define KSTR 528
#define PSTR 80
#define FQ 0
#define FK (FQ + 128 * KSTR)           // 67584
#define FV (FK + 32 * KSTR)            // 84480
#define FP (FV + 32 * KSTR)            // 101376
#define FLASH_SMEM (FP + 128 * PSTR)   // 111616

__global__ __launch_bounds__(256) void flash_hmma_kernel(
    const __half* __restrict__ Qp, const __half* __restrict__ Kp,
    const __half* __restrict__ Vp, __half* __restrict__ Op)
{
    extern __shared__ char fsm[];
    const uint32_t base = smem_u32(fsm);
    const int qt = (gridDim.x - 1) - blockIdx.x;
    const int h = blockIdx.y, b = blockIdx.z;
    const int tid = threadIdx.x, lane = tid & 31, w = tid >> 5;
    const int q0 = qt * 128;
    const int nj = (q0 + 128) >> 5;

    const __half* qp = Qp + ((size_t)(b * NHH + h) * SS + q0) * DD;
    const __half* kp = Kp + (size_t)b * SS * DD;
    const __half* vp = Vp + (size_t)b * SS * DD;

    // Q load: one group
    {
#pragma unroll
        for (int i = 0; i < 16; i++) {
            int g = tid + (i << 8);
            int r = g >> 5, cq = g & 31;
            cp16(base + FQ + r * KSTR + (cq << 4),
                 qp + (size_t)r * DD + (cq << 3));
        }
        asm volatile("cp.async.commit_group;" ::: "memory");
    }

    auto ldkv = [&](uint32_t off, const __half* p, int c0) {
#pragma unroll
        for (int i = 0; i < 4; i++) {
            int g = tid + (i << 8);
            int r = g >> 5, cq = g & 31;
            cp16(base + off + r * KSTR + (cq << 4),
                 p + (size_t)(c0 + r) * DD + (cq << 3));
        }
        asm volatile("cp.async.commit_group;" ::: "memory");
    };

    ldkv(FK, kp, 0);
    ldkv(FV, vp, 0);

    float acc[32][4];
#pragma unroll
    for (int t = 0; t < 32; t++)
#pragma unroll
        for (int e = 0; e < 4; e++) acc[t][e] = 0.f;
    float m0 = -1e30f, m1 = -1e30f, l0 = 0.f, l1 = 0.f;

    const uint32_t aQbase = base + FQ + (w * 16 + (lane & 15)) * KSTR + ((lane >> 4) << 4);
    const int quad = lane >> 3, wi = lane & 7;
    const uint32_t bKbase = base + FK + ((quad >> 1) * 8 + wi) * KSTR + ((quad & 1) << 4);
    const uint32_t aPbase = base + FP + (w * 16 + (lane & 15)) * PSTR + ((lane >> 4) << 4);
    const uint32_t bVbase = base + FV + ((lane & 7) + ((lane >> 3) & 1) * 8) * KSTR
                          + (lane >> 4) * 16;
    const uint32_t pstore = base + FP + (w * 16 + (lane >> 2)) * PSTR + (lane & 3) * 4;

    for (int jt = 0; jt < nj; jt++) {
        const int c0 = jt * 32;
        asm volatile("cp.async.wait_group 1;" ::: "memory");
        __syncthreads();

        // ---------------- S = Q K^T ----------------
        float sacc[4][4];
#pragma unroll
        for (int t = 0; t < 4; t++)
#pragma unroll
            for (int e = 0; e < 4; e++) sacc[t][e] = 0.f;

#pragma unroll
        for (int ks = 0; ks < 16; ks++) {
            uint32_t ah[4];
            ldsm_x4(ah, aQbase + ks * 32);
#pragma unroll
            for (int np = 0; np < 2; np++) {
                uint32_t bh4[4];
                ldsm_x4(bh4, bKbase + np * 16 * KSTR + ks * 32);
                mma_f16(sacc[2 * np],     ah, bh4);
                mma_f16(sacc[2 * np + 1], ah, bh4 + 2);
            }
        }
        __syncthreads();
        if (jt + 1 < nj) ldkv(FK, kp, c0 + 32);

        // ---------------- softmax ----------------
        const int colb = c0 + (lane & 3) * 2;
        const int row0g = q0 + w * 16 + (lane >> 2);
        const int row1g = row0g + 8;
        if (c0 + 31 > q0) {
#pragma unroll
            for (int t = 0; t < 4; t++) {
                int cg = colb + t * 8;
#pragma unroll
                for (int e = 0; e < 4; e++) {
                    int c = cg + (e & 1);
                    int rg = (e < 2) ? row0g : row1g;
                    if (c > rg) sacc[t][e] = -1e30f;
                }
            }
        }
        float mx0 = -1e30f, mx1 = -1e30f;
#pragma unroll
        for (int t = 0; t < 4; t++) {
            mx0 = fmaxf(mx0, fmaxf(sacc[t][0], sacc[t][1]));
            mx1 = fmaxf(mx1, fmaxf(sacc[t][2], sacc[t][3]));
        }
        mx0 = fmaxf(mx0, __shfl_xor_sync(0xffffffffu, mx0, 1));
        mx0 = fmaxf(mx0, __shfl_xor_sync(0xffffffffu, mx0, 2));
        mx1 = fmaxf(mx1, __shfl_xor_sync(0xffffffffu, mx1, 1));
        mx1 = fmaxf(mx1, __shfl_xor_sync(0xffffffffu, mx1, 2));

        float mn0 = fmaxf(m0, mx0), mn1 = fmaxf(m1, mx1);
        float a0 = __expf(m0 - mn0), a1 = __expf(m1 - mn1);
        m0 = mn0; m1 = mn1;
        float s0 = 0.f, s1 = 0.f;
#pragma unroll
        for (int t = 0; t < 4; t++) {
            float p0 = __expf(sacc[t][0] - mn0);
            float p1 = __expf(sacc[t][1] - mn0);
            float p2 = __expf(sacc[t][2] - mn1);
            float p3 = __expf(sacc[t][3] - mn1);
            s0 += p0 + p1; s1 += p2 + p3;
            uint32_t h01 = pk_h2(p0, p1);
            uint32_t h23 = pk_h2(p2, p3);
            asm volatile("st.shared.b32 [%0], %1;" :: "r"(pstore + t * 16), "r"(h01) : "memory");
            asm volatile("st.shared.b32 [%0], %1;" :: "r"(pstore + 8 * PSTR + t * 16), "r"(h23) : "memory");
        }
        s0 += __shfl_xor_sync(0xffffffffu, s0, 1);
        s0 += __shfl_xor_sync(0xffffffffu, s0, 2);
        s1 += __shfl_xor_sync(0xffffffffu, s1, 1);
        s1 += __shfl_xor_sync(0xffffffffu, s1, 2);
        l0 = l0 * a0 + s0;
        l1 = l1 * a1 + s1;
        bool noresc = __all_sync(0xffffffffu, (a0 == 1.0f) && (a1 == 1.0f));
        if (!noresc) {
#pragma unroll
            for (int t = 0; t < 32; t++) {
                acc[t][0] *= a0; acc[t][1] *= a0;
                acc[t][2] *= a1; acc[t][3] *= a1;
            }
        }

        if (jt + 1 < nj) { asm volatile("cp.async.wait_group 1;" ::: "memory"); }
        else             { asm volatile("cp.async.wait_group 0;" ::: "memory"); }
        __syncthreads();

        // ---------------- O += P V ----------------
#pragma unroll
        for (int ks = 0; ks < 2; ks++) {
            uint32_t ph4[4];
            ldsm_x4(ph4, aPbase + ks * 32);
#pragma unroll
            for (int np = 0; np < 16; np++) {
                uint32_t vh4[4];
                ldsm_x4_t(vh4, bVbase + ks * 16 * KSTR + np * 32);
                mma_f16(acc[2 * np],     ph4, vh4);
                mma_f16(acc[2 * np + 1], ph4, vh4 + 2);
            }
        }
        __syncthreads();
        if (jt + 1 < nj) ldkv(FV, vp, c0 + 32);
    }

    // epilogue: write O single fp16
    float inv0 = 1.0f / l0, inv1 = 1.0f / l1;
    size_t ob0 = ((size_t)(b * SS) + q0 + w * 16 + (lane >> 2)) * HH + h * DD + (lane & 3) * 2;
    size_t ob1 = ob0 + 8 * (size_t)HH;
#pragma unroll
    for (int t = 0; t < 32; t++) {
        uint32_t h01 = pk_h2(acc[t][0] * inv0, acc[t][1] * inv0);
        uint32_t h23 = pk_h2(acc[t][2] * inv1, acc[t][3] * inv1);
        *(uint32_t*)&Op[ob0 + t * 8] = h01;
        *(uint32_t*)&Op[ob1 + t * 8] = h23;
    }
}

// ---------------------------------------------------------------------------
extern "C" void kernel_launch(void* const* d_in, const int* in_sizes, int n_in,
                              void* d_out, int out_size)
{
    const float* hidden    = (const float*)d_in[0];
    const int*   positions = (const int*)d_in[1];
    const float* w_qkv     = (const float*)d_in[2];
    const float* w_o       = (const float*)d_in[3];
    float* out = (float*)d_out;

    float* qkv_ptr;
    __half *hid_hi, *hid_lo, *wqkv_p, *wo_p, *atn_p;
    __half *q_p, *k_p, *v_p;
    cudaGetSymbolAddress((void**)&qkv_ptr, g_qkv);
    cudaGetSymbolAddress((void**)&hid_hi, g_hid_hi);
    cudaGetSymbolAddress((void**)&hid_lo, g_hid_lo);
    cudaGetSymbolAddress((void**)&wqkv_p, g_wqkv);
    cudaGetSymbolAddress((void**)&wo_p, g_wo);
    cudaGetSymbolAddress((void**)&atn_p, g_atn);
    cudaGetSymbolAddress((void**)&q_p, g_q);
    cudaGetSymbolAddress((void**)&k_p, g_k);
    cudaGetSymbolAddress((void**)&v_p, g_v);

    cudaFuncSetAttribute(hmma_gemm2_kernel,
                         cudaFuncAttributeMaxDynamicSharedMemorySize, GEMM_SMEM);
    cudaFuncSetAttribute(hmma_gemm1_kernel,
                         cudaFuncAttributeMaxDynamicSharedMemorySize, GEMM1_SMEM);
    cudaFuncSetAttribute(flash_hmma_kernel,
                         cudaFuncAttributeMaxDynamicSharedMemorySize, FLASH_SMEM);

    // 1) split hidden -> fp16 hi/lo
    {
        int n4 = MROWS * HH / 4;
        split2h_kernel<<<(n4 + 255) / 256, 256>>>(hidden, hid_hi, hid_lo, n4);
    }
    // 2) transpose+convert w_qkv -> fp16 [N][K]
    tconvh_kernel<<<dim3(QKVW / 32, HH / 32), dim3(32, 8)>>>(w_qkv, wqkv_p, HH, QKVW);

    // 3) QKV projection (fp16 2-pass)
    hmma_gemm2_kernel<<<dim3(QKVW / 256, MROWS / 128), 256, GEMM_SMEM>>>(
        hid_hi, hid_lo, wqkv_p, qkv_ptr, MROWS, QKVW, HH);

    // 4) fused RoPE + convert: Q (pre-scaled), K, V single fp16
    {
        int total = MROWS * 11 * 128;
        rope_split_kernel<<<(total + 255) / 256, 256>>>(
            qkv_ptr, positions, q_p, k_p, v_p);
    }

    // 5) HMMA flash attention (fp16 single-pass) -> O fp16
    {
        dim3 grid2(SS / 128, NHH, BB);
        flash_hmma_kernel<<<grid2, 256, FLASH_SMEM>>>(q_p, k_p, v_p, atn_p);
    }

    // 6) transpose+convert w_o -> fp16 [N][K]
    tconvh_kernel<<<dim3(HH / 32, HH / 32), dim3(32, 8)>>>(w_o, wo_p, HH, HH);

    // 7) Output projection (fp16 single-pass)
    hmma_gemm1_kernel<<<dim3(HH / 256, MROWS / 128), 256, GEMM1_SMEM>>>(
        atn_p, wo_p, out, MROWS, HH, HH);
}

// round 11
// speedup vs baseline: 2.1037x; 1.1737x over previous
#include <cuda_runtime.h>
#include <cuda_fp16.h>
#include <math.h>
#include <stdint.h>

#define BB 4
#define SS 2048
#define HH 2048
#define NHH 8
#define DD 256
#define QKVW 2560            // (8 + 2*1) * 256
#define MROWS (BB * SS)      // 8192

// ---------------------------------------------------------------------------
// Scratch (allocation-free rule: device globals)
// ---------------------------------------------------------------------------
__device__ float g_qkv[MROWS * QKVW];                         // ~84 MB fp32
__device__ __align__(16) __half g_hid[MROWS * HH];            // hidden, single fp16
__device__ __align__(16) __half g_wqkv[QKVW * HH];            // transposed [N][K] fp16
__device__ __align__(16) __half g_wo[HH * HH];                // transposed [N][K] fp16
__device__ __align__(16) __half g_atn[MROWS * HH];            // attention out, fp16
__device__ __align__(16) __half g_q[(size_t)BB * NHH * SS * DD];
__device__ __align__(16) __half g_k[(size_t)BB * SS * DD];
__device__ __align__(16) __half g_v[(size_t)BB * SS * DD];

// ---------------------------------------------------------------------------
// helpers
// ---------------------------------------------------------------------------
__device__ __forceinline__ uint32_t smem_u32(const void* p) {
    uint32_t a;
    asm("{ .reg .u64 t; cvta.to.shared.u64 t, %1; cvt.u32.u64 %0, t; }"
        : "=r"(a) : "l"(p));
    return a;
}

__device__ __forceinline__ void ldsm_x4(uint32_t (&r)[4], uint32_t addr) {
    asm volatile("ldmatrix.sync.aligned.m8n8.x4.shared.b16 {%0,%1,%2,%3}, [%4];"
                 : "=r"(r[0]), "=r"(r[1]), "=r"(r[2]), "=r"(r[3]) : "r"(addr));
}

__device__ __forceinline__ void ldsm_x4_t(uint32_t (&r)[4], uint32_t addr) {
    asm volatile("ldmatrix.sync.aligned.m8n8.x4.trans.shared.b16 {%0,%1,%2,%3}, [%4];"
                 : "=r"(r[0]), "=r"(r[1]), "=r"(r[2]), "=r"(r[3]) : "r"(addr));
}

__device__ __forceinline__ void mma_f16(float (&d)[4], const uint32_t (&a)[4],
                                        const uint32_t* b) {
    asm volatile(
        "mma.sync.aligned.m16n8k16.row.col.f32.f16.f16.f32 "
        "{%0,%1,%2,%3}, {%4,%5,%6,%7}, {%8,%9}, {%0,%1,%2,%3};"
        : "+f"(d[0]), "+f"(d[1]), "+f"(d[2]), "+f"(d[3])
        : "r"(a[0]), "r"(a[1]), "r"(a[2]), "r"(a[3]), "r"(b[0]), "r"(b[1]));
}

__device__ __forceinline__ void cp16(uint32_t dst, const void* src) {
    asm volatile("cp.async.cg.shared.global [%0], [%1], 16;"
                 :: "r"(dst), "l"(src) : "memory");
}

__device__ __forceinline__ uint32_t pk_h2(float a, float b) {
    __half2 t = __floats2half2_rn(a, b);
    return *reinterpret_cast<uint32_t*>(&t);
}

// ---------------------------------------------------------------------------
// HMMA fp16 single-pass GEMM: C[M,N] fp32 = A[M,K] @ B[N,K]^T
// Block 128x256x32, 256 threads (2Mx4N warps), warp tile 64x64.
// 3-stage cp.async, distance-2 prefetch, 1 barrier/chunk. (structure verified)
// ---------------------------------------------------------------------------
#define ROWB 80
#define GA_T (128 * ROWB)              // 10240
#define GB_T (256 * ROWB)              // 20480
#define G1STAGE (GA_T + GB_T)          // 30720
#define GEMM1_SMEM (3 * G1STAGE)       // 92160

__global__ __launch_bounds__(256) void hmma_gemm1_kernel(
    const __half* __restrict__ A, const __half* __restrict__ Bw,
    float* __restrict__ C, int M, int N, int K)
{
    extern __shared__ char gsm[];
    const uint32_t base = smem_u32(gsm);

    const int tid = threadIdx.x;
    const int lane = tid & 31;
    const int wid = tid >> 5;
    const int warp_m = wid & 1;
    const int warp_n = wid >> 1;
    const int row0 = blockIdx.y * 128, col0 = blockIdx.x * 256;

    float acc[4][8][4];
#pragma unroll
    for (int i = 0; i < 4; i++)
#pragma unroll
        for (int j = 0; j < 8; j++)
#pragma unroll
            for (int e = 0; e < 4; e++) acc[i][j][e] = 0.f;

    const int nch = K >> 5;

    auto load_stage = [&](int st, int k0) {
        const uint32_t sb = base + st * G1STAGE;
#pragma unroll
        for (int i2 = 0; i2 < 6; i2++) {
            int g = tid + (i2 << 8);               // 0..1535
            const __half* src;
            uint32_t dst;
            if (g < 512) {
                int r = g >> 2;
                int kq = g & 3;
                src = A + (size_t)(row0 + r) * K + k0 + (kq << 3);
                dst = sb + r * ROWB + (kq << 4);
            } else {
                int g2 = g - 512;
                int r = g2 >> 2;
                int kq = g2 & 3;
                src = Bw + (size_t)(col0 + r) * K + k0 + (kq << 3);
                dst = sb + GA_T + r * ROWB + (kq << 4);
            }
            cp16(dst, src);
        }
        asm volatile("cp.async.commit_group;" ::: "memory");
    };

    load_stage(0, 0);
    load_stage(1, 32);

    int st = 0;
    for (int c = 0; c < nch; c++) {
        if (c == nch - 1) { asm volatile("cp.async.wait_group 0;" ::: "memory"); }
        else              { asm volatile("cp.async.wait_group 1;" ::: "memory"); }
        __syncthreads();

        if (c + 2 < nch) {
            int pst = st + 2; if (pst >= 3) pst -= 3;
            load_stage(pst, (c + 2) << 5);
        }

        const uint32_t sb = base + st * G1STAGE;
        const uint32_t aH = sb, bT = sb + GA_T;

#pragma unroll
        for (int ks = 0; ks < 2; ks++) {
            uint32_t ah[4][4], bw[8][2];
            const int arow = warp_m * 64 + (lane & 15);
            const uint32_t akoff = (ks << 5) + ((lane >> 4) << 4);
#pragma unroll
            for (int i = 0; i < 4; i++)
                ldsm_x4(ah[i], aH + (uint32_t)(arow + i * 16) * ROWB + akoff);
            const int quad = lane >> 3, wi = lane & 7;
#pragma unroll
            for (int t = 0; t < 4; t++) {
                int ntile = 2 * t + (quad >> 1);
                int brow = warp_n * 64 + ntile * 8 + wi;
                uint32_t bd = bT + (uint32_t)brow * ROWB + (ks << 5) + ((quad & 1) << 4);
                uint32_t r4[4];
                ldsm_x4(r4, bd);
                bw[2 * t][0] = r4[0]; bw[2 * t][1] = r4[1];
                bw[2 * t + 1][0] = r4[2]; bw[2 * t + 1][1] = r4[3];
            }
#pragma unroll
            for (int i = 0; i < 4; i++)
#pragma unroll
                for (int j = 0; j < 8; j++)
                    mma_f16(acc[i][j], ah[i], bw[j]);
        }
        if (++st >= 3) st -= 3;
    }

    const int rb = row0 + warp_m * 64 + (lane >> 2);
    const int cb = col0 + warp_n * 64 + (lane & 3) * 2;
#pragma unroll
    for (int i = 0; i < 4; i++)
#pragma unroll
        for (int j = 0; j < 8; j++) {
            float* p0 = C + (size_t)(rb + i * 16) * N + cb + j * 8;
            float* p1 = C + (size_t)(rb + i * 16 + 8) * N + cb + j * 8;
            *(float2*)p0 = make_float2(acc[i][j][0], acc[i][j][1]);
            *(float2*)p1 = make_float2(acc[i][j][2], acc[i][j][3]);
        }
}

// ---------------------------------------------------------------------------
// fp32 -> fp16 convert (straight copy layout)
// ---------------------------------------------------------------------------
__global__ void convh_kernel(const float* __restrict__ x,
                             __half* __restrict__ y, int n4)
{
    int i = blockIdx.x * blockDim.x + threadIdx.x;
    if (i >= n4) return;
    float4 v = ((const float4*)x)[i];
    __half hv[4];
    hv[0] = __float2half_rn(v.x);
    hv[1] = __float2half_rn(v.y);
    hv[2] = __float2half_rn(v.z);
    hv[3] = __float2half_rn(v.w);
    *(uint2*)&y[(size_t)i * 4] = *(uint2*)hv;
}

// ---------------------------------------------------------------------------
// fp32 [R][Cn] -> transposed fp16 [Cn][R]. 32x32 tiles.
// ---------------------------------------------------------------------------
__global__ void tconvh_kernel(const float* __restrict__ x,
                              __half* __restrict__ w, int R, int Cn)
{
    __shared__ float t[32][33];
    int bc = blockIdx.x * 32, br = blockIdx.y * 32;
    int tx = threadIdx.x, ty = threadIdx.y;
#pragma unroll
    for (int j = 0; j < 32; j += 8)
        t[ty + j][tx] = x[(size_t)(br + ty + j) * Cn + bc + tx];
    __syncthreads();
#pragma unroll
    for (int j = 0; j < 32; j += 8) {
        int orow = bc + ty + j;
        int ocol = br + tx;
        w[(size_t)orow * R + ocol] = __float2half_rn(t[tx][ty + j]);
    }
}

// ---------------------------------------------------------------------------
// Fused RoPE + convert: Q (pre-scaled 1/16), K, V -> single fp16
// ---------------------------------------------------------------------------
__global__ void rope_split_kernel(
    const float* __restrict__ qkv, const int* __restrict__ positions,
    __half* __restrict__ qq, __half* __restrict__ kk, __half* __restrict__ vv)
{
    const int total = MROWS * 11 * 128;
    int idx = blockIdx.x * blockDim.x + threadIdx.x;
    if (idx >= total) return;
    int j = idx & 127;
    int t = idx >> 7;
    int unit = t % 11;
    int row = t / 11;
    int s = row & (SS - 1);
    int b = row >> 11;

    if (unit < 9) {
        float pos = (float)positions[s];
        const float LOG_THETA = 9.210340371976184f;
        float e = (float)j * (1.0f / 128.0f);
        float invf = expf(-LOG_THETA * e);
        float ang = pos * invf;
        float sn, cs;
        sincosf(ang, &sn, &cs);

        int inoff = row * QKVW + (unit < 8 ? unit * 256 : 2048);
        float x1 = qkv[inoff + j];
        float x2 = qkv[inoff + 128 + j];
        float y1 = x1 * cs - x2 * sn;
        float y2 = x2 * cs + x1 * sn;

        if (unit < 8) {
            y1 *= 0.0625f;
            y2 *= 0.0625f;
            size_t ooff = ((size_t)(b * NHH + unit) * SS + s) * DD;
            qq[ooff + j] = __float2half_rn(y1);
            qq[ooff + 128 + j] = __float2half_rn(y2);
        } else {
            size_t ooff = (size_t)row * DD;
            kk[ooff + j] = __float2half_rn(y1);
            kk[ooff + 128 + j] = __float2half_rn(y2);
        }
    } else {
        int jj = (unit - 9) * 128 + j;
        float v = qkv[row * QKVW + 2304 + jj];
        vv[(size_t)row * DD + jj] = __float2half_rn(v);
    }
}

// ---------------------------------------------------------------------------
// HMMA flash attention fp16 single-pass: Br=128, Bc=32, 256 threads (8 warps).
// (verified R10)
// ---------------------------------------------------------------------------
#define KSTR 528
#define PSTR 80
#define FQ 0
#define FK (FQ + 128 * KSTR)
#define FV (FK + 32 * KSTR)
#define FP (FV + 32 * KSTR)
#define FLASH_SMEM (FP + 128 * PSTR)

__global__ __launch_bounds__(256) void flash_hmma_kernel(
    const __half* __restrict__ Qp, const __half* __restrict__ Kp,
    const __half* __restrict__ Vp, __half* __restrict__ Op)
{
    extern __shared__ char fsm[];
    const uint32_t base = smem_u32(fsm);
    const int qt = (gridDim.x - 1) - blockIdx.x;
    const int h = blockIdx.y, b = blockIdx.z;
    const int tid = threadIdx.x, lane = tid & 31, w = tid >> 5;
    const int q0 = qt * 128;
    const int nj = (q0 + 128) >> 5;

    const __half* qp = Qp + ((size_t)(b * NHH + h) * SS + q0) * DD;
    const __half* kp = Kp + (size_t)b * SS * DD;
    const __half* vp = Vp + (size_t)b * SS * DD;

    {
#pragma unroll
        for (int i = 0; i < 16; i++) {
            int g = tid + (i << 8);
            int r = g >> 5, cq = g & 31;
            cp16(base + FQ + r * KSTR + (cq << 4),
                 qp + (size_t)r * DD + (cq << 3));
        }
        asm volatile("cp.async.commit_group;" ::: "memory");
    }

    auto ldkv = [&](uint32_t off, const __half* p, int c0) {
#pragma unroll
        for (int i = 0; i < 4; i++) {
            int g = tid + (i << 8);
            int r = g >> 5, cq = g & 31;
            cp16(base + off + r * KSTR + (cq << 4),
                 p + (size_t)(c0 + r) * DD + (cq << 3));
        }
        asm volatile("cp.async.commit_group;" ::: "memory");
    };

    ldkv(FK, kp, 0);
    ldkv(FV, vp, 0);

    float acc[32][4];
#pragma unroll
    for (int t = 0; t < 32; t++)
#pragma unroll
        for (int e = 0; e < 4; e++) acc[t][e] = 0.f;
    float m0 = -1e30f, m1 = -1e30f, l0 = 0.f, l1 = 0.f;

    const uint32_t aQbase = base + FQ + (w * 16 + (lane & 15)) * KSTR + ((lane >> 4) << 4);
    const int quad = lane >> 3, wi = lane & 7;
    const uint32_t bKbase = base + FK + ((quad >> 1) * 8 + wi) * KSTR + ((quad & 1) << 4);
    const uint32_t aPbase = base + FP + (w * 16 + (lane & 15)) * PSTR + ((lane >> 4) << 4);
    const uint32_t bVbase = base + FV + ((lane & 7) + ((lane >> 3) & 1) * 8) * KSTR
                          + (lane >> 4) * 16;
    const uint32_t pstore = base + FP + (w * 16 + (lane >> 2)) * PSTR + (lane & 3) * 4;

    for (int jt = 0; jt < nj; jt++) {
        const int c0 = jt * 32;
        asm volatile("cp.async.wait_group 1;" ::: "memory");
        __syncthreads();

        // ---------------- S = Q K^T ----------------
        float sacc[4][4];
#pragma unroll
        for (int t = 0; t < 4; t++)
#pragma unroll
            for (int e = 0; e < 4; e++) sacc[t][e] = 0.f;

#pragma unroll
        for (int ks = 0; ks < 16; ks++) {
            uint32_t ah[4];
            ldsm_x4(ah, aQbase + ks * 32);
#pragma unroll
            for (int np = 0; np < 2; np++) {
                uint32_t bh4[4];
                ldsm_x4(bh4, bKbase + np * 16 * KSTR + ks * 32);
                mma_f16(sacc[2 * np],     ah, bh4);
                mma_f16(sacc[2 * np + 1], ah, bh4 + 2);
            }
        }
        __syncthreads();
        if (jt + 1 < nj) ldkv(FK, kp, c0 + 32);

        // ---------------- softmax ----------------
        const int colb = c0 + (lane & 3) * 2;
        const int row0g = q0 + w * 16 + (lane >> 2);
        const int row1g = row0g + 8;
        if (c0 + 31 > q0) {
#pragma unroll
            for (int t = 0; t < 4; t++) {
                int cg = colb + t * 8;
#pragma unroll
                for (int e = 0; e < 4; e++) {
                    int c = cg + (e & 1);
                    int rg = (e < 2) ? row0g : row1g;
                    if (c > rg) sacc[t][e] = -1e30f;
                }
            }
        }
        float mx0 = -1e30f, mx1 = -1e30f;
#pragma unroll
        for (int t = 0; t < 4; t++) {
            mx0 = fmaxf(mx0, fmaxf(sacc[t][0], sacc[t][1]));
            mx1 = fmaxf(mx1, fmaxf(sacc[t][2], sacc[t][3]));
        }
        mx0 = fmaxf(mx0, __shfl_xor_sync(0xffffffffu, mx0, 1));
        mx0 = fmaxf(mx0, __shfl_xor_sync(0xffffffffu, mx0, 2));
        mx1 = fmaxf(mx1, __shfl_xor_sync(0xffffffffu, mx1, 1));
        mx1 = fmaxf(mx1, __shfl_xor_sync(0xffffffffu, mx1, 2));

        float mn0 = fmaxf(m0, mx0), mn1 = fmaxf(m1, mx1);
        float a0 = __expf(m0 - mn0), a1 = __expf(m1 - mn1);
        m0 = mn0; m1 = mn1;
        float s0 = 0.f, s1 = 0.f;
#pragma unroll
        for (int t = 0; t < 4; t++) {
            float p0 = __expf(sacc[t][0] - mn0);
            float p1 = __expf(sacc[t][1] - mn0);
            float p2 = __expf(sacc[t][2] - mn1);
            float p3 = __expf(sacc[t][3] - mn1);
            s0 += p0 + p1; s1 += p2 + p3;
            uint32_t h01 = pk_h2(p0, p1);
            uint32_t h23 = pk_h2(p2, p3);
            asm volatile("st.shared.b32 [%0], %1;" :: "r"(pstore + t * 16), "r"(h01) : "memory");
            asm volatile("st.shared.b32 [%0], %1;" :: "r"(pstore + 8 * PSTR + t * 16), "r"(h23) : "memory");
        }
        s0 += __shfl_xor_sync(0xffffffffu, s0, 1);
        s0 += __shfl_xor_sync(0xffffffffu, s0, 2);
        s1 += __shfl_xor_sync(0xffffffffu, s1, 1);
        s1 += __shfl_xor_sync(0xffffffffu, s1, 2);
        l0 = l0 * a0 + s0;
        l1 = l1 * a1 + s1;
        bool noresc = __all_sync(0xffffffffu, (a0 == 1.0f) && (a1 == 1.0f));
        if (!noresc) {
#pragma unroll
            for (int t = 0; t < 32; t++) {
                acc[t][0] *= a0; acc[t][1] *= a0;
                acc[t][2] *= a1; acc[t][3] *= a1;
            }
        }

        if (jt + 1 < nj) { asm volatile("cp.async.wait_group 1;" ::: "memory"); }
        else             { asm volatile("cp.async.wait_group 0;" ::: "memory"); }
        __syncthreads();

        // ---------------- O += P V ----------------
#pragma unroll
        for (int ks = 0; ks < 2; ks++) {
            uint32_t ph4[4];
            ldsm_x4(ph4, aPbase + ks * 32);
#pragma unroll
            for (int np = 0; np < 16; np++) {
                uint32_t vh4[4];
                ldsm_x4_t(vh4, bVbase + ks * 16 * KSTR + np * 32);
                mma_f16(acc[2 * np],     ph4, vh4);
                mma_f16(acc[2 * np + 1], ph4, vh4 + 2);
            }
        }
        __syncthreads();
        if (jt + 1 < nj) ldkv(FV, vp, c0 + 32);
    }

    float inv0 = 1.0f / l0, inv1 = 1.0f / l1;
    size_t ob0 = ((size_t)(b * SS) + q0 + w * 16 + (lane >> 2)) * HH + h * DD + (lane & 3) * 2;
    size_t ob1 = ob0 + 8 * (size_t)HH;
#pragma unroll
    for (int t = 0; t < 32; t++) {
        uint32_t h01 = pk_h2(acc[t][0] * inv0, acc[t][1] * inv0);
        uint32_t h23 = pk_h2(acc[t][2] * inv1, acc[t][3] * inv1);
        *(uint32_t*)&Op[ob0 + t * 8] = h01;
        *(uint32_t*)&Op[ob1 + t * 8] = h23;
    }
}

// ---------------------------------------------------------------------------
extern "C" void kernel_launch(void* const* d_in, const int* in_sizes, int n_in,
                              void* d_out, int out_size)
{
    const float* hidden    = (const float*)d_in[0];
    const int*   positions = (const int*)d_in[1];
    const float* w_qkv     = (const float*)d_in[2];
    const float* w_o       = (const float*)d_in[3];
    float* out = (float*)d_out;

    float* qkv_ptr;
    __half *hid_p, *wqkv_p, *wo_p, *atn_p;
    __half *q_p, *k_p, *v_p;
    cudaGetSymbolAddress((void**)&qkv_ptr, g_qkv);
    cudaGetSymbolAddress((void**)&hid_p, g_hid);
    cudaGetSymbolAddress((void**)&wqkv_p, g_wqkv);
    cudaGetSymbolAddress((void**)&wo_p, g_wo);
    cudaGetSymbolAddress((void**)&atn_p, g_atn);
    cudaGetSymbolAddress((void**)&q_p, g_q);
    cudaGetSymbolAddress((void**)&k_p, g_k);
    cudaGetSymbolAddress((void**)&v_p, g_v);

    cudaFuncSetAttribute(hmma_gemm1_kernel,
                         cudaFuncAttributeMaxDynamicSharedMemorySize, GEMM1_SMEM);
    cudaFuncSetAttribute(flash_hmma_kernel,
                         cudaFuncAttributeMaxDynamicSharedMemorySize, FLASH_SMEM);

    // 1) convert hidden -> fp16
    {
        int n4 = MROWS * HH / 4;
        convh_kernel<<<(n4 + 255) / 256, 256>>>(hidden, hid_p, n4);
    }
    // 2) transpose+convert w_qkv -> fp16 [N][K]
    tconvh_kernel<<<dim3(QKVW / 32, HH / 32), dim3(32, 8)>>>(w_qkv, wqkv_p, HH, QKVW);

    // 3) QKV projection (fp16 single-pass)
    hmma_gemm1_kernel<<<dim3(QKVW / 256, MROWS / 128), 256, GEMM1_SMEM>>>(
        hid_p, wqkv_p, qkv_ptr, MROWS, QKVW, HH);

    // 4) fused RoPE + convert: Q (pre-scaled), K, V single fp16
    {
        int total = MROWS * 11 * 128;
        rope_split_kernel<<<(total + 255) / 256, 256>>>(
            qkv_ptr, positions, q_p, k_p, v_p);
    }

    // 5) HMMA flash attention (fp16 single-pass) -> O fp16
    {
        dim3 grid2(SS / 128, NHH, BB);
        flash_hmma_kernel<<<grid2, 256, FLASH_SMEM>>>(q_p, k_p, v_p, atn_p);
    }

    // 6) transpose+convert w_o -> fp16 [N][K]
    tconvh_kernel<<<dim3(HH / 32, HH / 32), dim3(32, 8)>>>(w_o, wo_p, HH, HH);

    // 7) Output projection (fp16 single-pass)
    hmma_gemm1_kernel<<<dim3(HH / 256, MROWS / 128), 256, GEMM1_SMEM>>>(
        atn_p, wo_p, out, MROWS, HH, HH);
}

// round 12
// speedup vs baseline: 2.2951x; 1.0910x over previous
#include <cuda_runtime.h>
#include <cuda_fp16.h>
#include <math.h>
#include <stdint.h>

#define BB 4
#define SS 2048
#define HH 2048
#define NHH 8
#define DD 256
#define QKVW 2560            // (8 + 2*1) * 256
#define MROWS (BB * SS)      // 8192

// ---------------------------------------------------------------------------
// Scratch (allocation-free rule: device globals)
// ---------------------------------------------------------------------------
__device__ __align__(16) __half g_qkvh[MROWS * QKVW];         // qkv intermediate fp16
__device__ __align__(16) __half g_hid[MROWS * HH];            // hidden fp16
__device__ __align__(16) __half g_wqkv[QKVW * HH];            // transposed [N][K] fp16
__device__ __align__(16) __half g_wo[HH * HH];                // transposed [N][K] fp16
__device__ __align__(16) __half g_atn[MROWS * HH];            // attention out fp16
__device__ __align__(16) __half g_q[(size_t)BB * NHH * SS * DD];
__device__ __align__(16) __half g_k[(size_t)BB * SS * DD];
__device__ __align__(16) __half g_v[(size_t)BB * SS * DD];

// ---------------------------------------------------------------------------
// helpers
// ---------------------------------------------------------------------------
__device__ __forceinline__ uint32_t smem_u32(const void* p) {
    uint32_t a;
    asm("{ .reg .u64 t; cvta.to.shared.u64 t, %1; cvt.u32.u64 %0, t; }"
        : "=r"(a) : "l"(p));
    return a;
}

__device__ __forceinline__ void ldsm_x4(uint32_t (&r)[4], uint32_t addr) {
    asm volatile("ldmatrix.sync.aligned.m8n8.x4.shared.b16 {%0,%1,%2,%3}, [%4];"
                 : "=r"(r[0]), "=r"(r[1]), "=r"(r[2]), "=r"(r[3]) : "r"(addr));
}

__device__ __forceinline__ void ldsm_x4_t(uint32_t (&r)[4], uint32_t addr) {
    asm volatile("ldmatrix.sync.aligned.m8n8.x4.trans.shared.b16 {%0,%1,%2,%3}, [%4];"
                 : "=r"(r[0]), "=r"(r[1]), "=r"(r[2]), "=r"(r[3]) : "r"(addr));
}

__device__ __forceinline__ void mma_f16(float (&d)[4], const uint32_t (&a)[4],
                                        const uint32_t* b) {
    asm volatile(
        "mma.sync.aligned.m16n8k16.row.col.f32.f16.f16.f32 "
        "{%0,%1,%2,%3}, {%4,%5,%6,%7}, {%8,%9}, {%0,%1,%2,%3};"
        : "+f"(d[0]), "+f"(d[1]), "+f"(d[2]), "+f"(d[3])
        : "r"(a[0]), "r"(a[1]), "r"(a[2]), "r"(a[3]), "r"(b[0]), "r"(b[1]));
}

__device__ __forceinline__ void cp16(uint32_t dst, const void* src) {
    asm volatile("cp.async.cg.shared.global [%0], [%1], 16;"
                 :: "r"(dst), "l"(src) : "memory");
}

__device__ __forceinline__ uint32_t pk_h2(float a, float b) {
    __half2 t = __floats2half2_rn(a, b);
    return *reinterpret_cast<uint32_t*>(&t);
}

// ---------------------------------------------------------------------------
// HMMA fp16 single-pass GEMM: C[M,N] = A[M,K] @ B[N,K]^T
// Block 64x256x32, 256 threads (2Mx4N warps), warp tile 32x64.
// 3-stage cp.async, distance-2 prefetch, 1 barrier/chunk. 2 CTAs/SM.
// half_out: 1 -> write __half C, 0 -> write fp32 C.
// ---------------------------------------------------------------------------
#define ROWB 80
#define GA_T (64 * ROWB)               // 5120
#define GB_T (256 * ROWB)              // 20480
#define G1STAGE (GA_T + GB_T)          // 25600
#define GEMM1_SMEM (3 * G1STAGE)       // 76800

__global__ __launch_bounds__(256, 2) void hmma_gemm1_kernel(
    const __half* __restrict__ A, const __half* __restrict__ Bw,
    void* __restrict__ Cv, int M, int N, int K, int half_out)
{
    extern __shared__ char gsm[];
    const uint32_t base = smem_u32(gsm);

    const int tid = threadIdx.x;
    const int lane = tid & 31;
    const int wid = tid >> 5;
    const int warp_m = wid & 1;          // 2 warps in M: 32 rows each
    const int warp_n = wid >> 1;         // 4 warps in N: 64 cols each
    const int row0 = blockIdx.y * 64, col0 = blockIdx.x * 256;

    float acc[2][8][4];
#pragma unroll
    for (int i = 0; i < 2; i++)
#pragma unroll
        for (int j = 0; j < 8; j++)
#pragma unroll
            for (int e = 0; e < 4; e++) acc[i][j][e] = 0.f;

    const int nch = K >> 5;

    // stage: A(256 x 16B) + B(1024 x 16B) = 1280 chunks; 256 thr x 5
    auto load_stage = [&](int st, int k0) {
        const uint32_t sb = base + st * G1STAGE;
#pragma unroll
        for (int i2 = 0; i2 < 5; i2++) {
            int g = tid + (i2 << 8);               // 0..1279
            const __half* src;
            uint32_t dst;
            if (g < 256) {
                int r = g >> 2;                    // 0..63
                int kq = g & 3;
                src = A + (size_t)(row0 + r) * K + k0 + (kq << 3);
                dst = sb + r * ROWB + (kq << 4);
            } else {
                int g2 = g - 256;
                int r = g2 >> 2;                   // 0..255
                int kq = g2 & 3;
                src = Bw + (size_t)(col0 + r) * K + k0 + (kq << 3);
                dst = sb + GA_T + r * ROWB + (kq << 4);
            }
            cp16(dst, src);
        }
        asm volatile("cp.async.commit_group;" ::: "memory");
    };

    load_stage(0, 0);
    load_stage(1, 32);

    int st = 0;
    for (int c = 0; c < nch; c++) {
        if (c == nch - 1) { asm volatile("cp.async.wait_group 0;" ::: "memory"); }
        else              { asm volatile("cp.async.wait_group 1;" ::: "memory"); }
        __syncthreads();

        if (c + 2 < nch) {
            int pst = st + 2; if (pst >= 3) pst -= 3;
            load_stage(pst, (c + 2) << 5);
        }

        const uint32_t sb = base + st * G1STAGE;
        const uint32_t aH = sb, bT = sb + GA_T;

#pragma unroll
        for (int ks = 0; ks < 2; ks++) {
            uint32_t ah[2][4], bw[8][2];
            const int arow = warp_m * 32 + (lane & 15);
            const uint32_t akoff = (ks << 5) + ((lane >> 4) << 4);
#pragma unroll
            for (int i = 0; i < 2; i++)
                ldsm_x4(ah[i], aH + (uint32_t)(arow + i * 16) * ROWB + akoff);
            const int quad = lane >> 3, wi = lane & 7;
#pragma unroll
            for (int t = 0; t < 4; t++) {
                int ntile = 2 * t + (quad >> 1);
                int brow = warp_n * 64 + ntile * 8 + wi;
                uint32_t bd = bT + (uint32_t)brow * ROWB + (ks << 5) + ((quad & 1) << 4);
                uint32_t r4[4];
                ldsm_x4(r4, bd);
                bw[2 * t][0] = r4[0]; bw[2 * t][1] = r4[1];
                bw[2 * t + 1][0] = r4[2]; bw[2 * t + 1][1] = r4[3];
            }
#pragma unroll
            for (int i = 0; i < 2; i++)
#pragma unroll
                for (int j = 0; j < 8; j++)
                    mma_f16(acc[i][j], ah[i], bw[j]);
        }
        if (++st >= 3) st -= 3;
    }

    const int rb = row0 + warp_m * 32 + (lane >> 2);
    const int cb = col0 + warp_n * 64 + (lane & 3) * 2;
    if (half_out) {
        __half* C = (__half*)Cv;
#pragma unroll
        for (int i = 0; i < 2; i++)
#pragma unroll
            for (int j = 0; j < 8; j++) {
                uint32_t h01 = pk_h2(acc[i][j][0], acc[i][j][1]);
                uint32_t h23 = pk_h2(acc[i][j][2], acc[i][j][3]);
                *(uint32_t*)&C[(size_t)(rb + i * 16) * N + cb + j * 8] = h01;
                *(uint32_t*)&C[(size_t)(rb + i * 16 + 8) * N + cb + j * 8] = h23;
            }
    } else {
        float* C = (float*)Cv;
#pragma unroll
        for (int i = 0; i < 2; i++)
#pragma unroll
            for (int j = 0; j < 8; j++) {
                float* p0 = C + (size_t)(rb + i * 16) * N + cb + j * 8;
                float* p1 = C + (size_t)(rb + i * 16 + 8) * N + cb + j * 8;
                *(float2*)p0 = make_float2(acc[i][j][0], acc[i][j][1]);
                *(float2*)p1 = make_float2(acc[i][j][2], acc[i][j][3]);
            }
    }
}

// ---------------------------------------------------------------------------
// fp32 -> fp16 convert
// ---------------------------------------------------------------------------
__global__ void convh_kernel(const float* __restrict__ x,
                             __half* __restrict__ y, int n4)
{
    int i = blockIdx.x * blockDim.x + threadIdx.x;
    if (i >= n4) return;
    float4 v = ((const float4*)x)[i];
    __half hv[4];
    hv[0] = __float2half_rn(v.x);
    hv[1] = __float2half_rn(v.y);
    hv[2] = __float2half_rn(v.z);
    hv[3] = __float2half_rn(v.w);
    *(uint2*)&y[(size_t)i * 4] = *(uint2*)hv;
}

// ---------------------------------------------------------------------------
// fp32 [R][Cn] -> transposed fp16 [Cn][R]. 32x32 tiles.
// ---------------------------------------------------------------------------
__global__ void tconvh_kernel(const float* __restrict__ x,
                              __half* __restrict__ w, int R, int Cn)
{
    __shared__ float t[32][33];
    int bc = blockIdx.x * 32, br = blockIdx.y * 32;
    int tx = threadIdx.x, ty = threadIdx.y;
#pragma unroll
    for (int j = 0; j < 32; j += 8)
        t[ty + j][tx] = x[(size_t)(br + ty + j) * Cn + bc + tx];
    __syncthreads();
#pragma unroll
    for (int j = 0; j < 32; j += 8) {
        int orow = bc + ty + j;
        int ocol = br + tx;
        w[(size_t)orow * R + ocol] = __float2half_rn(t[tx][ty + j]);
    }
}

// ---------------------------------------------------------------------------
// Fused RoPE + convert (reads fp16 qkv): Q (pre-scaled 1/16), K, V fp16
// ---------------------------------------------------------------------------
__global__ void rope_split_kernel(
    const __half* __restrict__ qkv, const int* __restrict__ positions,
    __half* __restrict__ qq, __half* __restrict__ kk, __half* __restrict__ vv)
{
    const int total = MROWS * 11 * 128;
    int idx = blockIdx.x * blockDim.x + threadIdx.x;
    if (idx >= total) return;
    int j = idx & 127;
    int t = idx >> 7;
    int unit = t % 11;
    int row = t / 11;
    int s = row & (SS - 1);
    int b = row >> 11;

    if (unit < 9) {
        float pos = (float)positions[s];
        const float LOG_THETA = 9.210340371976184f;
        float e = (float)j * (1.0f / 128.0f);
        float invf = expf(-LOG_THETA * e);
        float ang = pos * invf;
        float sn, cs;
        sincosf(ang, &sn, &cs);

        size_t inoff = (size_t)row * QKVW + (unit < 8 ? unit * 256 : 2048);
        float x1 = __half2float(qkv[inoff + j]);
        float x2 = __half2float(qkv[inoff + 128 + j]);
        float y1 = x1 * cs - x2 * sn;
        float y2 = x2 * cs + x1 * sn;

        if (unit < 8) {
            y1 *= 0.0625f;
            y2 *= 0.0625f;
            size_t ooff = ((size_t)(b * NHH + unit) * SS + s) * DD;
            qq[ooff + j] = __float2half_rn(y1);
            qq[ooff + 128 + j] = __float2half_rn(y2);
        } else {
            size_t ooff = (size_t)row * DD;
            kk[ooff + j] = __float2half_rn(y1);
            kk[ooff + 128 + j] = __float2half_rn(y2);
        }
    } else {
        int jj = (unit - 9) * 128 + j;
        vv[(size_t)row * DD + jj] = qkv[(size_t)row * QKVW + 2304 + jj];
    }
}

// ---------------------------------------------------------------------------
// HMMA flash attention fp16 single-pass: Br=128, Bc=32, 256 threads (8 warps).
// (verified R10/R11)
// ---------------------------------------------------------------------------
#define KSTR 528
#define PSTR 80
#define FQ 0
#define FK (FQ + 128 * KSTR)
#define FV (FK + 32 * KSTR)
#define FP (FV + 32 * KSTR)
#define FLASH_SMEM (FP + 128 * PSTR)

__global__ __launch_bounds__(256) void flash_hmma_kernel(
    const __half* __restrict__ Qp, const __half* __restrict__ Kp,
    const __half* __restrict__ Vp, __half* __restrict__ Op)
{
    extern __shared__ char fsm[];
    const uint32_t base = smem_u32(fsm);
    const int qt = (gridDim.x - 1) - blockIdx.x;
    const int h = blockIdx.y, b = blockIdx.z;
    const int tid = threadIdx.x, lane = tid & 31, w = tid >> 5;
    const int q0 = qt * 128;
    const int nj = (q0 + 128) >> 5;

    const __half* qp = Qp + ((size_t)(b * NHH + h) * SS + q0) * DD;
    const __half* kp = Kp + (size_t)b * SS * DD;
    const __half* vp = Vp + (size_t)b * SS * DD;

    {
#pragma unroll
        for (int i = 0; i < 16; i++) {
            int g = tid + (i << 8);
            int r = g >> 5, cq = g & 31;
            cp16(base + FQ + r * KSTR + (cq << 4),
                 qp + (size_t)r * DD + (cq << 3));
        }
        asm volatile("cp.async.commit_group;" ::: "memory");
    }

    auto ldkv = [&](uint32_t off, const __half* p, int c0) {
#pragma unroll
        for (int i = 0; i < 4; i++) {
            int g = tid + (i << 8);
            int r = g >> 5, cq = g & 31;
            cp16(base + off + r * KSTR + (cq << 4),
                 p + (size_t)(c0 + r) * DD + (cq << 3));
        }
        asm volatile("cp.async.commit_group;" ::: "memory");
    };

    ldkv(FK, kp, 0);
    ldkv(FV, vp, 0);

    float acc[32][4];
#pragma unroll
    for (int t = 0; t < 32; t++)
#pragma unroll
        for (int e = 0; e < 4; e++) acc[t][e] = 0.f;
    float m0 = -1e30f, m1 = -1e30f, l0 = 0.f, l1 = 0.f;

    const uint32_t aQbase = base + FQ + (w * 16 + (lane & 15)) * KSTR + ((lane >> 4) << 4);
    const int quad = lane >> 3, wi = lane & 7;
    const uint32_t bKbase = base + FK + ((quad >> 1) * 8 + wi) * KSTR + ((quad & 1) << 4);
    const uint32_t aPbase = base + FP + (w * 16 + (lane & 15)) * PSTR + ((lane >> 4) << 4);
    const uint32_t bVbase = base + FV + ((lane & 7) + ((lane >> 3) & 1) * 8) * KSTR
                          + (lane >> 4) * 16;
    const uint32_t pstore = base + FP + (w * 16 + (lane >> 2)) * PSTR + (lane & 3) * 4;

    for (int jt = 0; jt < nj; jt++) {
        const int c0 = jt * 32;
        asm volatile("cp.async.wait_group 1;" ::: "memory");
        __syncthreads();

        float sacc[4][4];
#pragma unroll
        for (int t = 0; t < 4; t++)
#pragma unroll
            for (int e = 0; e < 4; e++) sacc[t][e] = 0.f;

#pragma unroll
        for (int ks = 0; ks < 16; ks++) {
            uint32_t ah[4];
            ldsm_x4(ah, aQbase + ks * 32);
#pragma unroll
            for (int np = 0; np < 2; np++) {
                uint32_t bh4[4];
                ldsm_x4(bh4, bKbase + np * 16 * KSTR + ks * 32);
                mma_f16(sacc[2 * np],     ah, bh4);
                mma_f16(sacc[2 * np + 1], ah, bh4 + 2);
            }
        }
        __syncthreads();
        if (jt + 1 < nj) ldkv(FK, kp, c0 + 32);

        const int colb = c0 + (lane & 3) * 2;
        const int row0g = q0 + w * 16 + (lane >> 2);
        const int row1g = row0g + 8;
        if (c0 + 31 > q0) {
#pragma unroll
            for (int t = 0; t < 4; t++) {
                int cg = colb + t * 8;
#pragma unroll
                for (int e = 0; e < 4; e++) {
                    int c = cg + (e & 1);
                    int rg = (e < 2) ? row0g : row1g;
                    if (c > rg) sacc[t][e] = -1e30f;
                }
            }
        }
        float mx0 = -1e30f, mx1 = -1e30f;
#pragma unroll
        for (int t = 0; t < 4; t++) {
            mx0 = fmaxf(mx0, fmaxf(sacc[t][0], sacc[t][1]));
            mx1 = fmaxf(mx1, fmaxf(sacc[t][2], sacc[t][3]));
        }
        mx0 = fmaxf(mx0, __shfl_xor_sync(0xffffffffu, mx0, 1));
        mx0 = fmaxf(mx0, __shfl_xor_sync(0xffffffffu, mx0, 2));
        mx1 = fmaxf(mx1, __shfl_xor_sync(0xffffffffu, mx1, 1));
        mx1 = fmaxf(mx1, __shfl_xor_sync(0xffffffffu, mx1, 2));

        float mn0 = fmaxf(m0, mx0), mn1 = fmaxf(m1, mx1);
        float a0 = __expf(m0 - mn0), a1 = __expf(m1 - mn1);
        m0 = mn0; m1 = mn1;
        float s0 = 0.f, s1 = 0.f;
#pragma unroll
        for (int t = 0; t < 4; t++) {
            float p0 = __expf(sacc[t][0] - mn0);
            float p1 = __expf(sacc[t][1] - mn0);
            float p2 = __expf(sacc[t][2] - mn1);
            float p3 = __expf(sacc[t][3] - mn1);
            s0 += p0 + p1; s1 += p2 + p3;
            uint32_t h01 = pk_h2(p0, p1);
            uint32_t h23 = pk_h2(p2, p3);
            asm volatile("st.shared.b32 [%0], %1;" :: "r"(pstore + t * 16), "r"(h01) : "memory");
            asm volatile("st.shared.b32 [%0], %1;" :: "r"(pstore + 8 * PSTR + t * 16), "r"(h23) : "memory");
        }
        s0 += __shfl_xor_sync(0xffffffffu, s0, 1);
        s0 += __shfl_xor_sync(0xffffffffu, s0, 2);
        s1 += __shfl_xor_sync(0xffffffffu, s1, 1);
        s1 += __shfl_xor_sync(0xffffffffu, s1, 2);
        l0 = l0 * a0 + s0;
        l1 = l1 * a1 + s1;
        bool noresc = __all_sync(0xffffffffu, (a0 == 1.0f) && (a1 == 1.0f));
        if (!noresc) {
#pragma unroll
            for (int t = 0; t < 32; t++) {
                acc[t][0] *= a0; acc[t][1] *= a0;
                acc[t][2] *= a1; acc[t][3] *= a1;
            }
        }

        if (jt + 1 < nj) { asm volatile("cp.async.wait_group 1;" ::: "memory"); }
        else             { asm volatile("cp.async.wait_group 0;" ::: "memory"); }
        __syncthreads();

#pragma unroll
        for (int ks = 0; ks < 2; ks++) {
            uint32_t ph4[4];
            ldsm_x4(ph4, aPbase + ks * 32);
#pragma unroll
            for (int np = 0; np < 16; np++) {
                uint32_t vh4[4];
                ldsm_x4_t(vh4, bVbase + ks * 16 * KSTR + np * 32);
                mma_f16(acc[2 * np],     ph4, vh4);
                mma_f16(acc[2 * np + 1], ph4, vh4 + 2);
            }
        }
        __syncthreads();
        if (jt + 1 < nj) ldkv(FV, vp, c0 + 32);
    }

    float inv0 = 1.0f / l0, inv1 = 1.0f / l1;
    size_t ob0 = ((size_t)(b * SS) + q0 + w * 16 + (lane >> 2)) * HH + h * DD + (lane & 3) * 2;
    size_t ob1 = ob0 + 8 * (size_t)HH;
#pragma unroll
    for (int t = 0; t < 32; t++) {
        uint32_t h01 = pk_h2(acc[t][0] * inv0, acc[t][1] * inv0);
        uint32_t h23 = pk_h2(acc[t][2] * inv1, acc[t][3] * inv1);
        *(uint32_t*)&Op[ob0 + t * 8] = h01;
        *(uint32_t*)&Op[ob1 + t * 8] = h23;
    }
}

// ---------------------------------------------------------------------------
extern "C" void kernel_launch(void* const* d_in, const int* in_sizes, int n_in,
                              void* d_out, int out_size)
{
    const float* hidden    = (const float*)d_in[0];
    const int*   positions = (const int*)d_in[1];
    const float* w_qkv     = (const float*)d_in[2];
    const float* w_o       = (const float*)d_in[3];
    float* out = (float*)d_out;

    __half *qkvh_p, *hid_p, *wqkv_p, *wo_p, *atn_p;
    __half *q_p, *k_p, *v_p;
    cudaGetSymbolAddress((void**)&qkvh_p, g_qkvh);
    cudaGetSymbolAddress((void**)&hid_p, g_hid);
    cudaGetSymbolAddress((void**)&wqkv_p, g_wqkv);
    cudaGetSymbolAddress((void**)&wo_p, g_wo);
    cudaGetSymbolAddress((void**)&atn_p, g_atn);
    cudaGetSymbolAddress((void**)&q_p, g_q);
    cudaGetSymbolAddress((void**)&k_p, g_k);
    cudaGetSymbolAddress((void**)&v_p, g_v);

    cudaFuncSetAttribute(hmma_gemm1_kernel,
                         cudaFuncAttributeMaxDynamicSharedMemorySize, GEMM1_SMEM);
    cudaFuncSetAttribute(flash_hmma_kernel,
                         cudaFuncAttributeMaxDynamicSharedMemorySize, FLASH_SMEM);

    // 1) convert hidden -> fp16
    {
        int n4 = MROWS * HH / 4;
        convh_kernel<<<(n4 + 255) / 256, 256>>>(hidden, hid_p, n4);
    }
    // 2) transpose+convert w_qkv -> fp16 [N][K]
    tconvh_kernel<<<dim3(QKVW / 32, HH / 32), dim3(32, 8)>>>(w_qkv, wqkv_p, HH, QKVW);

    // 3) QKV projection (fp16 single-pass, 64x256 tiles, fp16 out)
    hmma_gemm1_kernel<<<dim3(QKVW / 256, MROWS / 64), 256, GEMM1_SMEM>>>(
        hid_p, wqkv_p, qkvh_p, MROWS, QKVW, HH, 1);

    // 4) fused RoPE + convert (reads fp16 qkv)
    {
        int total = MROWS * 11 * 128;
        rope_split_kernel<<<(total + 255) / 256, 256>>>(
            qkvh_p, positions, q_p, k_p, v_p);
    }

    // 5) HMMA flash attention (fp16 single-pass) -> O fp16
    {
        dim3 grid2(SS / 128, NHH, BB);
        flash_hmma_kernel<<<grid2, 256, FLASH_SMEM>>>(q_p, k_p, v_p, atn_p);
    }

    // 6) transpose+convert w_o -> fp16 [N][K]
    tconvh_kernel<<<dim3(HH / 32, HH / 32), dim3(32, 8)>>>(w_o, wo_p, HH, HH);

    // 7) Output projection (fp16 single-pass, 64x256 tiles, fp32 out)
    hmma_gemm1_kernel<<<dim3(HH / 256, MROWS / 64), 256, GEMM1_SMEM>>>(
        atn_p, wo_p, out, MROWS, HH, HH, 0);
}

// round 13
// speedup vs baseline: 2.3535x; 1.0255x over previous
#include <cuda_runtime.h>
#include <cuda_fp16.h>
#include <math.h>
#include <stdint.h>

#define BB 4
#define SS 2048
#define HH 2048
#define NHH 8
#define DD 256
#define QKVW 2560            // (8 + 2*1) * 256
#define MROWS (BB * SS)      // 8192

// ---------------------------------------------------------------------------
// Scratch (allocation-free rule: device globals)
// ---------------------------------------------------------------------------
__device__ __align__(16) __half g_hid[MROWS * HH];            // hidden fp16
__device__ __align__(16) __half g_wqkv[QKVW * HH];            // transposed+permuted [N][K]
__device__ __align__(16) __half g_wo[HH * HH];                // transposed [N][K]
__device__ __align__(16) __half g_atn[MROWS * HH];            // attention out fp16
__device__ __align__(16) __half g_q[(size_t)BB * NHH * SS * DD];
__device__ __align__(16) __half g_k[(size_t)BB * SS * DD];
__device__ __align__(16) __half g_v[(size_t)BB * SS * DD];

// ---------------------------------------------------------------------------
// helpers
// ---------------------------------------------------------------------------
__device__ __forceinline__ uint32_t smem_u32(const void* p) {
    uint32_t a;
    asm("{ .reg .u64 t; cvta.to.shared.u64 t, %1; cvt.u32.u64 %0, t; }"
        : "=r"(a) : "l"(p));
    return a;
}

__device__ __forceinline__ void ldsm_x4(uint32_t (&r)[4], uint32_t addr) {
    asm volatile("ldmatrix.sync.aligned.m8n8.x4.shared.b16 {%0,%1,%2,%3}, [%4];"
                 : "=r"(r[0]), "=r"(r[1]), "=r"(r[2]), "=r"(r[3]) : "r"(addr));
}

__device__ __forceinline__ void ldsm_x4_t(uint32_t (&r)[4], uint32_t addr) {
    asm volatile("ldmatrix.sync.aligned.m8n8.x4.trans.shared.b16 {%0,%1,%2,%3}, [%4];"
                 : "=r"(r[0]), "=r"(r[1]), "=r"(r[2]), "=r"(r[3]) : "r"(addr));
}

__device__ __forceinline__ void mma_f16(float (&d)[4], const uint32_t (&a)[4],
                                        const uint32_t* b) {
    asm volatile(
        "mma.sync.aligned.m16n8k16.row.col.f32.f16.f16.f32 "
        "{%0,%1,%2,%3}, {%4,%5,%6,%7}, {%8,%9}, {%0,%1,%2,%3};"
        : "+f"(d[0]), "+f"(d[1]), "+f"(d[2]), "+f"(d[3])
        : "r"(a[0]), "r"(a[1]), "r"(a[2]), "r"(a[3]), "r"(b[0]), "r"(b[1]));
}

__device__ __forceinline__ void cp16(uint32_t dst, const void* src) {
    asm volatile("cp.async.cg.shared.global [%0], [%1], 16;"
                 :: "r"(dst), "l"(src) : "memory");
}

__device__ __forceinline__ uint32_t pk_h2(float a, float b) {
    __half2 t = __floats2half2_rn(a, b);
    return *reinterpret_cast<uint32_t*>(&t);
}

// ---------------------------------------------------------------------------
// Shared GEMM config: block 64x256x32, 256 threads (2Mx4N), warp 32x64,
// 3-stage cp.async, 2 CTAs/SM.
// ---------------------------------------------------------------------------
#define ROWB 80
#define GA_T (64 * ROWB)               // 5120
#define GB_T (256 * ROWB)              // 20480
#define G1STAGE (GA_T + GB_T)          // 25600
#define GEMM1_SMEM (3 * G1STAGE)       // 76800

// Mainloop macro-free shared body implemented in both kernels (kept textual).

// ---------------------------------------------------------------------------
// QKV GEMM with fused RoPE epilogue. B is column-PERMUTED so each register
// pair (even,odd) = rope pair (x[m], x[m+128]). blockIdx.x = head (0..9).
// Writes q (pre-scaled), k, v directly.
// ---------------------------------------------------------------------------
__global__ __launch_bounds__(256, 2) void hmma_gemmqkv_kernel(
    const __half* __restrict__ A, const __half* __restrict__ Bw,
    const int* __restrict__ positions,
    __half* __restrict__ qq, __half* __restrict__ kk, __half* __restrict__ vv)
{
    extern __shared__ char gsm[];
    const uint32_t base = smem_u32(gsm);
    const int K = HH, N = QKVW;

    const int tid = threadIdx.x;
    const int lane = tid & 31;
    const int wid = tid >> 5;
    const int warp_m = wid & 1;
    const int warp_n = wid >> 1;
    const int row0 = blockIdx.y * 64, col0 = blockIdx.x * 256;

    float acc[2][8][4];
#pragma unroll
    for (int i = 0; i < 2; i++)
#pragma unroll
        for (int j = 0; j < 8; j++)
#pragma unroll
            for (int e = 0; e < 4; e++) acc[i][j][e] = 0.f;

    const int nch = K >> 5;

    auto load_stage = [&](int st, int k0) {
        const uint32_t sb = base + st * G1STAGE;
#pragma unroll
        for (int i2 = 0; i2 < 5; i2++) {
            int g = tid + (i2 << 8);
            const __half* src;
            uint32_t dst;
            if (g < 256) {
                int r = g >> 2;
                int kq = g & 3;
                src = A + (size_t)(row0 + r) * K + k0 + (kq << 3);
                dst = sb + r * ROWB + (kq << 4);
            } else {
                int g2 = g - 256;
                int r = g2 >> 2;
                int kq = g2 & 3;
                src = Bw + (size_t)(col0 + r) * K + k0 + (kq << 3);
                dst = sb + GA_T + r * ROWB + (kq << 4);
            }
            cp16(dst, src);
        }
        asm volatile("cp.async.commit_group;" ::: "memory");
    };

    load_stage(0, 0);
    load_stage(1, 32);

    int st = 0;
    for (int c = 0; c < nch; c++) {
        if (c == nch - 1) { asm volatile("cp.async.wait_group 0;" ::: "memory"); }
        else              { asm volatile("cp.async.wait_group 1;" ::: "memory"); }
        __syncthreads();

        if (c + 2 < nch) {
            int pst = st + 2; if (pst >= 3) pst -= 3;
            load_stage(pst, (c + 2) << 5);
        }

        const uint32_t sb = base + st * G1STAGE;
        const uint32_t aH = sb, bT = sb + GA_T;

#pragma unroll
        for (int ks = 0; ks < 2; ks++) {
            uint32_t ah[2][4], bw[8][2];
            const int arow = warp_m * 32 + (lane & 15);
            const uint32_t akoff = (ks << 5) + ((lane >> 4) << 4);
#pragma unroll
            for (int i = 0; i < 2; i++)
                ldsm_x4(ah[i], aH + (uint32_t)(arow + i * 16) * ROWB + akoff);
            const int quad = lane >> 3, wi = lane & 7;
#pragma unroll
            for (int t = 0; t < 4; t++) {
                int ntile = 2 * t + (quad >> 1);
                int brow = warp_n * 64 + ntile * 8 + wi;
                uint32_t bd = bT + (uint32_t)brow * ROWB + (ks << 5) + ((quad & 1) << 4);
                uint32_t r4[4];
                ldsm_x4(r4, bd);
                bw[2 * t][0] = r4[0]; bw[2 * t][1] = r4[1];
                bw[2 * t + 1][0] = r4[2]; bw[2 * t + 1][1] = r4[3];
            }
#pragma unroll
            for (int i = 0; i < 2; i++)
#pragma unroll
                for (int j = 0; j < 8; j++)
                    mma_f16(acc[i][j], ah[i], bw[j]);
        }
        if (++st >= 3) st -= 3;
    }

    // ---------------- fused RoPE epilogue ----------------
    const int rb = row0 + warp_m * 32 + (lane >> 2);
    const int head = blockIdx.x;
    const int pb = warp_n * 64 + (lane & 3) * 2;   // even pair base within head

    if (head == 9) {
        // V: identity, no rope
#pragma unroll
        for (int i = 0; i < 2; i++)
#pragma unroll
            for (int j = 0; j < 8; j++) {
                int colp = pb + j * 8;
                uint32_t h01 = pk_h2(acc[i][j][0], acc[i][j][1]);
                uint32_t h23 = pk_h2(acc[i][j][2], acc[i][j][3]);
                *(uint32_t*)&vv[(size_t)(rb + i * 16) * DD + colp] = h01;
                *(uint32_t*)&vv[(size_t)(rb + i * 16 + 8) * DD + colp] = h23;
            }
    } else {
        float inv[8];
        const float LOG_THETA = 9.210340371976184f;
#pragma unroll
        for (int j = 0; j < 8; j++) {
            int m = (pb + j * 8) >> 1;
            inv[j] = expf(-LOG_THETA * ((float)m * (1.0f / 128.0f)));
        }
        const float qscale = (head < 8) ? 0.0625f : 1.0f;
#pragma unroll
        for (int i = 0; i < 2; i++) {
#pragma unroll
            for (int half = 0; half < 2; half++) {
                int r = rb + i * 16 + half * 8;
                int s = r & (SS - 1);
                int bidx = r >> 11;
                float pos = (float)positions[s];
                size_t ooff;
                __half* outp;
                if (head < 8) {
                    ooff = ((size_t)(bidx * NHH + head) * SS + s) * DD;
                    outp = qq;
                } else {
                    ooff = (size_t)r * DD;
                    outp = kk;
                }
#pragma unroll
                for (int j = 0; j < 8; j++) {
                    float a = acc[i][j][half * 2 + 0];   // x[m]
                    float b = acc[i][j][half * 2 + 1];   // x[m+128]
                    float ang = pos * inv[j];
                    float sn, cs;
                    sincosf(ang, &sn, &cs);
                    float y1 = (a * cs - b * sn) * qscale;
                    float y2 = (b * cs + a * sn) * qscale;
                    int m = (pb + j * 8) >> 1;
                    outp[ooff + m]       = __float2half_rn(y1);
                    outp[ooff + m + 128] = __float2half_rn(y2);
                }
            }
        }
    }
}

// ---------------------------------------------------------------------------
// Plain single-pass GEMM (O-projection): C fp32 = A fp16 @ B^T fp16
// ---------------------------------------------------------------------------
__global__ __launch_bounds__(256, 2) void hmma_gemm1_kernel(
    const __half* __restrict__ A, const __half* __restrict__ Bw,
    float* __restrict__ C, int M, int N, int K)
{
    extern __shared__ char gsm[];
    const uint32_t base = smem_u32(gsm);

    const int tid = threadIdx.x;
    const int lane = tid & 31;
    const int wid = tid >> 5;
    const int warp_m = wid & 1;
    const int warp_n = wid >> 1;
    const int row0 = blockIdx.y * 64, col0 = blockIdx.x * 256;

    float acc[2][8][4];
#pragma unroll
    for (int i = 0; i < 2; i++)
#pragma unroll
        for (int j = 0; j < 8; j++)
#pragma unroll
            for (int e = 0; e < 4; e++) acc[i][j][e] = 0.f;

    const int nch = K >> 5;

    auto load_stage = [&](int st, int k0) {
        const uint32_t sb = base + st * G1STAGE;
#pragma unroll
        for (int i2 = 0; i2 < 5; i2++) {
            int g = tid + (i2 << 8);
            const __half* src;
            uint32_t dst;
            if (g < 256) {
                int r = g >> 2;
                int kq = g & 3;
                src = A + (size_t)(row0 + r) * K + k0 + (kq << 3);
                dst = sb + r * ROWB + (kq << 4);
            } else {
                int g2 = g - 256;
                int r = g2 >> 2;
                int kq = g2 & 3;
                src = Bw + (size_t)(col0 + r) * K + k0 + (kq << 3);
                dst = sb + GA_T + r * ROWB + (kq << 4);
            }
            cp16(dst, src);
        }
        asm volatile("cp.async.commit_group;" ::: "memory");
    };

    load_stage(0, 0);
    load_stage(1, 32);

    int st = 0;
    for (int c = 0; c < nch; c++) {
        if (c == nch - 1) { asm volatile("cp.async.wait_group 0;" ::: "memory"); }
        else              { asm volatile("cp.async.wait_group 1;" ::: "memory"); }
        __syncthreads();

        if (c + 2 < nch) {
            int pst = st + 2; if (pst >= 3) pst -= 3;
            load_stage(pst, (c + 2) << 5);
        }

        const uint32_t sb = base + st * G1STAGE;
        const uint32_t aH = sb, bT = sb + GA_T;

#pragma unroll
        for (int ks = 0; ks < 2; ks++) {
            uint32_t ah[2][4], bw[8][2];
            const int arow = warp_m * 32 + (lane & 15);
            const uint32_t akoff = (ks << 5) + ((lane >> 4) << 4);
#pragma unroll
            for (int i = 0; i < 2; i++)
                ldsm_x4(ah[i], aH + (uint32_t)(arow + i * 16) * ROWB + akoff);
            const int quad = lane >> 3, wi = lane & 7;
#pragma unroll
            for (int t = 0; t < 4; t++) {
                int ntile = 2 * t + (quad >> 1);
                int brow = warp_n * 64 + ntile * 8 + wi;
                uint32_t bd = bT + (uint32_t)brow * ROWB + (ks << 5) + ((quad & 1) << 4);
                uint32_t r4[4];
                ldsm_x4(r4, bd);
                bw[2 * t][0] = r4[0]; bw[2 * t][1] = r4[1];
                bw[2 * t + 1][0] = r4[2]; bw[2 * t + 1][1] = r4[3];
            }
#pragma unroll
            for (int i = 0; i < 2; i++)
#pragma unroll
                for (int j = 0; j < 8; j++)
                    mma_f16(acc[i][j], ah[i], bw[j]);
        }
        if (++st >= 3) st -= 3;
    }

    const int rb = row0 + warp_m * 32 + (lane >> 2);
    const int cb = col0 + warp_n * 64 + (lane & 3) * 2;
#pragma unroll
    for (int i = 0; i < 2; i++)
#pragma unroll
        for (int j = 0; j < 8; j++) {
            float* p0 = C + (size_t)(rb + i * 16) * N + cb + j * 8;
            float* p1 = C + (size_t)(rb + i * 16 + 8) * N + cb + j * 8;
            *(float2*)p0 = make_float2(acc[i][j][0], acc[i][j][1]);
            *(float2*)p1 = make_float2(acc[i][j][2], acc[i][j][3]);
        }
}

// ---------------------------------------------------------------------------
// fp32 -> fp16 convert
// ---------------------------------------------------------------------------
__global__ void convh_kernel(const float* __restrict__ x,
                             __half* __restrict__ y, int n4)
{
    int i = blockIdx.x * blockDim.x + threadIdx.x;
    if (i >= n4) return;
    float4 v = ((const float4*)x)[i];
    __half hv[4];
    hv[0] = __float2half_rn(v.x);
    hv[1] = __float2half_rn(v.y);
    hv[2] = __float2half_rn(v.z);
    hv[3] = __float2half_rn(v.w);
    *(uint2*)&y[(size_t)i * 4] = *(uint2*)hv;
}

// ---------------------------------------------------------------------------
// fp32 [R][Cn] -> transposed fp16 [Cn][R]. 32x32 tiles. (w_o)
// ---------------------------------------------------------------------------
__global__ void tconvh_kernel(const float* __restrict__ x,
                              __half* __restrict__ w, int R, int Cn)
{
    __shared__ float t[32][33];
    int bc = blockIdx.x * 32, br = blockIdx.y * 32;
    int tx = threadIdx.x, ty = threadIdx.y;
#pragma unroll
    for (int j = 0; j < 32; j += 8)
        t[ty + j][tx] = x[(size_t)(br + ty + j) * Cn + bc + tx];
    __syncthreads();
#pragma unroll
    for (int j = 0; j < 32; j += 8) {
        int orow = bc + ty + j;
        int ocol = br + tx;
        w[(size_t)orow * R + ocol] = __float2half_rn(t[tx][ty + j]);
    }
}

// ---------------------------------------------------------------------------
// w_qkv transpose + convert + ROPE COLUMN PERMUTATION:
// dest row p = within q/k heads: c'=c mod 256; p = hb + (c'<128 ? 2c' : 2(c'-128)+1)
// ---------------------------------------------------------------------------
__global__ void tconvh_perm_kernel(const float* __restrict__ x,
                                   __half* __restrict__ w, int R, int Cn)
{
    __shared__ float t[32][33];
    int bc = blockIdx.x * 32, br = blockIdx.y * 32;
    int tx = threadIdx.x, ty = threadIdx.y;
#pragma unroll
    for (int j = 0; j < 32; j += 8)
        t[ty + j][tx] = x[(size_t)(br + ty + j) * Cn + bc + tx];
    __syncthreads();
#pragma unroll
    for (int j = 0; j < 32; j += 8) {
        int c = bc + ty + j;        // source N col
        int ocol = br + tx;         // K index
        int p;
        if (c < 2304) {
            int hb = c & ~255;
            int cp = c - hb;
            p = hb + ((cp < 128) ? (2 * cp) : (2 * (cp - 128) + 1));
        } else {
            p = c;
        }
        w[(size_t)p * R + ocol] = __float2half_rn(t[tx][ty + j]);
    }
}

// ---------------------------------------------------------------------------
// HMMA flash attention fp16 single-pass: Br=128, Bc=32, 256 threads (8 warps).
// (verified R10-R12, unchanged)
// ---------------------------------------------------------------------------
#define KSTR 528
#define PSTR 80
#define FQ 0
#define FK (FQ + 128 * KSTR)
#define FV (FK + 32 * KSTR)
#define FP (FV + 32 * KSTR)
#define FLASH_SMEM (FP + 128 * PSTR)

__global__ __launch_bounds__(256) void flash_hmma_kernel(
    const __half* __restrict__ Qp, const __half* __restrict__ Kp,
    const __half* __restrict__ Vp, __half* __restrict__ Op)
{
    extern __shared__ char fsm[];
    const uint32_t base = smem_u32(fsm);
    const int qt = (gridDim.x - 1) - blockIdx.x;
    const int h = blockIdx.y, b = blockIdx.z;
    const int tid = threadIdx.x, lane = tid & 31, w = tid >> 5;
    const int q0 = qt * 128;
    const int nj = (q0 + 128) >> 5;

    const __half* qp = Qp + ((size_t)(b * NHH + h) * SS + q0) * DD;
    const __half* kp = Kp + (size_t)b * SS * DD;
    const __half* vp = Vp + (size_t)b * SS * DD;

    {
#pragma unroll
        for (int i = 0; i < 16; i++) {
            int g = tid + (i << 8);
            int r = g >> 5, cq = g & 31;
            cp16(base + FQ + r * KSTR + (cq << 4),
                 qp + (size_t)r * DD + (cq << 3));
        }
        asm volatile("cp.async.commit_group;" ::: "memory");
    }

    auto ldkv = [&](uint32_t off, const __half* p, int c0) {
#pragma unroll
        for (int i = 0; i < 4; i++) {
            int g = tid + (i << 8);
            int r = g >> 5, cq = g & 31;
            cp16(base + off + r * KSTR + (cq << 4),
                 p + (size_t)(c0 + r) * DD + (cq << 3));
        }
        asm volatile("cp.async.commit_group;" ::: "memory");
    };

    ldkv(FK, kp, 0);
    ldkv(FV, vp, 0);

    float acc[32][4];
#pragma unroll
    for (int t = 0; t < 32; t++)
#pragma unroll
        for (int e = 0; e < 4; e++) acc[t][e] = 0.f;
    float m0 = -1e30f, m1 = -1e30f, l0 = 0.f, l1 = 0.f;

    const uint32_t aQbase = base + FQ + (w * 16 + (lane & 15)) * KSTR + ((lane >> 4) << 4);
    const int quad = lane >> 3, wi = lane & 7;
    const uint32_t bKbase = base + FK + ((quad >> 1) * 8 + wi) * KSTR + ((quad & 1) << 4);
    const uint32_t aPbase = base + FP + (w * 16 + (lane & 15)) * PSTR + ((lane >> 4) << 4);
    const uint32_t bVbase = base + FV + ((lane & 7) + ((lane >> 3) & 1) * 8) * KSTR
                          + (lane >> 4) * 16;
    const uint32_t pstore = base + FP + (w * 16 + (lane >> 2)) * PSTR + (lane & 3) * 4;

    for (int jt = 0; jt < nj; jt++) {
        const int c0 = jt * 32;
        asm volatile("cp.async.wait_group 1;" ::: "memory");
        __syncthreads();

        float sacc[4][4];
#pragma unroll
        for (int t = 0; t < 4; t++)
#pragma unroll
            for (int e = 0; e < 4; e++) sacc[t][e] = 0.f;

#pragma unroll
        for (int ks = 0; ks < 16; ks++) {
            uint32_t ah[4];
            ldsm_x4(ah, aQbase + ks * 32);
#pragma unroll
            for (int np = 0; np < 2; np++) {
                uint32_t bh4[4];
                ldsm_x4(bh4, bKbase + np * 16 * KSTR + ks * 32);
                mma_f16(sacc[2 * np],     ah, bh4);
                mma_f16(sacc[2 * np + 1], ah, bh4 + 2);
            }
        }
        __syncthreads();
        if (jt + 1 < nj) ldkv(FK, kp, c0 + 32);

        const int colb = c0 + (lane & 3) * 2;
        const int row0g = q0 + w * 16 + (lane >> 2);
        const int row1g = row0g + 8;
        if (c0 + 31 > q0) {
#pragma unroll
            for (int t = 0; t < 4; t++) {
                int cg = colb + t * 8;
#pragma unroll
                for (int e = 0; e < 4; e++) {
                    int c = cg + (e & 1);
                    int rg = (e < 2) ? row0g : row1g;
                    if (c > rg) sacc[t][e] = -1e30f;
                }
            }
        }
        float mx0 = -1e30f, mx1 = -1e30f;
#pragma unroll
        for (int t = 0; t < 4; t++) {
            mx0 = fmaxf(mx0, fmaxf(sacc[t][0], sacc[t][1]));
            mx1 = fmaxf(mx1, fmaxf(sacc[t][2], sacc[t][3]));
        }
        mx0 = fmaxf(mx0, __shfl_xor_sync(0xffffffffu, mx0, 1));
        mx0 = fmaxf(mx0, __shfl_xor_sync(0xffffffffu, mx0, 2));
        mx1 = fmaxf(mx1, __shfl_xor_sync(0xffffffffu, mx1, 1));
        mx1 = fmaxf(mx1, __shfl_xor_sync(0xffffffffu, mx1, 2));

        float mn0 = fmaxf(m0, mx0), mn1 = fmaxf(m1, mx1);
        float a0 = __expf(m0 - mn0), a1 = __expf(m1 - mn1);
        m0 = mn0; m1 = mn1;
        float s0 = 0.f, s1 = 0.f;
#pragma unroll
        for (int t = 0; t < 4; t++) {
            float p0 = __expf(sacc[t][0] - mn0);
            float p1 = __expf(sacc[t][1] - mn0);
            float p2 = __expf(sacc[t][2] - mn1);
            float p3 = __expf(sacc[t][3] - mn1);
            s0 += p0 + p1; s1 += p2 + p3;
            uint32_t h01 = pk_h2(p0, p1);
            uint32_t h23 = pk_h2(p2, p3);
            asm volatile("st.shared.b32 [%0], %1;" :: "r"(pstore + t * 16), "r"(h01) : "memory");
            asm volatile("st.shared.b32 [%0], %1;" :: "r"(pstore + 8 * PSTR + t * 16), "r"(h23) : "memory");
        }
        s0 += __shfl_xor_sync(0xffffffffu, s0, 1);
        s0 += __shfl_xor_sync(0xffffffffu, s0, 2);
        s1 += __shfl_xor_sync(0xffffffffu, s1, 1);
        s1 += __shfl_xor_sync(0xffffffffu, s1, 2);
        l0 = l0 * a0 + s0;
        l1 = l1 * a1 + s1;
        bool noresc = __all_sync(0xffffffffu, (a0 == 1.0f) && (a1 == 1.0f));
        if (!noresc) {
#pragma unroll
            for (int t = 0; t < 32; t++) {
                acc[t][0] *= a0; acc[t][1] *= a0;
                acc[t][2] *= a1; acc[t][3] *= a1;
            }
        }

        if (jt + 1 < nj) { asm volatile("cp.async.wait_group 1;" ::: "memory"); }
        else             { asm volatile("cp.async.wait_group 0;" ::: "memory"); }
        __syncthreads();

#pragma unroll
        for (int ks = 0; ks < 2; ks++) {
            uint32_t ph4[4];
            ldsm_x4(ph4, aPbase + ks * 32);
#pragma unroll
            for (int np = 0; np < 16; np++) {
                uint32_t vh4[4];
                ldsm_x4_t(vh4, bVbase + ks * 16 * KSTR + np * 32);
                mma_f16(acc[2 * np],     ph4, vh4);
                mma_f16(acc[2 * np + 1], ph4, vh4 + 2);
            }
        }
        __syncthreads();
        if (jt + 1 < nj) ldkv(FV, vp, c0 + 32);
    }

    float inv0 = 1.0f / l0, inv1 = 1.0f / l1;
    size_t ob0 = ((size_t)(b * SS) + q0 + w * 16 + (lane >> 2)) * HH + h * DD + (lane & 3) * 2;
    size_t ob1 = ob0 + 8 * (size_t)HH;
#pragma unroll
    for (int t = 0; t < 32; t++) {
        uint32_t h01 = pk_h2(acc[t][0] * inv0, acc[t][1] * inv0);
        uint32_t h23 = pk_h2(acc[t][2] * inv1, acc[t][3] * inv1);
        *(uint32_t*)&Op[ob0 + t * 8] = h01;
        *(uint32_t*)&Op[ob1 + t * 8] = h23;
    }
}

// ---------------------------------------------------------------------------
extern "C" void kernel_launch(void* const* d_in, const int* in_sizes, int n_in,
                              void* d_out, int out_size)
{
    const float* hidden    = (const float*)d_in[0];
    const int*   positions = (const int*)d_in[1];
    const float* w_qkv     = (const float*)d_in[2];
    const float* w_o       = (const float*)d_in[3];
    float* out = (float*)d_out;

    __half *hid_p, *wqkv_p, *wo_p, *atn_p;
    __half *q_p, *k_p, *v_p;
    cudaGetSymbolAddress((void**)&hid_p, g_hid);
    cudaGetSymbolAddress((void**)&wqkv_p, g_wqkv);
    cudaGetSymbolAddress((void**)&wo_p, g_wo);
    cudaGetSymbolAddress((void**)&atn_p, g_atn);
    cudaGetSymbolAddress((void**)&q_p, g_q);
    cudaGetSymbolAddress((void**)&k_p, g_k);
    cudaGetSymbolAddress((void**)&v_p, g_v);

    cudaFuncSetAttribute(hmma_gemmqkv_kernel,
                         cudaFuncAttributeMaxDynamicSharedMemorySize, GEMM1_SMEM);
    cudaFuncSetAttribute(hmma_gemm1_kernel,
                         cudaFuncAttributeMaxDynamicSharedMemorySize, GEMM1_SMEM);
    cudaFuncSetAttribute(flash_hmma_kernel,
                         cudaFuncAttributeMaxDynamicSharedMemorySize, FLASH_SMEM);

    // 1) convert hidden -> fp16
    {
        int n4 = MROWS * HH / 4;
        convh_kernel<<<(n4 + 255) / 256, 256>>>(hidden, hid_p, n4);
    }
    // 2) transpose+convert+PERMUTE w_qkv -> fp16 [N][K]
    tconvh_perm_kernel<<<dim3(QKVW / 32, HH / 32), dim3(32, 8)>>>(w_qkv, wqkv_p, HH, QKVW);

    // 3) QKV projection with fused RoPE epilogue -> q (pre-scaled), k, v
    hmma_gemmqkv_kernel<<<dim3(QKVW / 256, MROWS / 64), 256, GEMM1_SMEM>>>(
        hid_p, wqkv_p, positions, q_p, k_p, v_p);

    // 4) HMMA flash attention (fp16 single-pass) -> O fp16
    {
        dim3 grid2(SS / 128, NHH, BB);
        flash_hmma_kernel<<<grid2, 256, FLASH_SMEM>>>(q_p, k_p, v_p, atn_p);
    }

    // 5) transpose+convert w_o -> fp16 [N][K]
    tconvh_kernel<<<dim3(HH / 32, HH / 32), dim3(32, 8)>>>(w_o, wo_p, HH, HH);

    // 6) Output projection (fp16 single-pass, fp32 out)
    hmma_gemm1_kernel<<<dim3(HH / 256, MROWS / 64), 256, GEMM1_SMEM>>>(
        atn_p, wo_p, out, MROWS, HH, HH);
}

// round 14
// speedup vs baseline: 2.3732x; 1.0084x over previous
#include <cuda_runtime.h>
#include <cuda_fp16.h>
#include <math.h>
#include <stdint.h>

#define BB 4
#define SS 2048
#define HH 2048
#define NHH 8
#define DD 256
#define QKVW 2560            // (8 + 2*1) * 256
#define MROWS (BB * SS)      // 8192

// ---------------------------------------------------------------------------
// Scratch (allocation-free rule: device globals)
// ---------------------------------------------------------------------------
__device__ __align__(16) __half g_hid[MROWS * HH];            // hidden fp16
__device__ __align__(16) __half g_wqkv[QKVW * HH];            // transposed+permuted [N][K]
__device__ __align__(16) __half g_wo[HH * HH];                // transposed [N][K]
__device__ __align__(16) __half g_atn[MROWS * HH];            // attention out fp16
__device__ __align__(16) __half g_q[(size_t)BB * NHH * SS * DD];
__device__ __align__(16) __half g_k[(size_t)BB * SS * DD];
__device__ __align__(16) __half g_v[(size_t)BB * SS * DD];

// ---------------------------------------------------------------------------
// helpers
// ---------------------------------------------------------------------------
__device__ __forceinline__ uint32_t smem_u32(const void* p) {
    uint32_t a;
    asm("{ .reg .u64 t; cvta.to.shared.u64 t, %1; cvt.u32.u64 %0, t; }"
        : "=r"(a) : "l"(p));
    return a;
}

__device__ __forceinline__ void ldsm_x4(uint32_t (&r)[4], uint32_t addr) {
    asm volatile("ldmatrix.sync.aligned.m8n8.x4.shared.b16 {%0,%1,%2,%3}, [%4];"
                 : "=r"(r[0]), "=r"(r[1]), "=r"(r[2]), "=r"(r[3]) : "r"(addr));
}

__device__ __forceinline__ void ldsm_x4_t(uint32_t (&r)[4], uint32_t addr) {
    asm volatile("ldmatrix.sync.aligned.m8n8.x4.trans.shared.b16 {%0,%1,%2,%3}, [%4];"
                 : "=r"(r[0]), "=r"(r[1]), "=r"(r[2]), "=r"(r[3]) : "r"(addr));
}

__device__ __forceinline__ void mma_f16(float (&d)[4], const uint32_t (&a)[4],
                                        const uint32_t* b) {
    asm volatile(
        "mma.sync.aligned.m16n8k16.row.col.f32.f16.f16.f32 "
        "{%0,%1,%2,%3}, {%4,%5,%6,%7}, {%8,%9}, {%0,%1,%2,%3};"
        : "+f"(d[0]), "+f"(d[1]), "+f"(d[2]), "+f"(d[3])
        : "r"(a[0]), "r"(a[1]), "r"(a[2]), "r"(a[3]), "r"(b[0]), "r"(b[1]));
}

__device__ __forceinline__ void cp16(uint32_t dst, const void* src) {
    asm volatile("cp.async.cg.shared.global [%0], [%1], 16;"
                 :: "r"(dst), "l"(src) : "memory");
}

__device__ __forceinline__ uint32_t pk_h2(float a, float b) {
    __half2 t = __floats2half2_rn(a, b);
    return *reinterpret_cast<uint32_t*>(&t);
}

// ---------------------------------------------------------------------------
// GEMM config: block 64x256x32, 256 threads (2Mx4N), warp 32x64, 3-stage.
// ---------------------------------------------------------------------------
#define ROWB 80
#define GA_T (64 * ROWB)
#define GB_T (256 * ROWB)
#define G1STAGE (GA_T + GB_T)
#define GEMM1_SMEM (3 * G1STAGE)

// ---------------------------------------------------------------------------
// QKV GEMM with fused RoPE epilogue (verified R13).
// ---------------------------------------------------------------------------
__global__ __launch_bounds__(256, 2) void hmma_gemmqkv_kernel(
    const __half* __restrict__ A, const __half* __restrict__ Bw,
    const int* __restrict__ positions,
    __half* __restrict__ qq, __half* __restrict__ kk, __half* __restrict__ vv)
{
    extern __shared__ char gsm[];
    const uint32_t base = smem_u32(gsm);
    const int K = HH;

    const int tid = threadIdx.x;
    const int lane = tid & 31;
    const int wid = tid >> 5;
    const int warp_m = wid & 1;
    const int warp_n = wid >> 1;
    const int row0 = blockIdx.y * 64, col0 = blockIdx.x * 256;

    float acc[2][8][4];
#pragma unroll
    for (int i = 0; i < 2; i++)
#pragma unroll
        for (int j = 0; j < 8; j++)
#pragma unroll
            for (int e = 0; e < 4; e++) acc[i][j][e] = 0.f;

    const int nch = K >> 5;

    auto load_stage = [&](int st, int k0) {
        const uint32_t sb = base + st * G1STAGE;
#pragma unroll
        for (int i2 = 0; i2 < 5; i2++) {
            int g = tid + (i2 << 8);
            const __half* src;
            uint32_t dst;
            if (g < 256) {
                int r = g >> 2;
                int kq = g & 3;
                src = A + (size_t)(row0 + r) * K + k0 + (kq << 3);
                dst = sb + r * ROWB + (kq << 4);
            } else {
                int g2 = g - 256;
                int r = g2 >> 2;
                int kq = g2 & 3;
                src = Bw + (size_t)(col0 + r) * K + k0 + (kq << 3);
                dst = sb + GA_T + r * ROWB + (kq << 4);
            }
            cp16(dst, src);
        }
        asm volatile("cp.async.commit_group;" ::: "memory");
    };

    load_stage(0, 0);
    load_stage(1, 32);

    int st = 0;
    for (int c = 0; c < nch; c++) {
        if (c == nch - 1) { asm volatile("cp.async.wait_group 0;" ::: "memory"); }
        else              { asm volatile("cp.async.wait_group 1;" ::: "memory"); }
        __syncthreads();

        if (c + 2 < nch) {
            int pst = st + 2; if (pst >= 3) pst -= 3;
            load_stage(pst, (c + 2) << 5);
        }

        const uint32_t sb = base + st * G1STAGE;
        const uint32_t aH = sb, bT = sb + GA_T;

#pragma unroll
        for (int ks = 0; ks < 2; ks++) {
            uint32_t ah[2][4], bw[8][2];
            const int arow = warp_m * 32 + (lane & 15);
            const uint32_t akoff = (ks << 5) + ((lane >> 4) << 4);
#pragma unroll
            for (int i = 0; i < 2; i++)
                ldsm_x4(ah[i], aH + (uint32_t)(arow + i * 16) * ROWB + akoff);
            const int quad = lane >> 3, wi = lane & 7;
#pragma unroll
            for (int t = 0; t < 4; t++) {
                int ntile = 2 * t + (quad >> 1);
                int brow = warp_n * 64 + ntile * 8 + wi;
                uint32_t bd = bT + (uint32_t)brow * ROWB + (ks << 5) + ((quad & 1) << 4);
                uint32_t r4[4];
                ldsm_x4(r4, bd);
                bw[2 * t][0] = r4[0]; bw[2 * t][1] = r4[1];
                bw[2 * t + 1][0] = r4[2]; bw[2 * t + 1][1] = r4[3];
            }
#pragma unroll
            for (int i = 0; i < 2; i++)
#pragma unroll
                for (int j = 0; j < 8; j++)
                    mma_f16(acc[i][j], ah[i], bw[j]);
        }
        if (++st >= 3) st -= 3;
    }

    // fused RoPE epilogue
    const int rb = row0 + warp_m * 32 + (lane >> 2);
    const int head = blockIdx.x;
    const int pb = warp_n * 64 + (lane & 3) * 2;

    if (head == 9) {
#pragma unroll
        for (int i = 0; i < 2; i++)
#pragma unroll
            for (int j = 0; j < 8; j++) {
                int colp = pb + j * 8;
                uint32_t h01 = pk_h2(acc[i][j][0], acc[i][j][1]);
                uint32_t h23 = pk_h2(acc[i][j][2], acc[i][j][3]);
                *(uint32_t*)&vv[(size_t)(rb + i * 16) * DD + colp] = h01;
                *(uint32_t*)&vv[(size_t)(rb + i * 16 + 8) * DD + colp] = h23;
            }
    } else {
        float inv[8];
        const float LOG_THETA = 9.210340371976184f;
#pragma unroll
        for (int j = 0; j < 8; j++) {
            int m = (pb + j * 8) >> 1;
            inv[j] = expf(-LOG_THETA * ((float)m * (1.0f / 128.0f)));
        }
        const float qscale = (head < 8) ? 0.0625f : 1.0f;
#pragma unroll
        for (int i = 0; i < 2; i++) {
#pragma unroll
            for (int half = 0; half < 2; half++) {
                int r = rb + i * 16 + half * 8;
                int s = r & (SS - 1);
                int bidx = r >> 11;
                float pos = (float)positions[s];
                size_t ooff;
                __half* outp;
                if (head < 8) {
                    ooff = ((size_t)(bidx * NHH + head) * SS + s) * DD;
                    outp = qq;
                } else {
                    ooff = (size_t)r * DD;
                    outp = kk;
                }
#pragma unroll
                for (int j = 0; j < 8; j++) {
                    float a = acc[i][j][half * 2 + 0];
                    float b = acc[i][j][half * 2 + 1];
                    float ang = pos * inv[j];
                    float sn, cs;
                    sincosf(ang, &sn, &cs);
                    float y1 = (a * cs - b * sn) * qscale;
                    float y2 = (b * cs + a * sn) * qscale;
                    int m = (pb + j * 8) >> 1;
                    outp[ooff + m]       = __float2half_rn(y1);
                    outp[ooff + m + 128] = __float2half_rn(y2);
                }
            }
        }
    }
}

// ---------------------------------------------------------------------------
// Plain single-pass GEMM (O-projection), fp32 out (verified).
// ---------------------------------------------------------------------------
__global__ __launch_bounds__(256, 2) void hmma_gemm1_kernel(
    const __half* __restrict__ A, const __half* __restrict__ Bw,
    float* __restrict__ C, int M, int N, int K)
{
    extern __shared__ char gsm[];
    const uint32_t base = smem_u32(gsm);

    const int tid = threadIdx.x;
    const int lane = tid & 31;
    const int wid = tid >> 5;
    const int warp_m = wid & 1;
    const int warp_n = wid >> 1;
    const int row0 = blockIdx.y * 64, col0 = blockIdx.x * 256;

    float acc[2][8][4];
#pragma unroll
    for (int i = 0; i < 2; i++)
#pragma unroll
        for (int j = 0; j < 8; j++)
#pragma unroll
            for (int e = 0; e < 4; e++) acc[i][j][e] = 0.f;

    const int nch = K >> 5;

    auto load_stage = [&](int st, int k0) {
        const uint32_t sb = base + st * G1STAGE;
#pragma unroll
        for (int i2 = 0; i2 < 5; i2++) {
            int g = tid + (i2 << 8);
            const __half* src;
            uint32_t dst;
            if (g < 256) {
                int r = g >> 2;
                int kq = g & 3;
                src = A + (size_t)(row0 + r) * K + k0 + (kq << 3);
                dst = sb + r * ROWB + (kq << 4);
            } else {
                int g2 = g - 256;
                int r = g2 >> 2;
                int kq = g2 & 3;
                src = Bw + (size_t)(col0 + r) * K + k0 + (kq << 3);
                dst = sb + GA_T + r * ROWB + (kq << 4);
            }
            cp16(dst, src);
        }
        asm volatile("cp.async.commit_group;" ::: "memory");
    };

    load_stage(0, 0);
    load_stage(1, 32);

    int st = 0;
    for (int c = 0; c < nch; c++) {
        if (c == nch - 1) { asm volatile("cp.async.wait_group 0;" ::: "memory"); }
        else              { asm volatile("cp.async.wait_group 1;" ::: "memory"); }
        __syncthreads();

        if (c + 2 < nch) {
            int pst = st + 2; if (pst >= 3) pst -= 3;
            load_stage(pst, (c + 2) << 5);
        }

        const uint32_t sb = base + st * G1STAGE;
        const uint32_t aH = sb, bT = sb + GA_T;

#pragma unroll
        for (int ks = 0; ks < 2; ks++) {
            uint32_t ah[2][4], bw[8][2];
            const int arow = warp_m * 32 + (lane & 15);
            const uint32_t akoff = (ks << 5) + ((lane >> 4) << 4);
#pragma unroll
            for (int i = 0; i < 2; i++)
                ldsm_x4(ah[i], aH + (uint32_t)(arow + i * 16) * ROWB + akoff);
            const int quad = lane >> 3, wi = lane & 7;
#pragma unroll
            for (int t = 0; t < 4; t++) {
                int ntile = 2 * t + (quad >> 1);
                int brow = warp_n * 64 + ntile * 8 + wi;
                uint32_t bd = bT + (uint32_t)brow * ROWB + (ks << 5) + ((quad & 1) << 4);
                uint32_t r4[4];
                ldsm_x4(r4, bd);
                bw[2 * t][0] = r4[0]; bw[2 * t][1] = r4[1];
                bw[2 * t + 1][0] = r4[2]; bw[2 * t + 1][1] = r4[3];
            }
#pragma unroll
            for (int i = 0; i < 2; i++)
#pragma unroll
                for (int j = 0; j < 8; j++)
                    mma_f16(acc[i][j], ah[i], bw[j]);
        }
        if (++st >= 3) st -= 3;
    }

    const int rb = row0 + warp_m * 32 + (lane >> 2);
    const int cb = col0 + warp_n * 64 + (lane & 3) * 2;
#pragma unroll
    for (int i = 0; i < 2; i++)
#pragma unroll
        for (int j = 0; j < 8; j++) {
            float* p0 = C + (size_t)(rb + i * 16) * N + cb + j * 8;
            float* p1 = C + (size_t)(rb + i * 16 + 8) * N + cb + j * 8;
            *(float2*)p0 = make_float2(acc[i][j][0], acc[i][j][1]);
            *(float2*)p1 = make_float2(acc[i][j][2], acc[i][j][3]);
        }
}

// ---------------------------------------------------------------------------
// fp32 -> fp16 convert
// ---------------------------------------------------------------------------
__global__ void convh_kernel(const float* __restrict__ x,
                             __half* __restrict__ y, int n4)
{
    int i = blockIdx.x * blockDim.x + threadIdx.x;
    if (i >= n4) return;
    float4 v = ((const float4*)x)[i];
    __half hv[4];
    hv[0] = __float2half_rn(v.x);
    hv[1] = __float2half_rn(v.y);
    hv[2] = __float2half_rn(v.z);
    hv[3] = __float2half_rn(v.w);
    *(uint2*)&y[(size_t)i * 4] = *(uint2*)hv;
}

// ---------------------------------------------------------------------------
// w_o transpose + convert
// ---------------------------------------------------------------------------
__global__ void tconvh_kernel(const float* __restrict__ x,
                              __half* __restrict__ w, int R, int Cn)
{
    __shared__ float t[32][33];
    int bc = blockIdx.x * 32, br = blockIdx.y * 32;
    int tx = threadIdx.x, ty = threadIdx.y;
#pragma unroll
    for (int j = 0; j < 32; j += 8)
        t[ty + j][tx] = x[(size_t)(br + ty + j) * Cn + bc + tx];
    __syncthreads();
#pragma unroll
    for (int j = 0; j < 32; j += 8) {
        int orow = bc + ty + j;
        int ocol = br + tx;
        w[(size_t)orow * R + ocol] = __float2half_rn(t[tx][ty + j]);
    }
}

// ---------------------------------------------------------------------------
// w_qkv transpose + convert + RoPE column permutation (verified R13)
// ---------------------------------------------------------------------------
__global__ void tconvh_perm_kernel(const float* __restrict__ x,
                                   __half* __restrict__ w, int R, int Cn)
{
    __shared__ float t[32][33];
    int bc = blockIdx.x * 32, br = blockIdx.y * 32;
    int tx = threadIdx.x, ty = threadIdx.y;
#pragma unroll
    for (int j = 0; j < 32; j += 8)
        t[ty + j][tx] = x[(size_t)(br + ty + j) * Cn + bc + tx];
    __syncthreads();
#pragma unroll
    for (int j = 0; j < 32; j += 8) {
        int c = bc + ty + j;
        int ocol = br + tx;
        int p;
        if (c < 2304) {
            int hb = c & ~255;
            int cp = c - hb;
            p = hb + ((cp < 128) ? (2 * cp) : (2 * (cp - 128) + 1));
        } else {
            p = c;
        }
        w[(size_t)p * R + ocol] = __float2half_rn(t[tx][ty + j]);
    }
}

// ---------------------------------------------------------------------------
// HMMA flash attention v3: Br=128, Bc=32, 256 threads (8 warps).
// Double-buffered K+V (one cp.async group per iter); NO barriers inside the
// compute phase (P is warp-private) -> warps skew, scalar softmax of one warp
// overlaps MMAs of another.
// ---------------------------------------------------------------------------
#define KSTR 528
#define PSTR 80
#define FQ 0
#define FKV0 (FQ + 128 * KSTR)            // 67584; K rows 0-31, V rows 32-63
#define FKV1 (FKV0 + 64 * KSTR)           // +33792
#define FP (FKV1 + 64 * KSTR)             // 135168
#define FLASH_SMEM (FP + 128 * PSTR)      // 145408

__global__ __launch_bounds__(256) void flash_hmma_kernel(
    const __half* __restrict__ Qp, const __half* __restrict__ Kp,
    const __half* __restrict__ Vp, __half* __restrict__ Op)
{
    extern __shared__ char fsm[];
    const uint32_t base = smem_u32(fsm);
    const int qt = (gridDim.x - 1) - blockIdx.x;
    const int h = blockIdx.y, b = blockIdx.z;
    const int tid = threadIdx.x, lane = tid & 31, w = tid >> 5;
    const int q0 = qt * 128;
    const int nj = (q0 + 128) >> 5;

    const __half* qp = Qp + ((size_t)(b * NHH + h) * SS + q0) * DD;
    const __half* kp = Kp + (size_t)b * SS * DD;
    const __half* vp = Vp + (size_t)b * SS * DD;

    // Q load: one group
    {
#pragma unroll
        for (int i = 0; i < 16; i++) {
            int g = tid + (i << 8);
            int r = g >> 5, cq = g & 31;
            cp16(base + FQ + r * KSTR + (cq << 4),
                 qp + (size_t)r * DD + (cq << 3));
        }
        asm volatile("cp.async.commit_group;" ::: "memory");
    }

    // K+V tile loader into buffer buf (K rows 0-31, V rows 32-63), ONE group
    auto ldkv = [&](int buf, int c0) {
        uint32_t bb = base + (buf ? FKV1 : FKV0);
#pragma unroll
        for (int i = 0; i < 8; i++) {
            int g = tid + (i << 8);             // 0..2047
            int r = g >> 5, cq = g & 31;        // r 0..63
            const __half* p = (r < 32) ? (kp + (size_t)(c0 + r) * DD)
                                       : (vp + (size_t)(c0 + r - 32) * DD);
            cp16(bb + r * KSTR + (cq << 4), p + (cq << 3));
        }
        asm volatile("cp.async.commit_group;" ::: "memory");
    };

    ldkv(0, 0);
    if (nj > 1) ldkv(1, 32);

    float acc[32][4];
#pragma unroll
    for (int t = 0; t < 32; t++)
#pragma unroll
        for (int e = 0; e < 4; e++) acc[t][e] = 0.f;
    float m0 = -1e30f, m1 = -1e30f, l0 = 0.f, l1 = 0.f;

    const uint32_t aQbase = base + FQ + (w * 16 + (lane & 15)) * KSTR + ((lane >> 4) << 4);
    const int quad = lane >> 3, wi = lane & 7;
    const uint32_t kOff = ((quad >> 1) * 8 + wi) * KSTR + ((quad & 1) << 4);
    const uint32_t vOff = 32 * KSTR + ((lane & 7) + ((lane >> 3) & 1) * 8) * KSTR
                        + (lane >> 4) * 16;
    const uint32_t aPbase = base + FP + (w * 16 + (lane & 15)) * PSTR + ((lane >> 4) << 4);
    const uint32_t pstore = base + FP + (w * 16 + (lane >> 2)) * PSTR + (lane & 3) * 4;

    for (int jt = 0; jt < nj; jt++) {
        const int c0 = jt * 32;
        const uint32_t bb = base + ((jt & 1) ? FKV1 : FKV0);
        // ensure KV(jt) group is complete (it is the oldest pending)
        if (jt + 1 < nj) { asm volatile("cp.async.wait_group 1;" ::: "memory"); }
        else             { asm volatile("cp.async.wait_group 0;" ::: "memory"); }
        __syncthreads();          // buffer visible to all warps

        // ---------------- S = Q K^T (no barriers from here to end) --------
        float sacc[4][4];
#pragma unroll
        for (int t = 0; t < 4; t++)
#pragma unroll
            for (int e = 0; e < 4; e++) sacc[t][e] = 0.f;

#pragma unroll
        for (int ks = 0; ks < 16; ks++) {
            uint32_t ah[4];
            ldsm_x4(ah, aQbase + ks * 32);
#pragma unroll
            for (int np = 0; np < 2; np++) {
                uint32_t bh4[4];
                ldsm_x4(bh4, bb + kOff + np * 16 * KSTR + ks * 32);
                mma_f16(sacc[2 * np],     ah, bh4);
                mma_f16(sacc[2 * np + 1], ah, bh4 + 2);
            }
        }

        // ---------------- softmax (warp-local) ----------------
        const int colb = c0 + (lane & 3) * 2;
        const int row0g = q0 + w * 16 + (lane >> 2);
        const int row1g = row0g + 8;
        if (c0 + 31 > q0) {
#pragma unroll
            for (int t = 0; t < 4; t++) {
                int cg = colb + t * 8;
#pragma unroll
                for (int e = 0; e < 4; e++) {
                    int c = cg + (e & 1);
                    int rg = (e < 2) ? row0g : row1g;
                    if (c > rg) sacc[t][e] = -1e30f;
                }
            }
        }
        float mx0 = -1e30f, mx1 = -1e30f;
#pragma unroll
        for (int t = 0; t < 4; t++) {
            mx0 = fmaxf(mx0, fmaxf(sacc[t][0], sacc[t][1]));
            mx1 = fmaxf(mx1, fmaxf(sacc[t][2], sacc[t][3]));
        }
        mx0 = fmaxf(mx0, __shfl_xor_sync(0xffffffffu, mx0, 1));
        mx0 = fmaxf(mx0, __shfl_xor_sync(0xffffffffu, mx0, 2));
        mx1 = fmaxf(mx1, __shfl_xor_sync(0xffffffffu, mx1, 1));
        mx1 = fmaxf(mx1, __shfl_xor_sync(0xffffffffu, mx1, 2));

        float mn0 = fmaxf(m0, mx0), mn1 = fmaxf(m1, mx1);
        float a0 = __expf(m0 - mn0), a1 = __expf(m1 - mn1);
        m0 = mn0; m1 = mn1;
        float s0 = 0.f, s1 = 0.f;
#pragma unroll
        for (int t = 0; t < 4; t++) {
            float p0 = __expf(sacc[t][0] - mn0);
            float p1 = __expf(sacc[t][1] - mn0);
            float p2 = __expf(sacc[t][2] - mn1);
            float p3 = __expf(sacc[t][3] - mn1);
            s0 += p0 + p1; s1 += p2 + p3;
            uint32_t h01 = pk_h2(p0, p1);
            uint32_t h23 = pk_h2(p2, p3);
            asm volatile("st.shared.b32 [%0], %1;" :: "r"(pstore + t * 16), "r"(h01) : "memory");
            asm volatile("st.shared.b32 [%0], %1;" :: "r"(pstore + 8 * PSTR + t * 16), "r"(h23) : "memory");
        }
        s0 += __shfl_xor_sync(0xffffffffu, s0, 1);
        s0 += __shfl_xor_sync(0xffffffffu, s0, 2);
        s1 += __shfl_xor_sync(0xffffffffu, s1, 1);
        s1 += __shfl_xor_sync(0xffffffffu, s1, 2);
        l0 = l0 * a0 + s0;
        l1 = l1 * a1 + s1;
        bool noresc = __all_sync(0xffffffffu, (a0 == 1.0f) && (a1 == 1.0f));
        if (!noresc) {
#pragma unroll
            for (int t = 0; t < 32; t++) {
                acc[t][0] *= a0; acc[t][1] *= a0;
                acc[t][2] *= a1; acc[t][3] *= a1;
            }
        }
        __syncwarp();          // P stores visible within warp for ldsm

        // ---------------- O += P V (P warp-private, V from this buffer) ---
#pragma unroll
        for (int ks = 0; ks < 2; ks++) {
            uint32_t ph4[4];
            ldsm_x4(ph4, aPbase + ks * 32);
#pragma unroll
            for (int np = 0; np < 16; np++) {
                uint32_t vh4[4];
                ldsm_x4_t(vh4, bb + vOff + ks * 16 * KSTR + np * 32);
                mma_f16(acc[2 * np],     ph4, vh4);
                mma_f16(acc[2 * np + 1], ph4, vh4 + 2);
            }
        }

        __syncthreads();       // all warps done reading this buffer
        if (jt + 2 < nj) ldkv(jt & 1, c0 + 64);   // refill this buffer
    }

    float inv0 = 1.0f / l0, inv1 = 1.0f / l1;
    size_t ob0 = ((size_t)(b * SS) + q0 + w * 16 + (lane >> 2)) * HH + h * DD + (lane & 3) * 2;
    size_t ob1 = ob0 + 8 * (size_t)HH;
#pragma unroll
    for (int t = 0; t < 32; t++) {
        uint32_t h01 = pk_h2(acc[t][0] * inv0, acc[t][1] * inv0);
        uint32_t h23 = pk_h2(acc[t][2] * inv1, acc[t][3] * inv1);
        *(uint32_t*)&Op[ob0 + t * 8] = h01;
        *(uint32_t*)&Op[ob1 + t * 8] = h23;
    }
}

// ---------------------------------------------------------------------------
extern "C" void kernel_launch(void* const* d_in, const int* in_sizes, int n_in,
                              void* d_out, int out_size)
{
    const float* hidden    = (const float*)d_in[0];
    const int*   positions = (const int*)d_in[1];
    const float* w_qkv     = (const float*)d_in[2];
    const float* w_o       = (const float*)d_in[3];
    float* out = (float*)d_out;

    __half *hid_p, *wqkv_p, *wo_p, *atn_p;
    __half *q_p, *k_p, *v_p;
    cudaGetSymbolAddress((void**)&hid_p, g_hid);
    cudaGetSymbolAddress((void**)&wqkv_p, g_wqkv);
    cudaGetSymbolAddress((void**)&wo_p, g_wo);
    cudaGetSymbolAddress((void**)&atn_p, g_atn);
    cudaGetSymbolAddress((void**)&q_p, g_q);
    cudaGetSymbolAddress((void**)&k_p, g_k);
    cudaGetSymbolAddress((void**)&v_p, g_v);

    cudaFuncSetAttribute(hmma_gemmqkv_kernel,
                         cudaFuncAttributeMaxDynamicSharedMemorySize, GEMM1_SMEM);
    cudaFuncSetAttribute(hmma_gemm1_kernel,
                         cudaFuncAttributeMaxDynamicSharedMemorySize, GEMM1_SMEM);
    cudaFuncSetAttribute(flash_hmma_kernel,
                         cudaFuncAttributeMaxDynamicSharedMemorySize, FLASH_SMEM);

    // 1) convert hidden -> fp16
    {
        int n4 = MROWS * HH / 4;
        convh_kernel<<<(n4 + 255) / 256, 256>>>(hidden, hid_p, n4);
    }
    // 2) transpose+convert+permute w_qkv
    tconvh_perm_kernel<<<dim3(QKVW / 32, HH / 32), dim3(32, 8)>>>(w_qkv, wqkv_p, HH, QKVW);

    // 3) QKV projection with fused RoPE epilogue
    hmma_gemmqkv_kernel<<<dim3(QKVW / 256, MROWS / 64), 256, GEMM1_SMEM>>>(
        hid_p, wqkv_p, positions, q_p, k_p, v_p);

    // 4) HMMA flash attention v3 (de-barriered)
    {
        dim3 grid2(SS / 128, NHH, BB);
        flash_hmma_kernel<<<grid2, 256, FLASH_SMEM>>>(q_p, k_p, v_p, atn_p);
    }

    // 5) transpose+convert w_o
    tconvh_kernel<<<dim3(HH / 32, HH / 32), dim3(32, 8)>>>(w_o, wo_p, HH, HH);

    // 6) Output projection
    hmma_gemm1_kernel<<<dim3(HH / 256, MROWS / 64), 256, GEMM1_SMEM>>>(
        atn_p, wo_p, out, MROWS, HH, HH);
}